// round 4
// baseline (speedup 1.0000x reference)
#include <cuda_runtime.h>
#include <math.h>

#define B_ 16
#define N_ 1024
#define D_ 128

// Scratch (device globals — allocation-free per harness rules)
static __device__ float d_h[B_ * N_ * D_];        // 8 MB
static __device__ float d_g[B_ * N_ * D_];        // 8 MB
static __device__ float d_S[B_ * N_ * N_];        // 64 MB: scores -> masked scores -> attention (in place)
static __device__ float d_cmax[B_ * N_];
static __device__ float d_csum[B_ * N_];
static __device__ float d_xd[3 * B_ * N_];        // x·wi_x, x·wf_x, x·wo_x per node

// ---------------------------------------------------------------------------
// K0: per-node dots of x with gate input vectors. One warp per node row.
// ---------------------------------------------------------------------------
__global__ void k_xdots(const float* __restrict__ x,
                        const float* __restrict__ wix,
                        const float* __restrict__ wfx,
                        const float* __restrict__ wox) {
    int row  = blockIdx.x * 8 + (threadIdx.x >> 5);
    int lane = threadIdx.x & 31;
    float4 xv = *(const float4*)(x + (size_t)row * D_ + lane * 4);
    float4 wi = *(const float4*)(wix + lane * 4);
    float4 wf = *(const float4*)(wfx + lane * 4);
    float4 wo = *(const float4*)(wox + lane * 4);
    float s0 = xv.x * wi.x + xv.y * wi.y + xv.z * wi.z + xv.w * wi.w;
    float s1 = xv.x * wf.x + xv.y * wf.y + xv.z * wf.z + xv.w * wf.w;
    float s2 = xv.x * wo.x + xv.y * wo.y + xv.z * wo.z + xv.w * wo.w;
#pragma unroll
    for (int o = 16; o > 0; o >>= 1) {
        s0 += __shfl_xor_sync(0xffffffffu, s0, o);
        s1 += __shfl_xor_sync(0xffffffffu, s1, o);
        s2 += __shfl_xor_sync(0xffffffffu, s2, o);
    }
    if (lane == 0) {
        d_xd[row]             = s0;
        d_xd[B_ * N_ + row]   = s1;
        d_xd[2 * B_ * N_ + row] = s2;
    }
}

// ---------------------------------------------------------------------------
// K1: h[r][d] = sum_f x[r][f] * Ww[d][f] + Wb[d]   (16384 x 128 x 128)
// 128x128 tile per block, 256 threads, 8x8 micro-tile.
// ---------------------------------------------------------------------------
__global__ void __launch_bounds__(256) k_gemm_h(const float* __restrict__ x,
                                                const float* __restrict__ Ww,
                                                const float* __restrict__ Wb) {
    __shared__ float Xt[32 * 132];   // [kk][row]
    __shared__ float Wt[32 * 132];   // [kk][dcol]
    int r0 = blockIdx.x * 128;
    int t = threadIdx.x, tx = t & 15, ty = t >> 4;
    float acc[8][8];
#pragma unroll
    for (int i = 0; i < 8; i++)
#pragma unroll
        for (int j = 0; j < 8; j++) acc[i][j] = 0.f;

#pragma unroll 1
    for (int kc = 0; kc < 128; kc += 32) {
        for (int idx = t; idx < 128 * 32; idx += 256) {
            int kk = idx & 31, row = idx >> 5;
            Xt[kk * 132 + row] = x[(size_t)(r0 + row) * 128 + kc + kk];
        }
        for (int idx = t; idx < 128 * 32; idx += 256) {
            int kk = idx & 31, dc = idx >> 5;
            Wt[kk * 132 + dc] = Ww[dc * 128 + kc + kk];
        }
        __syncthreads();
#pragma unroll
        for (int kk = 0; kk < 32; kk++) {
            float a[8], b[8];
            *(float4*)&a[0] = *(const float4*)&Xt[kk * 132 + ty * 8];
            *(float4*)&a[4] = *(const float4*)&Xt[kk * 132 + ty * 8 + 4];
            *(float4*)&b[0] = *(const float4*)&Wt[kk * 132 + tx * 8];
            *(float4*)&b[4] = *(const float4*)&Wt[kk * 132 + tx * 8 + 4];
#pragma unroll
            for (int i = 0; i < 8; i++)
#pragma unroll
                for (int j = 0; j < 8; j++) acc[i][j] += a[i] * b[j];
        }
        __syncthreads();
    }
#pragma unroll
    for (int i = 0; i < 8; i++) {
        int r = r0 + ty * 8 + i;
#pragma unroll
        for (int jv = 0; jv < 8; jv += 4) {
            int c = tx * 8 + jv;
            float4 o;
            o.x = acc[i][jv + 0] + Wb[c + 0];
            o.y = acc[i][jv + 1] + Wb[c + 1];
            o.z = acc[i][jv + 2] + Wb[c + 2];
            o.w = acc[i][jv + 3] + Wb[c + 3];
            *(float4*)&d_h[(size_t)r * 128 + c] = o;
        }
    }
}

// ---------------------------------------------------------------------------
// K2: g[r][l] = sum_d h[r][d] * A[d][l]
// ---------------------------------------------------------------------------
__global__ void __launch_bounds__(256) k_gemm_g(const float* __restrict__ A) {
    __shared__ float Ht[32 * 132];   // [kk][row]
    __shared__ float At[32 * 132];   // [kk][l]
    int r0 = blockIdx.x * 128;
    int t = threadIdx.x, tx = t & 15, ty = t >> 4;
    float acc[8][8];
#pragma unroll
    for (int i = 0; i < 8; i++)
#pragma unroll
        for (int j = 0; j < 8; j++) acc[i][j] = 0.f;

#pragma unroll 1
    for (int kc = 0; kc < 128; kc += 32) {
        for (int idx = t; idx < 128 * 32; idx += 256) {
            int kk = idx & 31, row = idx >> 5;
            Ht[kk * 132 + row] = d_h[(size_t)(r0 + row) * 128 + kc + kk];
        }
        for (int idx = t; idx < 32 * 128; idx += 256) {
            int l = idx & 127, kk = idx >> 7;
            At[kk * 132 + l] = A[(kc + kk) * 128 + l];
        }
        __syncthreads();
#pragma unroll
        for (int kk = 0; kk < 32; kk++) {
            float a[8], b[8];
            *(float4*)&a[0] = *(const float4*)&Ht[kk * 132 + ty * 8];
            *(float4*)&a[4] = *(const float4*)&Ht[kk * 132 + ty * 8 + 4];
            *(float4*)&b[0] = *(const float4*)&At[kk * 132 + tx * 8];
            *(float4*)&b[4] = *(const float4*)&At[kk * 132 + tx * 8 + 4];
#pragma unroll
            for (int i = 0; i < 8; i++)
#pragma unroll
                for (int j = 0; j < 8; j++) acc[i][j] += a[i] * b[j];
        }
        __syncthreads();
    }
#pragma unroll
    for (int i = 0; i < 8; i++) {
        int r = r0 + ty * 8 + i;
#pragma unroll
        for (int jv = 0; jv < 8; jv += 4) {
            int c = tx * 8 + jv;
            float4 o;
            o.x = acc[i][jv + 0]; o.y = acc[i][jv + 1];
            o.z = acc[i][jv + 2]; o.w = acc[i][jv + 3];
            *(float4*)&d_g[(size_t)r * 128 + c] = o;
        }
    }
}

// ---------------------------------------------------------------------------
// K3: symmetric scores S[j,k] = g_j.h_k + h_j.g_k, computed once per tile pair
// (J<=K), transpose tile written via shared-mem stash. No mask here.
// ---------------------------------------------------------------------------
__global__ void __launch_bounds__(256) k_scores() {
    extern __shared__ float sm[];
    float* Gj = sm;
    float* Hj = sm + 32 * 132;
    float* Gk = sm + 2 * 32 * 132;
    float* Hk = sm + 3 * 32 * 132;

    int b = blockIdx.y;
    int rem = blockIdx.x;
    int J = 0;
    while (rem >= 8 - J) { rem -= 8 - J; J++; }
    int K = J + rem;
    int j0 = J * 128, k0 = K * 128;

    const float* gb = d_g + (size_t)b * N_ * D_;
    const float* hb = d_h + (size_t)b * N_ * D_;

    int t = threadIdx.x, tx = t & 15, ty = t >> 4;
    float acc[8][8];
#pragma unroll
    for (int i = 0; i < 8; i++)
#pragma unroll
        for (int j = 0; j < 8; j++) acc[i][j] = 0.f;

#pragma unroll 1
    for (int kc = 0; kc < 128; kc += 32) {
        for (int idx = t; idx < 128 * 32; idx += 256) {
            int kk = idx & 31, row = idx >> 5;
            int go = (j0 + row) * 128 + kc + kk;
            int ko = (k0 + row) * 128 + kc + kk;
            Gj[kk * 132 + row] = gb[go];
            Hj[kk * 132 + row] = hb[go];
            Gk[kk * 132 + row] = gb[ko];
            Hk[kk * 132 + row] = hb[ko];
        }
        __syncthreads();
#pragma unroll
        for (int kk = 0; kk < 32; kk++) {
            float ag[8], ah[8], bh[8], bg[8];
            *(float4*)&ag[0] = *(const float4*)&Gj[kk * 132 + ty * 8];
            *(float4*)&ag[4] = *(const float4*)&Gj[kk * 132 + ty * 8 + 4];
            *(float4*)&ah[0] = *(const float4*)&Hj[kk * 132 + ty * 8];
            *(float4*)&ah[4] = *(const float4*)&Hj[kk * 132 + ty * 8 + 4];
            *(float4*)&bh[0] = *(const float4*)&Hk[kk * 132 + tx * 8];
            *(float4*)&bh[4] = *(const float4*)&Hk[kk * 132 + tx * 8 + 4];
            *(float4*)&bg[0] = *(const float4*)&Gk[kk * 132 + tx * 8];
            *(float4*)&bg[4] = *(const float4*)&Gk[kk * 132 + tx * 8 + 4];
#pragma unroll
            for (int i = 0; i < 8; i++)
#pragma unroll
                for (int j = 0; j < 8; j++)
                    acc[i][j] += ag[i] * bh[j] + ah[i] * bg[j];
        }
        __syncthreads();
    }

    float* Sb = d_S + (size_t)b * N_ * N_;
    // direct tile (J,K)
#pragma unroll
    for (int i = 0; i < 8; i++) {
        int r = j0 + ty * 8 + i;
#pragma unroll
        for (int jv = 0; jv < 8; jv += 4) {
            int c = k0 + tx * 8 + jv;
            float4 o;
            o.x = acc[i][jv + 0]; o.y = acc[i][jv + 1];
            o.z = acc[i][jv + 2]; o.w = acc[i][jv + 3];
            *(float4*)&Sb[(size_t)r * N_ + c] = o;
        }
    }
    if (J != K) {
        __syncthreads();
        float* St = sm;  // reuse: 128*129 floats
#pragma unroll
        for (int i = 0; i < 8; i++)
#pragma unroll
            for (int j = 0; j < 8; j++)
                St[(ty * 8 + i) * 129 + tx * 8 + j] = acc[i][j];
        __syncthreads();
        for (int idx = t; idx < 128 * 128; idx += 256) {
            int rr = idx & 127, cc = idx >> 7;
            Sb[(size_t)(k0 + cc) * N_ + j0 + rr] = St[rr * 129 + cc];
        }
    }
}

// ---------------------------------------------------------------------------
// K4: mask + online column softmax stats. scores = adj>0 ? e : 0 (in place),
// per-column (axis=1 == j) running max & sum-of-exp.
// ---------------------------------------------------------------------------
__global__ void k_softmax1(const float* __restrict__ adj) {
    __shared__ float sm_m[2][128], sm_s[2][128];
    int b = blockIdx.y, kb = blockIdx.x;
    int t = threadIdx.x;
    int c = t & 127, half = t >> 7;
    int k = kb * 128 + c;
    float* Sb = d_S + (size_t)b * N_ * N_;
    const float* ab = adj + (size_t)b * N_ * N_;

    float m = -1e30f, s = 0.f;
    for (int jj = 0; jj < 512; jj++) {
        int j = half * 512 + jj;
        int off = j * N_ + k;
        float e = Sb[off];
        float av = ab[off];
        float v = (av > 0.f) ? e : 0.f;
        Sb[off] = v;
        float nm = fmaxf(m, v);
        s = s * expf(m - nm) + expf(v - nm);
        m = nm;
    }
    sm_m[half][c] = m;
    sm_s[half][c] = s;
    __syncthreads();
    if (half == 0) {
        float m2 = sm_m[1][c], s2 = sm_s[1][c];
        float M = fmaxf(m, m2);
        float S = s * expf(m - M) + s2 * expf(m2 - M);
        d_cmax[b * N_ + k] = M;
        d_csum[b * N_ + k] = S;
    }
}

// ---------------------------------------------------------------------------
// K5: attention = exp(v - max_col)/sum_col * adj, in place over d_S.
// ---------------------------------------------------------------------------
__global__ void k_softmax2(const float* __restrict__ adj) {
    size_t base = ((size_t)blockIdx.x * blockDim.x + threadIdx.x) * 4;
    int b = (int)(base >> 20);                  // / (N_*N_)
    int k = (int)(base & (N_ - 1));
    int cb = b * N_ + k;
    float4 sv = *(const float4*)&d_S[base];
    float4 av = *(const float4*)&adj[base];
    float m0 = d_cmax[cb + 0], m1 = d_cmax[cb + 1], m2 = d_cmax[cb + 2], m3 = d_cmax[cb + 3];
    float q0 = d_csum[cb + 0], q1 = d_csum[cb + 1], q2 = d_csum[cb + 2], q3 = d_csum[cb + 3];
    float4 o;
    o.x = expf(sv.x - m0) / q0 * av.x;
    o.y = expf(sv.y - m1) / q1 * av.y;
    o.z = expf(sv.z - m2) / q2 * av.z;
    o.w = expf(sv.w - m3) / q3 * av.w;
    *(float4*)&d_S[base] = o;
}

// ---------------------------------------------------------------------------
// K6: h' = relu(att @ h); gates fused in epilogue:
// out = oc * tanh(ic*h' + fc*x), gates = sigmoid(h'.w_u + x.w_x)
// ---------------------------------------------------------------------------
__global__ void __launch_bounds__(256) k_out(const float* __restrict__ x,
                                             const float* __restrict__ wiu,
                                             const float* __restrict__ wfu,
                                             const float* __restrict__ wou,
                                             float* __restrict__ out) {
    __shared__ float Ast[32 * 132];   // [kk][row]
    __shared__ float Hst[32 * 132];   // [kk][d]
    __shared__ float red[3][128];
    __shared__ float wu[3][128];

    int b = blockIdx.y, i0 = blockIdx.x * 128;
    int t = threadIdx.x, tx = t & 15, ty = t >> 4;
    if (t < 128) {
        wu[0][t] = wiu[t]; wu[1][t] = wfu[t]; wu[2][t] = wou[t];
        red[0][t] = 0.f; red[1][t] = 0.f; red[2][t] = 0.f;
    }

    const float* Ab = d_S + (size_t)b * N_ * N_;
    const float* hb = d_h + (size_t)b * N_ * D_;

    float acc[8][8];
#pragma unroll
    for (int i = 0; i < 8; i++)
#pragma unroll
        for (int j = 0; j < 8; j++) acc[i][j] = 0.f;

#pragma unroll 1
    for (int kc = 0; kc < N_; kc += 32) {
        for (int idx = t; idx < 128 * 32; idx += 256) {
            int kk = idx & 31, row = idx >> 5;
            Ast[kk * 132 + row] = Ab[(size_t)(i0 + row) * N_ + kc + kk];
        }
        for (int idx = t; idx < 32 * 128; idx += 256) {
            int dc = idx & 127, kk = idx >> 7;
            Hst[kk * 132 + dc] = hb[(size_t)(kc + kk) * 128 + dc];
        }
        __syncthreads();
#pragma unroll
        for (int kk = 0; kk < 32; kk++) {
            float a[8], bb[8];
            *(float4*)&a[0]  = *(const float4*)&Ast[kk * 132 + ty * 8];
            *(float4*)&a[4]  = *(const float4*)&Ast[kk * 132 + ty * 8 + 4];
            *(float4*)&bb[0] = *(const float4*)&Hst[kk * 132 + tx * 8];
            *(float4*)&bb[4] = *(const float4*)&Hst[kk * 132 + tx * 8 + 4];
#pragma unroll
            for (int i = 0; i < 8; i++)
#pragma unroll
                for (int j = 0; j < 8; j++) acc[i][j] += a[i] * bb[j];
        }
        __syncthreads();
    }

    // relu -> h', partial gate dots reduced across tx via shared atomics
    float w0[8], w1[8], w2[8];
#pragma unroll
    for (int j = 0; j < 8; j++) {
        w0[j] = wu[0][tx * 8 + j];
        w1[j] = wu[1][tx * 8 + j];
        w2[j] = wu[2][tx * 8 + j];
    }
#pragma unroll
    for (int i = 0; i < 8; i++) {
        float p0 = 0.f, p1 = 0.f, p2 = 0.f;
#pragma unroll
        for (int j = 0; j < 8; j++) {
            float v = fmaxf(acc[i][j], 0.f);
            acc[i][j] = v;
            p0 += v * w0[j]; p1 += v * w1[j]; p2 += v * w2[j];
        }
        atomicAdd(&red[0][ty * 8 + i], p0);
        atomicAdd(&red[1][ty * 8 + i], p1);
        atomicAdd(&red[2][ty * 8 + i], p2);
    }
    __syncthreads();

    const float* xb = x + (size_t)b * N_ * D_;
    int nb = b * N_ + i0;
#pragma unroll
    for (int i = 0; i < 8; i++) {
        int r = ty * 8 + i;
        float zi = red[0][r] + d_xd[nb + r];
        float zf = red[1][r] + d_xd[B_ * N_ + nb + r];
        float zo = red[2][r] + d_xd[2 * B_ * N_ + nb + r];
        float ic = 1.f / (1.f + expf(-zi));
        float fc = 1.f / (1.f + expf(-zf));
        float oc = 1.f / (1.f + expf(-zo));
#pragma unroll
        for (int jv = 0; jv < 8; jv += 4) {
            int c = tx * 8 + jv;
            float4 xv = *(const float4*)&xb[(size_t)(i0 + r) * D_ + c];
            float4 o;
            o.x = oc * tanhf(ic * acc[i][jv + 0] + fc * xv.x);
            o.y = oc * tanhf(ic * acc[i][jv + 1] + fc * xv.y);
            o.z = oc * tanhf(ic * acc[i][jv + 2] + fc * xv.z);
            o.w = oc * tanhf(ic * acc[i][jv + 3] + fc * xv.w);
            *(float4*)&out[((size_t)nb + r) * D_ + c] = o;
        }
    }
}

// ---------------------------------------------------------------------------
extern "C" void kernel_launch(void* const* d_in, const int* in_sizes, int n_in,
                              void* d_out, int out_size) {
    const float* x   = (const float*)d_in[0];
    const float* adj = (const float*)d_in[1];
    const float* Ww  = (const float*)d_in[2];
    const float* Wb  = (const float*)d_in[3];
    const float* A   = (const float*)d_in[4];
    const float* wiu = (const float*)d_in[5];
    const float* wix = (const float*)d_in[6];
    const float* wfu = (const float*)d_in[7];
    const float* wfx = (const float*)d_in[8];
    const float* wou = (const float*)d_in[9];
    const float* wox = (const float*)d_in[10];
    float* out = (float*)d_out;

    const int smem3 = (4 * 32 * 132 > 128 * 129 ? 4 * 32 * 132 : 128 * 129) * 4;
    cudaFuncSetAttribute(k_scores, cudaFuncAttributeMaxDynamicSharedMemorySize, smem3);

    k_xdots<<<B_ * N_ / 8, 256>>>(x, wix, wfx, wox);
    k_gemm_h<<<B_ * N_ / 128, 256>>>(x, Ww, Wb);
    k_gemm_g<<<B_ * N_ / 128, 256>>>(A);
    {
        dim3 g(36, B_);
        k_scores<<<g, 256, smem3>>>();
    }
    {
        dim3 g(N_ / 128, B_);
        k_softmax1<<<g, 256>>>(adj);
    }
    k_softmax2<<<(B_ * N_ * N_ / 4) / 256, 256>>>(adj);
    {
        dim3 g(N_ / 128, B_);
        k_out<<<g, 256>>>(x, wiu, wfu, wou, out);
    }
}

// round 5
// speedup vs baseline: 1.5979x; 1.5979x over previous
#include <cuda_runtime.h>
#include <math.h>

#define B_ 16
#define N_ 1024
#define D_ 128

// Scratch (device globals — allocation-free per harness rules)
static __device__ float d_h[B_ * N_ * D_];        // 8 MB
static __device__ float d_g[B_ * N_ * D_];        // 8 MB
static __device__ float d_S[B_ * N_ * N_];        // 64 MB: e (symmetric) -> attention^T in place
static __device__ float d_adjT[B_ * N_ * N_];     // 64 MB: transposed adjacency
static __device__ float d_xd[3 * B_ * N_];        // x·wi_x, x·wf_x, x·wo_x per node

// ---------------------------------------------------------------------------
// FMA-only exp (no MUFU). |err| ~1e-7 for the range used here.
// ---------------------------------------------------------------------------
__device__ __forceinline__ float fexp(float x) {
    x = fmaxf(x, -87.0f);
    float y = x * 1.44269504089f;
    float n = rintf(y);
    float t = (y - n) * 0.69314718056f;       // t in [-0.347, 0.347]
    float p = 1.38888889e-3f;
    p = fmaf(p, t, 8.33333333e-3f);
    p = fmaf(p, t, 4.16666667e-2f);
    p = fmaf(p, t, 1.66666667e-1f);
    p = fmaf(p, t, 0.5f);
    p = fmaf(p, t, 1.0f);
    p = fmaf(p, t, 1.0f);
    float s = __int_as_float(((int)n + 127) << 23);
    return p * s;
}

// ---------------------------------------------------------------------------
// K0: per-node dots of x with gate input vectors. One warp per node row.
// ---------------------------------------------------------------------------
__global__ void k_xdots(const float* __restrict__ x,
                        const float* __restrict__ wix,
                        const float* __restrict__ wfx,
                        const float* __restrict__ wox) {
    int row  = blockIdx.x * 8 + (threadIdx.x >> 5);
    int lane = threadIdx.x & 31;
    float4 xv = *(const float4*)(x + (size_t)row * D_ + lane * 4);
    float4 wi = *(const float4*)(wix + lane * 4);
    float4 wf = *(const float4*)(wfx + lane * 4);
    float4 wo = *(const float4*)(wox + lane * 4);
    float s0 = xv.x * wi.x + xv.y * wi.y + xv.z * wi.z + xv.w * wi.w;
    float s1 = xv.x * wf.x + xv.y * wf.y + xv.z * wf.z + xv.w * wf.w;
    float s2 = xv.x * wo.x + xv.y * wo.y + xv.z * wo.z + xv.w * wo.w;
#pragma unroll
    for (int o = 16; o > 0; o >>= 1) {
        s0 += __shfl_xor_sync(0xffffffffu, s0, o);
        s1 += __shfl_xor_sync(0xffffffffu, s1, o);
        s2 += __shfl_xor_sync(0xffffffffu, s2, o);
    }
    if (lane == 0) {
        d_xd[row]               = s0;
        d_xd[B_ * N_ + row]     = s1;
        d_xd[2 * B_ * N_ + row] = s2;
    }
}

// ---------------------------------------------------------------------------
// K1: h[r][d] = sum_f x[r][f] * Ww[d][f] + Wb[d]
// ---------------------------------------------------------------------------
__global__ void __launch_bounds__(256, 2) k_gemm_h(const float* __restrict__ x,
                                                   const float* __restrict__ Ww,
                                                   const float* __restrict__ Wb) {
    __shared__ float Xt[32 * 132];   // [kk][row]
    __shared__ float Wt[32 * 132];   // [kk][dcol]
    int r0 = blockIdx.x * 128;
    int t = threadIdx.x, tx = t & 15, ty = t >> 4;
    float acc[8][8];
#pragma unroll
    for (int i = 0; i < 8; i++)
#pragma unroll
        for (int j = 0; j < 8; j++) acc[i][j] = 0.f;

#pragma unroll 1
    for (int kc = 0; kc < 128; kc += 32) {
        for (int idx = t; idx < 128 * 32; idx += 256) {
            int kk = idx & 31, row = idx >> 5;
            Xt[kk * 132 + row] = x[(size_t)(r0 + row) * 128 + kc + kk];
        }
        for (int idx = t; idx < 128 * 32; idx += 256) {
            int kk = idx & 31, dc = idx >> 5;
            Wt[kk * 132 + dc] = Ww[dc * 128 + kc + kk];
        }
        __syncthreads();
#pragma unroll
        for (int kk = 0; kk < 32; kk++) {
            float a[8], b[8];
            *(float4*)&a[0] = *(const float4*)&Xt[kk * 132 + ty * 8];
            *(float4*)&a[4] = *(const float4*)&Xt[kk * 132 + ty * 8 + 4];
            *(float4*)&b[0] = *(const float4*)&Wt[kk * 132 + tx * 8];
            *(float4*)&b[4] = *(const float4*)&Wt[kk * 132 + tx * 8 + 4];
#pragma unroll
            for (int i = 0; i < 8; i++)
#pragma unroll
                for (int j = 0; j < 8; j++) acc[i][j] += a[i] * b[j];
        }
        __syncthreads();
    }
#pragma unroll
    for (int i = 0; i < 8; i++) {
        int r = r0 + ty * 8 + i;
#pragma unroll
        for (int jv = 0; jv < 8; jv += 4) {
            int c = tx * 8 + jv;
            float4 o;
            o.x = acc[i][jv + 0] + Wb[c + 0];
            o.y = acc[i][jv + 1] + Wb[c + 1];
            o.z = acc[i][jv + 2] + Wb[c + 2];
            o.w = acc[i][jv + 3] + Wb[c + 3];
            *(float4*)&d_h[(size_t)r * 128 + c] = o;
        }
    }
}

// ---------------------------------------------------------------------------
// K2: g[r][l] = sum_d h[r][d] * A[d][l]   (h is L2-hot)
// ---------------------------------------------------------------------------
__global__ void __launch_bounds__(256, 2) k_gemm_g(const float* __restrict__ A) {
    __shared__ float Ht[32 * 132];   // [kk][row]
    __shared__ float At[32 * 132];   // [kk][l]
    int r0 = blockIdx.x * 128;
    int t = threadIdx.x, tx = t & 15, ty = t >> 4;
    float acc[8][8];
#pragma unroll
    for (int i = 0; i < 8; i++)
#pragma unroll
        for (int j = 0; j < 8; j++) acc[i][j] = 0.f;

#pragma unroll 1
    for (int kc = 0; kc < 128; kc += 32) {
        for (int idx = t; idx < 128 * 32; idx += 256) {
            int kk = idx & 31, row = idx >> 5;
            Ht[kk * 132 + row] = d_h[(size_t)(r0 + row) * 128 + kc + kk];
        }
        for (int idx = t; idx < 32 * 128; idx += 256) {
            int l = idx & 127, kk = idx >> 7;
            At[kk * 132 + l] = A[(kc + kk) * 128 + l];
        }
        __syncthreads();
#pragma unroll
        for (int kk = 0; kk < 32; kk++) {
            float a[8], b[8];
            *(float4*)&a[0] = *(const float4*)&Ht[kk * 132 + ty * 8];
            *(float4*)&a[4] = *(const float4*)&Ht[kk * 132 + ty * 8 + 4];
            *(float4*)&b[0] = *(const float4*)&At[kk * 132 + tx * 8];
            *(float4*)&b[4] = *(const float4*)&At[kk * 132 + tx * 8 + 4];
#pragma unroll
            for (int i = 0; i < 8; i++)
#pragma unroll
                for (int j = 0; j < 8; j++) acc[i][j] += a[i] * b[j];
        }
        __syncthreads();
    }
#pragma unroll
    for (int i = 0; i < 8; i++) {
        int r = r0 + ty * 8 + i;
#pragma unroll
        for (int jv = 0; jv < 8; jv += 4) {
            int c = tx * 8 + jv;
            float4 o;
            o.x = acc[i][jv + 0]; o.y = acc[i][jv + 1];
            o.z = acc[i][jv + 2]; o.w = acc[i][jv + 3];
            *(float4*)&d_g[(size_t)r * 128 + c] = o;
        }
    }
}

// ---------------------------------------------------------------------------
// K3: symmetric scores e[j,k] = g_j.h_k + h_j.g_k as a single K=256 GEMM
// with U=[G|H], V=[H|G]. One tile pair (J<=K) per block; mirror via smem stash.
// ---------------------------------------------------------------------------
__global__ void __launch_bounds__(256, 2) k_scores() {
    extern __shared__ float sm[];
    float* Uj = sm;                  // 32*132
    float* Vk = sm + 32 * 132;       // 32*132

    int b = blockIdx.y;
    int rem = blockIdx.x;
    int J = 0;
    while (rem >= 8 - J) { rem -= 8 - J; J++; }
    int K = J + rem;
    int j0 = J * 128, k0 = K * 128;

    const float* gb = d_g + (size_t)b * N_ * D_;
    const float* hb = d_h + (size_t)b * N_ * D_;

    int t = threadIdx.x, tx = t & 15, ty = t >> 4;
    float acc[8][8];
#pragma unroll
    for (int i = 0; i < 8; i++)
#pragma unroll
        for (int j = 0; j < 8; j++) acc[i][j] = 0.f;

#pragma unroll 1
    for (int kc = 0; kc < 256; kc += 32) {
        const float* Us = (kc < 128) ? gb : hb;
        const float* Vs = (kc < 128) ? hb : gb;
        int c0 = kc & 127;
        for (int idx = t; idx < 128 * 32; idx += 256) {
            int kk = idx & 31, row = idx >> 5;
            Uj[kk * 132 + row] = Us[(size_t)(j0 + row) * 128 + c0 + kk];
            Vk[kk * 132 + row] = Vs[(size_t)(k0 + row) * 128 + c0 + kk];
        }
        __syncthreads();
#pragma unroll
        for (int kk = 0; kk < 32; kk++) {
            float u[8], v[8];
            *(float4*)&u[0] = *(const float4*)&Uj[kk * 132 + ty * 8];
            *(float4*)&u[4] = *(const float4*)&Uj[kk * 132 + ty * 8 + 4];
            *(float4*)&v[0] = *(const float4*)&Vk[kk * 132 + tx * 8];
            *(float4*)&v[4] = *(const float4*)&Vk[kk * 132 + tx * 8 + 4];
#pragma unroll
            for (int i = 0; i < 8; i++)
#pragma unroll
                for (int j = 0; j < 8; j++) acc[i][j] += u[i] * v[j];
        }
        __syncthreads();
    }

    float* Sb = d_S + (size_t)b * N_ * N_;
    // direct tile (J,K)
#pragma unroll
    for (int i = 0; i < 8; i++) {
        int r = j0 + ty * 8 + i;
#pragma unroll
        for (int jv = 0; jv < 8; jv += 4) {
            int c = k0 + tx * 8 + jv;
            float4 o;
            o.x = acc[i][jv + 0]; o.y = acc[i][jv + 1];
            o.z = acc[i][jv + 2]; o.w = acc[i][jv + 3];
            *(float4*)&Sb[(size_t)r * N_ + c] = o;
        }
    }
    if (J != K) {
        __syncthreads();
        float* St = sm;  // reuse: 128*129 floats
#pragma unroll
        for (int i = 0; i < 8; i++)
#pragma unroll
            for (int j = 0; j < 8; j++)
                St[(ty * 8 + i) * 129 + tx * 8 + j] = acc[i][j];
        __syncthreads();
        for (int idx = t; idx < 128 * 128; idx += 256) {
            int rr = idx & 127, cc = idx >> 7;
            Sb[(size_t)(k0 + cc) * N_ + j0 + rr] = St[rr * 129 + cc];
        }
    }
}

// ---------------------------------------------------------------------------
// K4: transpose adj -> d_adjT (32x32 smem tiles)
// ---------------------------------------------------------------------------
__global__ void k_adjT(const float* __restrict__ adj) {
    __shared__ float tile[32][33];
    int b = blockIdx.z;
    int x0 = blockIdx.x * 32, y0 = blockIdx.y * 32;
    const float* ab = adj + (size_t)b * N_ * N_;
    float* tb = d_adjT + (size_t)b * N_ * N_;
    int tx = threadIdx.x, ty = threadIdx.y;
#pragma unroll
    for (int i = 0; i < 32; i += 8)
        tile[ty + i][tx] = ab[(size_t)(y0 + ty + i) * N_ + x0 + tx];
    __syncthreads();
#pragma unroll
    for (int i = 0; i < 32; i += 8)
        tb[(size_t)(x0 + ty + i) * N_ + y0 + tx] = tile[tx][ty + i];
}

// ---------------------------------------------------------------------------
// K5: fused masked softmax. Uses e's symmetry: d_S row r = {e[b,i,r]: i}.
// For column r (softmax over i): v_i = adjT[b,r,i]>0 ? e : 0;
// attn^T[b,r,i] = exp(v_i - m)/Z * adjT[b,r,i], written in place over d_S.
// One block per (r, b); 4 elems/thread; FMA-poly exp.
// ---------------------------------------------------------------------------
__global__ void __launch_bounds__(256) k_sm() {
    __shared__ float red_m[8], red_s[8];
    int b = blockIdx.y, r = blockIdx.x, t = threadIdx.x;
    float* Mrow = d_S + ((size_t)b * N_ + r) * N_;
    const float* Arow = d_adjT + ((size_t)b * N_ + r) * N_;

    float4 e4 = *(const float4*)&Mrow[t * 4];
    float4 a4 = *(const float4*)&Arow[t * 4];
    float v0 = (a4.x > 0.f) ? e4.x : 0.f;
    float v1 = (a4.y > 0.f) ? e4.y : 0.f;
    float v2 = (a4.z > 0.f) ? e4.z : 0.f;
    float v3 = (a4.w > 0.f) ? e4.w : 0.f;

    float lm = fmaxf(fmaxf(v0, v1), fmaxf(v2, v3));
#pragma unroll
    for (int o = 16; o > 0; o >>= 1)
        lm = fmaxf(lm, __shfl_xor_sync(0xffffffffu, lm, o));
    if ((t & 31) == 0) red_m[t >> 5] = lm;
    __syncthreads();
    float m = red_m[0];
#pragma unroll
    for (int i = 1; i < 8; i++) m = fmaxf(m, red_m[i]);

    float p0 = fexp(v0 - m), p1 = fexp(v1 - m);
    float p2 = fexp(v2 - m), p3 = fexp(v3 - m);
    float ls = (p0 + p1) + (p2 + p3);
#pragma unroll
    for (int o = 16; o > 0; o >>= 1)
        ls += __shfl_xor_sync(0xffffffffu, ls, o);
    if ((t & 31) == 0) red_s[t >> 5] = ls;
    __syncthreads();
    float Z = red_s[0];
#pragma unroll
    for (int i = 1; i < 8; i++) Z += red_s[i];
    float inv = 1.0f / Z;

    float4 o;
    o.x = p0 * inv * a4.x;
    o.y = p1 * inv * a4.y;
    o.z = p2 * inv * a4.z;
    o.w = p3 * inv * a4.w;
    *(float4*)&Mrow[t * 4] = o;
}

// ---------------------------------------------------------------------------
// K6: h' = relu(att @ h) with att read from its transpose (d_S holds attn^T,
// so A[i, j] = d_S[b, j, i] — contiguous per-kk loads). Gates fused in epilogue.
// ---------------------------------------------------------------------------
__global__ void __launch_bounds__(256, 2) k_out(const float* __restrict__ x,
                                                const float* __restrict__ wiu,
                                                const float* __restrict__ wfu,
                                                const float* __restrict__ wou,
                                                float* __restrict__ out) {
    __shared__ float Ast[32 * 132];   // [kk][row]
    __shared__ float Hst[32 * 132];   // [kk][d]
    __shared__ float red[3][128];
    __shared__ float wu[3][128];

    int b = blockIdx.y, i0 = blockIdx.x * 128;
    int t = threadIdx.x, tx = t & 15, ty = t >> 4;
    if (t < 128) {
        wu[0][t] = wiu[t]; wu[1][t] = wfu[t]; wu[2][t] = wou[t];
        red[0][t] = 0.f; red[1][t] = 0.f; red[2][t] = 0.f;
    }

    const float* Ab = d_S + (size_t)b * N_ * N_;   // attn^T: [j][i]
    const float* hb = d_h + (size_t)b * N_ * D_;

    float acc[8][8];
#pragma unroll
    for (int i = 0; i < 8; i++)
#pragma unroll
        for (int j = 0; j < 8; j++) acc[i][j] = 0.f;

#pragma unroll 1
    for (int kc = 0; kc < N_; kc += 32) {
        for (int idx = t; idx < 32 * 128; idx += 256) {
            int row = idx & 127, kk = idx >> 7;
            Ast[kk * 132 + row] = Ab[(size_t)(kc + kk) * N_ + i0 + row];
        }
        for (int idx = t; idx < 32 * 128; idx += 256) {
            int dc = idx & 127, kk = idx >> 7;
            Hst[kk * 132 + dc] = hb[(size_t)(kc + kk) * 128 + dc];
        }
        __syncthreads();
#pragma unroll
        for (int kk = 0; kk < 32; kk++) {
            float a[8], bb[8];
            *(float4*)&a[0]  = *(const float4*)&Ast[kk * 132 + ty * 8];
            *(float4*)&a[4]  = *(const float4*)&Ast[kk * 132 + ty * 8 + 4];
            *(float4*)&bb[0] = *(const float4*)&Hst[kk * 132 + tx * 8];
            *(float4*)&bb[4] = *(const float4*)&Hst[kk * 132 + tx * 8 + 4];
#pragma unroll
            for (int i = 0; i < 8; i++)
#pragma unroll
                for (int j = 0; j < 8; j++) acc[i][j] += a[i] * bb[j];
        }
        __syncthreads();
    }

    // relu -> h', partial gate dots reduced across tx via shared atomics
    float w0[8], w1[8], w2[8];
#pragma unroll
    for (int j = 0; j < 8; j++) {
        w0[j] = wu[0][tx * 8 + j];
        w1[j] = wu[1][tx * 8 + j];
        w2[j] = wu[2][tx * 8 + j];
    }
#pragma unroll
    for (int i = 0; i < 8; i++) {
        float p0 = 0.f, p1 = 0.f, p2 = 0.f;
#pragma unroll
        for (int j = 0; j < 8; j++) {
            float v = fmaxf(acc[i][j], 0.f);
            acc[i][j] = v;
            p0 += v * w0[j]; p1 += v * w1[j]; p2 += v * w2[j];
        }
        atomicAdd(&red[0][ty * 8 + i], p0);
        atomicAdd(&red[1][ty * 8 + i], p1);
        atomicAdd(&red[2][ty * 8 + i], p2);
    }
    __syncthreads();

    const float* xb = x + (size_t)b * N_ * D_;
    int nb = b * N_ + i0;
#pragma unroll
    for (int i = 0; i < 8; i++) {
        int r = ty * 8 + i;
        float zi = red[0][r] + d_xd[nb + r];
        float zf = red[1][r] + d_xd[B_ * N_ + nb + r];
        float zo = red[2][r] + d_xd[2 * B_ * N_ + nb + r];
        float ic = 1.f / (1.f + fexp(-zi));
        float fc = 1.f / (1.f + fexp(-zf));
        float oc = 1.f / (1.f + fexp(-zo));
#pragma unroll
        for (int jv = 0; jv < 8; jv += 4) {
            int c = tx * 8 + jv;
            float4 xv = *(const float4*)&xb[(size_t)(i0 + r) * D_ + c];
            float4 o;
            o.x = oc * tanhf(ic * acc[i][jv + 0] + fc * xv.x);
            o.y = oc * tanhf(ic * acc[i][jv + 1] + fc * xv.y);
            o.z = oc * tanhf(ic * acc[i][jv + 2] + fc * xv.z);
            o.w = oc * tanhf(ic * acc[i][jv + 3] + fc * xv.w);
            *(float4*)&out[((size_t)nb + r) * D_ + c] = o;
        }
    }
}

// ---------------------------------------------------------------------------
extern "C" void kernel_launch(void* const* d_in, const int* in_sizes, int n_in,
                              void* d_out, int out_size) {
    const float* x   = (const float*)d_in[0];
    const float* adj = (const float*)d_in[1];
    const float* Ww  = (const float*)d_in[2];
    const float* Wb  = (const float*)d_in[3];
    const float* A   = (const float*)d_in[4];
    const float* wiu = (const float*)d_in[5];
    const float* wix = (const float*)d_in[6];
    const float* wfu = (const float*)d_in[7];
    const float* wfx = (const float*)d_in[8];
    const float* wou = (const float*)d_in[9];
    const float* wox = (const float*)d_in[10];
    float* out = (float*)d_out;

    // k_scores dynamic smem: max(2 tiles of 32x132, 128x129 transpose stash)
    const int smem3 = (2 * 32 * 132 > 128 * 129 ? 2 * 32 * 132 : 128 * 129) * 4;
    static int attr_set = 0;
    if (!attr_set) {
        cudaFuncSetAttribute(k_scores, cudaFuncAttributeMaxDynamicSharedMemorySize, smem3);
        attr_set = 1;
    }

    {
        dim3 g(N_ / 32, N_ / 32, B_);
        k_adjT<<<g, dim3(32, 8)>>>(adj);
    }
    k_xdots<<<B_ * N_ / 8, 256>>>(x, wix, wfx, wox);
    k_gemm_h<<<B_ * N_ / 128, 256>>>(x, Ww, Wb);
    k_gemm_g<<<B_ * N_ / 128, 256>>>(A);
    {
        dim3 g(36, B_);
        k_scores<<<g, 256, smem3>>>();
    }
    {
        dim3 g(N_, B_);
        k_sm<<<g, 256>>>();
    }
    {
        dim3 g(N_ / 128, B_);
        k_out<<<g, 256>>>(x, wiu, wfu, wou, out);
    }
}

// round 7
// speedup vs baseline: 1.8749x; 1.1733x over previous
#include <cuda_runtime.h>
#include <cuda_bf16.h>
#include <math.h>
#include <stdint.h>

#define B_ 16
#define N_ 1024
#define D_ 128

// Scratch (device globals — allocation-free per harness rules)
static __device__ float d_h[B_ * N_ * D_];              // 8 MB fp32 (k_out B-operand)
static __device__ float d_S[B_ * N_ * N_];              // 64 MB: e -> attention^T in place
static __device__ float d_adjT[B_ * N_ * N_];           // 64 MB transposed adjacency
static __device__ float d_xd[3 * B_ * N_];              // x·w*_x per node
static __device__ __nv_bfloat16 d_Uhi[B_ * N_ * 256];   // 8 MB: [g|h] hi part
static __device__ __nv_bfloat16 d_Ulo[B_ * N_ * 256];   // 8 MB: [g|h] lo part

// ---------------------------------------------------------------------------
__device__ __forceinline__ uint32_t smem_u32(const void* p) {
    uint32_t a;
    asm("{ .reg .u64 t; cvta.to.shared.u64 t, %1; cvt.u32.u64 %0, t; }" : "=r"(a) : "l"(p));
    return a;
}

__device__ __forceinline__ void ldsm_x4(uint32_t* r, uint32_t addr) {
    asm volatile("ldmatrix.sync.aligned.m8n8.x4.shared.b16 {%0,%1,%2,%3}, [%4];"
                 : "=r"(r[0]), "=r"(r[1]), "=r"(r[2]), "=r"(r[3]) : "r"(addr));
}
__device__ __forceinline__ void mma16816(float* d, const uint32_t* a,
                                         uint32_t b0, uint32_t b1) {
    asm volatile(
        "mma.sync.aligned.m16n8k16.row.col.f32.bf16.bf16.f32 "
        "{%0,%1,%2,%3}, {%4,%5,%6,%7}, {%8,%9}, {%0,%1,%2,%3};"
        : "+f"(d[0]), "+f"(d[1]), "+f"(d[2]), "+f"(d[3])
        : "r"(a[0]), "r"(a[1]), "r"(a[2]), "r"(a[3]), "r"(b0), "r"(b1));
}

// ---------------------------------------------------------------------------
// fp32 -> bf16 hi/lo split store (packed pairs)
// ---------------------------------------------------------------------------
__device__ __forceinline__ void split2(float v0, float v1, uint32_t& hi, uint32_t& lo) {
    __nv_bfloat16 h0 = __float2bfloat16(v0), h1 = __float2bfloat16(v1);
    __nv_bfloat16 l0 = __float2bfloat16(v0 - __bfloat162float(h0));
    __nv_bfloat16 l1 = __float2bfloat16(v1 - __bfloat162float(h1));
    __nv_bfloat162 H = __halves2bfloat162(h0, h1);
    __nv_bfloat162 L = __halves2bfloat162(l0, l1);
    hi = *(uint32_t*)&H; lo = *(uint32_t*)&L;
}

// ---------------------------------------------------------------------------
// FMA-only exp
// ---------------------------------------------------------------------------
__device__ __forceinline__ float fexp(float x) {
    x = fmaxf(x, -87.0f);
    float y = x * 1.44269504089f;
    float n = rintf(y);
    float t = (y - n) * 0.69314718056f;
    float p = 1.38888889e-3f;
    p = fmaf(p, t, 8.33333333e-3f);
    p = fmaf(p, t, 4.16666667e-2f);
    p = fmaf(p, t, 1.66666667e-1f);
    p = fmaf(p, t, 0.5f);
    p = fmaf(p, t, 1.0f);
    p = fmaf(p, t, 1.0f);
    return p * __int_as_float(((int)n + 127) << 23);
}

// ---------------------------------------------------------------------------
// K0: per-node gate input dots
// ---------------------------------------------------------------------------
__global__ void k_xdots(const float* __restrict__ x,
                        const float* __restrict__ wix,
                        const float* __restrict__ wfx,
                        const float* __restrict__ wox) {
    int row  = blockIdx.x * 8 + (threadIdx.x >> 5);
    int lane = threadIdx.x & 31;
    float4 xv = *(const float4*)(x + (size_t)row * D_ + lane * 4);
    float4 wi = *(const float4*)(wix + lane * 4);
    float4 wf = *(const float4*)(wfx + lane * 4);
    float4 wo = *(const float4*)(wox + lane * 4);
    float s0 = xv.x * wi.x + xv.y * wi.y + xv.z * wi.z + xv.w * wi.w;
    float s1 = xv.x * wf.x + xv.y * wf.y + xv.z * wf.z + xv.w * wf.w;
    float s2 = xv.x * wo.x + xv.y * wo.y + xv.z * wo.z + xv.w * wo.w;
#pragma unroll
    for (int o = 16; o > 0; o >>= 1) {
        s0 += __shfl_xor_sync(0xffffffffu, s0, o);
        s1 += __shfl_xor_sync(0xffffffffu, s1, o);
        s2 += __shfl_xor_sync(0xffffffffu, s2, o);
    }
    if (lane == 0) {
        d_xd[row]               = s0;
        d_xd[B_ * N_ + row]     = s1;
        d_xd[2 * B_ * N_ + row] = s2;
    }
}

// ---------------------------------------------------------------------------
// K1: h = x·Ww^T + Wb ; write d_h fp32 AND bf16 hi/lo into U cols [128,256)
// ---------------------------------------------------------------------------
__global__ void __launch_bounds__(256, 2) k_gemm_h(const float* __restrict__ x,
                                                   const float* __restrict__ Ww,
                                                   const float* __restrict__ Wb) {
    __shared__ float Xt[32 * 132];
    __shared__ float Wt[32 * 132];
    int r0 = blockIdx.x * 128;
    int t = threadIdx.x, tx = t & 15, ty = t >> 4;
    float acc[8][8];
#pragma unroll
    for (int i = 0; i < 8; i++)
#pragma unroll
        for (int j = 0; j < 8; j++) acc[i][j] = 0.f;

#pragma unroll 1
    for (int kc = 0; kc < 128; kc += 32) {
        for (int idx = t; idx < 128 * 32; idx += 256) {
            int kk = idx & 31, row = idx >> 5;
            Xt[kk * 132 + row] = x[(size_t)(r0 + row) * 128 + kc + kk];
        }
        for (int idx = t; idx < 128 * 32; idx += 256) {
            int kk = idx & 31, dc = idx >> 5;
            Wt[kk * 132 + dc] = Ww[dc * 128 + kc + kk];
        }
        __syncthreads();
#pragma unroll
        for (int kk = 0; kk < 32; kk++) {
            float a[8], b[8];
            *(float4*)&a[0] = *(const float4*)&Xt[kk * 132 + ty * 8];
            *(float4*)&a[4] = *(const float4*)&Xt[kk * 132 + ty * 8 + 4];
            *(float4*)&b[0] = *(const float4*)&Wt[kk * 132 + tx * 8];
            *(float4*)&b[4] = *(const float4*)&Wt[kk * 132 + tx * 8 + 4];
#pragma unroll
            for (int i = 0; i < 8; i++)
#pragma unroll
                for (int j = 0; j < 8; j++) acc[i][j] += a[i] * b[j];
        }
        __syncthreads();
    }
#pragma unroll
    for (int i = 0; i < 8; i++) {
        int r = r0 + ty * 8 + i;
#pragma unroll
        for (int jv = 0; jv < 8; jv += 4) {
            int c = tx * 8 + jv;
            float4 o;
            o.x = acc[i][jv + 0] + Wb[c + 0];
            o.y = acc[i][jv + 1] + Wb[c + 1];
            o.z = acc[i][jv + 2] + Wb[c + 2];
            o.w = acc[i][jv + 3] + Wb[c + 3];
            *(float4*)&d_h[(size_t)r * 128 + c] = o;
            uint32_t h01, l01, h23, l23;
            split2(o.x, o.y, h01, l01);
            split2(o.z, o.w, h23, l23);
            uint32_t* uh = (uint32_t*)&d_Uhi[(size_t)r * 256 + 128 + c];
            uint32_t* ul = (uint32_t*)&d_Ulo[(size_t)r * 256 + 128 + c];
            uh[0] = h01; uh[1] = h23; ul[0] = l01; ul[1] = l23;
        }
    }
}

// ---------------------------------------------------------------------------
// K2: g = h·A ; write bf16 hi/lo into U cols [0,128) only (no fp32 g)
// ---------------------------------------------------------------------------
__global__ void __launch_bounds__(256, 2) k_gemm_g(const float* __restrict__ A) {
    __shared__ float Ht[32 * 132];
    __shared__ float At[32 * 132];
    int r0 = blockIdx.x * 128;
    int t = threadIdx.x, tx = t & 15, ty = t >> 4;
    float acc[8][8];
#pragma unroll
    for (int i = 0; i < 8; i++)
#pragma unroll
        for (int j = 0; j < 8; j++) acc[i][j] = 0.f;

#pragma unroll 1
    for (int kc = 0; kc < 128; kc += 32) {
        for (int idx = t; idx < 128 * 32; idx += 256) {
            int kk = idx & 31, row = idx >> 5;
            Ht[kk * 132 + row] = d_h[(size_t)(r0 + row) * 128 + kc + kk];
        }
        for (int idx = t; idx < 32 * 128; idx += 256) {
            int l = idx & 127, kk = idx >> 7;
            At[kk * 132 + l] = A[(kc + kk) * 128 + l];
        }
        __syncthreads();
#pragma unroll
        for (int kk = 0; kk < 32; kk++) {
            float a[8], b[8];
            *(float4*)&a[0] = *(const float4*)&Ht[kk * 132 + ty * 8];
            *(float4*)&a[4] = *(const float4*)&Ht[kk * 132 + ty * 8 + 4];
            *(float4*)&b[0] = *(const float4*)&At[kk * 132 + tx * 8];
            *(float4*)&b[4] = *(const float4*)&At[kk * 132 + tx * 8 + 4];
#pragma unroll
            for (int i = 0; i < 8; i++)
#pragma unroll
                for (int j = 0; j < 8; j++) acc[i][j] += a[i] * b[j];
        }
        __syncthreads();
    }
#pragma unroll
    for (int i = 0; i < 8; i++) {
        int r = r0 + ty * 8 + i;
#pragma unroll
        for (int jv = 0; jv < 8; jv += 4) {
            int c = tx * 8 + jv;
            uint32_t h01, l01, h23, l23;
            split2(acc[i][jv + 0], acc[i][jv + 1], h01, l01);
            split2(acc[i][jv + 2], acc[i][jv + 3], h23, l23);
            uint32_t* uh = (uint32_t*)&d_Uhi[(size_t)r * 256 + c];
            uint32_t* ul = (uint32_t*)&d_Ulo[(size_t)r * 256 + c];
            uh[0] = h01; uh[1] = h23; ul[0] = l01; ul[1] = l23;
        }
    }
}

// ---------------------------------------------------------------------------
// K3: scores via warp-level mma.sync (HMMA, bf16 hi/lo split, fp32 accum).
// e = U·V^T, K=256, V = half-swapped U. One 128x128 tile pair (J<=K) per
// block; 8 warps of 32x64. Mirror tile via padded smem stash.
// smem: 4 operand tiles of 128 rows x 16 bf16 (row stride 24 bf16 = 48B),
// reused after the mainloop as a 128x133 float stash.
// ---------------------------------------------------------------------------
#define SC_TILE_B (128 * 24 * 2)     // 6144 B per operand tile
#define SC_SMEM   (128 * 133 * 4)    // 68096 B stash (covers 4*6144 operands)

__global__ void __launch_bounds__(256) k_scores_mma() {
    extern __shared__ char sc[];
    uint32_t sbase = smem_u32(sc);
    __nv_bfloat16* sAhi = (__nv_bfloat16*)(sc);
    __nv_bfloat16* sAlo = (__nv_bfloat16*)(sc + SC_TILE_B);
    __nv_bfloat16* sBhi = (__nv_bfloat16*)(sc + 2 * SC_TILE_B);
    __nv_bfloat16* sBlo = (__nv_bfloat16*)(sc + 3 * SC_TILE_B);

    int t = threadIdx.x, lane = t & 31, wid = t >> 5;
    int wm = wid & 3, wn = wid >> 2;        // warp tile: rows wm*32, cols wn*64

    int b = blockIdx.y;
    int rem = blockIdx.x;
    int J = 0;
    while (rem >= 8 - J) { rem -= 8 - J; J++; }
    int K = J + rem;
    int j0 = J * 128, k0 = K * 128;

    const __nv_bfloat16* Uh = d_Uhi + (size_t)b * N_ * 256;
    const __nv_bfloat16* Ul = d_Ulo + (size_t)b * N_ * 256;

    float acc[2][8][4];
#pragma unroll
    for (int i = 0; i < 2; i++)
#pragma unroll
        for (int j = 0; j < 8; j++)
#pragma unroll
            for (int q = 0; q < 4; q++) acc[i][j][q] = 0.f;

    // per-thread gmem load coords: one uint4 (8 bf16) per tile per chunk
    int lrow = t >> 1, lhalf = t & 1;
    uint32_t s_off = (uint32_t)(lrow * 24 + lhalf * 8) * 2;  // bytes into tile

    // per-thread ldmatrix addresses (byte offsets into a tile)
    // A frag (m16x16): addr = row (mbase + (lane&15)), koff (lane>>4)*8
    uint32_t a_off[2];
#pragma unroll
    for (int mf = 0; mf < 2; mf++) {
        int rr = wm * 32 + mf * 16 + (lane & 15);
        a_off[mf] = (uint32_t)(rr * 24 + (lane >> 4) * 8) * 2;
    }
    // B frag (n16 block): addr = row (n0 + ((lane>>4)<<3) + (lane&7)), koff ((lane>>3)&1)*8
    uint32_t b_off[4];
#pragma unroll
    for (int nb = 0; nb < 4; nb++) {
        int rr = wn * 64 + nb * 16 + ((lane >> 4) << 3) + (lane & 7);
        b_off[nb] = (uint32_t)(rr * 24 + ((lane >> 3) & 1) * 8) * 2;
    }

#pragma unroll 1
    for (int ch = 0; ch < 16; ch++) {
        int ca = ch * 16;
        int cb = (ca + 128) & 255;
        {
            const uint4* gAh = (const uint4*)(Uh + (size_t)(j0 + lrow) * 256 + ca) + lhalf;
            const uint4* gAl = (const uint4*)(Ul + (size_t)(j0 + lrow) * 256 + ca) + lhalf;
            const uint4* gBh = (const uint4*)(Uh + (size_t)(k0 + lrow) * 256 + cb) + lhalf;
            const uint4* gBl = (const uint4*)(Ul + (size_t)(k0 + lrow) * 256 + cb) + lhalf;
            *(uint4*)((char*)sAhi + s_off) = *gAh;
            *(uint4*)((char*)sAlo + s_off) = *gAl;
            *(uint4*)((char*)sBhi + s_off) = *gBh;
            *(uint4*)((char*)sBlo + s_off) = *gBl;
        }
        __syncthreads();

        uint32_t ah[2][4], al[2][4];
#pragma unroll
        for (int mf = 0; mf < 2; mf++) {
            ldsm_x4(ah[mf], sbase + a_off[mf]);
            ldsm_x4(al[mf], sbase + SC_TILE_B + a_off[mf]);
        }
#pragma unroll
        for (int nb = 0; nb < 4; nb++) {
            uint32_t bh[4], bl[4];
            ldsm_x4(bh, sbase + 2 * SC_TILE_B + b_off[nb]);
            ldsm_x4(bl, sbase + 3 * SC_TILE_B + b_off[nb]);
#pragma unroll
            for (int mf = 0; mf < 2; mf++) {
#pragma unroll
                for (int sub = 0; sub < 2; sub++) {
                    float* d = acc[mf][nb * 2 + sub];
                    mma16816(d, ah[mf], bh[sub * 2], bh[sub * 2 + 1]);
                    mma16816(d, ah[mf], bl[sub * 2], bl[sub * 2 + 1]);
                    mma16816(d, al[mf], bh[sub * 2], bh[sub * 2 + 1]);
                }
            }
        }
        __syncthreads();
    }

    // stash accumulators into smem [row][col] with 133-float row stride
    float* st = (float*)sc;
    int g = lane >> 2, tg = lane & 3;
#pragma unroll
    for (int mf = 0; mf < 2; mf++) {
        int rbase = wm * 32 + mf * 16;
#pragma unroll
        for (int n8 = 0; n8 < 8; n8++) {
            int cbase = wn * 64 + n8 * 8 + tg * 2;
            float* d = acc[mf][n8];
            st[(rbase + g) * 133 + cbase]         = d[0];
            st[(rbase + g) * 133 + cbase + 1]     = d[1];
            st[(rbase + g + 8) * 133 + cbase]     = d[2];
            st[(rbase + g + 8) * 133 + cbase + 1] = d[3];
        }
    }
    __syncthreads();

    float* Sb = d_S + (size_t)b * N_ * N_;
    // direct tile (J,K): coalesced float4 writes
    {
        int row = t >> 1, chalf = (t & 1) * 64;
        const float* srow = st + row * 133 + chalf;
        float4* dst = (float4*)&Sb[(size_t)(j0 + row) * N_ + k0 + chalf];
#pragma unroll
        for (int q = 0; q < 16; q++) {
            float4 o;
            o.x = srow[q * 4 + 0]; o.y = srow[q * 4 + 1];
            o.z = srow[q * 4 + 2]; o.w = srow[q * 4 + 3];
            dst[q] = o;
        }
    }
    if (J != K) {
        int r = t & 127, c0 = t >> 7;
#pragma unroll 1
        for (int i = 0; i < 64; i++) {
            int c = c0 + i * 2;
            Sb[(size_t)(k0 + c) * N_ + j0 + r] = st[r * 133 + c];
        }
    }
}

// ---------------------------------------------------------------------------
// K4: transpose adj -> d_adjT
// ---------------------------------------------------------------------------
__global__ void k_adjT(const float* __restrict__ adj) {
    __shared__ float tile[32][33];
    int b = blockIdx.z;
    int x0 = blockIdx.x * 32, y0 = blockIdx.y * 32;
    const float* ab = adj + (size_t)b * N_ * N_;
    float* tb = d_adjT + (size_t)b * N_ * N_;
    int tx = threadIdx.x, ty = threadIdx.y;
#pragma unroll
    for (int i = 0; i < 32; i += 8)
        tile[ty + i][tx] = ab[(size_t)(y0 + ty + i) * N_ + x0 + tx];
    __syncthreads();
#pragma unroll
    for (int i = 0; i < 32; i += 8)
        tb[(size_t)(x0 + ty + i) * N_ + y0 + tx] = tile[tx][ty + i];
}

// ---------------------------------------------------------------------------
// K5: fused masked softmax over contiguous rows of symmetric e; writes attn^T.
// ---------------------------------------------------------------------------
__global__ void __launch_bounds__(256) k_sm() {
    __shared__ float red_m[8], red_s[8];
    int b = blockIdx.y, r = blockIdx.x, t = threadIdx.x;
    float* Mrow = d_S + ((size_t)b * N_ + r) * N_;
    const float* Arow = d_adjT + ((size_t)b * N_ + r) * N_;

    float4 e4 = *(const float4*)&Mrow[t * 4];
    float4 a4 = *(const float4*)&Arow[t * 4];
    float v0 = (a4.x > 0.f) ? e4.x : 0.f;
    float v1 = (a4.y > 0.f) ? e4.y : 0.f;
    float v2 = (a4.z > 0.f) ? e4.z : 0.f;
    float v3 = (a4.w > 0.f) ? e4.w : 0.f;

    float lm = fmaxf(fmaxf(v0, v1), fmaxf(v2, v3));
#pragma unroll
    for (int o = 16; o > 0; o >>= 1)
        lm = fmaxf(lm, __shfl_xor_sync(0xffffffffu, lm, o));
    if ((t & 31) == 0) red_m[t >> 5] = lm;
    __syncthreads();
    float m = red_m[0];
#pragma unroll
    for (int i = 1; i < 8; i++) m = fmaxf(m, red_m[i]);

    float p0 = fexp(v0 - m), p1 = fexp(v1 - m);
    float p2 = fexp(v2 - m), p3 = fexp(v3 - m);
    float ls = (p0 + p1) + (p2 + p3);
#pragma unroll
    for (int o = 16; o > 0; o >>= 1)
        ls += __shfl_xor_sync(0xffffffffu, ls, o);
    if ((t & 31) == 0) red_s[t >> 5] = ls;
    __syncthreads();
    float Z = red_s[0];
#pragma unroll
    for (int i = 1; i < 8; i++) Z += red_s[i];
    float inv = 1.0f / Z;

    float4 o;
    o.x = p0 * inv * a4.x;
    o.y = p1 * inv * a4.y;
    o.z = p2 * inv * a4.z;
    o.w = p3 * inv * a4.w;
    *(float4*)&Mrow[t * 4] = o;
}

// ---------------------------------------------------------------------------
// K6: h' = relu(att @ h), gates fused. 64x128 tiles for occupancy.
// ---------------------------------------------------------------------------
__global__ void __launch_bounds__(256, 2) k_out(const float* __restrict__ x,
                                                const float* __restrict__ wiu,
                                                const float* __restrict__ wfu,
                                                const float* __restrict__ wou,
                                                float* __restrict__ out) {
    __shared__ float Ast[32 * 68];    // [kk][row], 64 rows
    __shared__ float Hst[32 * 132];   // [kk][d]
    __shared__ float red[3][64];
    __shared__ float wu[3][128];

    int b = blockIdx.y, i0 = blockIdx.x * 64;
    int t = threadIdx.x, tx = t & 15, ty = t >> 4;
    if (t < 128) {
        wu[0][t] = wiu[t]; wu[1][t] = wfu[t]; wu[2][t] = wou[t];
    }
    if (t < 64) { red[0][t] = 0.f; red[1][t] = 0.f; red[2][t] = 0.f; }

    const float* Ab = d_S + (size_t)b * N_ * N_;   // attn^T [j][i]
    const float* hb = d_h + (size_t)b * N_ * D_;

    float acc[4][8];
#pragma unroll
    for (int i = 0; i < 4; i++)
#pragma unroll
        for (int j = 0; j < 8; j++) acc[i][j] = 0.f;

#pragma unroll 1
    for (int kc = 0; kc < N_; kc += 32) {
        for (int idx = t; idx < 32 * 64; idx += 256) {
            int row = idx & 63, kk = idx >> 6;
            Ast[kk * 68 + row] = Ab[(size_t)(kc + kk) * N_ + i0 + row];
        }
        for (int idx = t; idx < 32 * 128; idx += 256) {
            int dc = idx & 127, kk = idx >> 7;
            Hst[kk * 132 + dc] = hb[(size_t)(kc + kk) * 128 + dc];
        }
        __syncthreads();
#pragma unroll
        for (int kk = 0; kk < 32; kk++) {
            float a[4], bb[8];
            *(float4*)&a[0]  = *(const float4*)&Ast[kk * 68 + ty * 4];
            *(float4*)&bb[0] = *(const float4*)&Hst[kk * 132 + tx * 8];
            *(float4*)&bb[4] = *(const float4*)&Hst[kk * 132 + tx * 8 + 4];
#pragma unroll
            for (int i = 0; i < 4; i++)
#pragma unroll
                for (int j = 0; j < 8; j++) acc[i][j] += a[i] * bb[j];
        }
        __syncthreads();
    }

    float w0[8], w1[8], w2[8];
#pragma unroll
    for (int j = 0; j < 8; j++) {
        w0[j] = wu[0][tx * 8 + j];
        w1[j] = wu[1][tx * 8 + j];
        w2[j] = wu[2][tx * 8 + j];
    }
#pragma unroll
    for (int i = 0; i < 4; i++) {
        float p0 = 0.f, p1 = 0.f, p2 = 0.f;
#pragma unroll
        for (int j = 0; j < 8; j++) {
            float v = fmaxf(acc[i][j], 0.f);
            acc[i][j] = v;
            p0 += v * w0[j]; p1 += v * w1[j]; p2 += v * w2[j];
        }
        atomicAdd(&red[0][ty * 4 + i], p0);
        atomicAdd(&red[1][ty * 4 + i], p1);
        atomicAdd(&red[2][ty * 4 + i], p2);
    }
    __syncthreads();

    const float* xb = x + (size_t)b * N_ * D_;
    int nb = b * N_ + i0;
#pragma unroll
    for (int i = 0; i < 4; i++) {
        int r = ty * 4 + i;
        float zi = red[0][r] + d_xd[nb + r];
        float zf = red[1][r] + d_xd[B_ * N_ + nb + r];
        float zo = red[2][r] + d_xd[2 * B_ * N_ + nb + r];
        float ic = 1.f / (1.f + fexp(-zi));
        float fc = 1.f / (1.f + fexp(-zf));
        float oc = 1.f / (1.f + fexp(-zo));
#pragma unroll
        for (int jv = 0; jv < 8; jv += 4) {
            int c = tx * 8 + jv;
            float4 xv = *(const float4*)&xb[(size_t)(i0 + r) * D_ + c];
            float4 o;
            o.x = oc * tanhf(ic * acc[i][jv + 0] + fc * xv.x);
            o.y = oc * tanhf(ic * acc[i][jv + 1] + fc * xv.y);
            o.z = oc * tanhf(ic * acc[i][jv + 2] + fc * xv.z);
            o.w = oc * tanhf(ic * acc[i][jv + 3] + fc * xv.w);
            *(float4*)&out[((size_t)nb + r) * D_ + c] = o;
        }
    }
}

// ---------------------------------------------------------------------------
extern "C" void kernel_launch(void* const* d_in, const int* in_sizes, int n_in,
                              void* d_out, int out_size) {
    const float* x   = (const float*)d_in[0];
    const float* adj = (const float*)d_in[1];
    const float* Ww  = (const float*)d_in[2];
    const float* Wb  = (const float*)d_in[3];
    const float* A   = (const float*)d_in[4];
    const float* wiu = (const float*)d_in[5];
    const float* wix = (const float*)d_in[6];
    const float* wfu = (const float*)d_in[7];
    const float* wfx = (const float*)d_in[8];
    const float* wou = (const float*)d_in[9];
    const float* wox = (const float*)d_in[10];
    float* out = (float*)d_out;

    static int attr_set = 0;
    if (!attr_set) {
        cudaFuncSetAttribute(k_scores_mma, cudaFuncAttributeMaxDynamicSharedMemorySize, SC_SMEM);
        attr_set = 1;
    }

    {
        dim3 g(N_ / 32, N_ / 32, B_);
        k_adjT<<<g, dim3(32, 8)>>>(adj);
    }
    k_xdots<<<B_ * N_ / 8, 256>>>(x, wix, wfx, wox);
    k_gemm_h<<<B_ * N_ / 128, 256>>>(x, Ww, Wb);
    k_gemm_g<<<B_ * N_ / 128, 256>>>(A);
    {
        dim3 g(36, B_);
        k_scores_mma<<<g, 256, SC_SMEM>>>();
    }
    {
        dim3 g(N_, B_);
        k_sm<<<g, 256>>>();
    }
    {
        dim3 g(N_ / 64, B_);
        k_out<<<g, 256>>>(x, wiu, wfu, wou, out);
    }
}

// round 8
// speedup vs baseline: 3.0605x; 1.6324x over previous
#include <cuda_runtime.h>
#include <cuda_bf16.h>
#include <math.h>
#include <stdint.h>

#define B_ 16
#define N_ 1024
#define D_ 128

// Scratch (device globals — allocation-free per harness rules)
static __device__ float d_h[B_ * N_ * D_];              // 8 MB fp32
static __device__ float d_S[B_ * N_ * N_];              // 64 MB: e scores (fp32)
static __device__ __nv_bfloat16 d_adjT[B_ * N_ * N_];   // 32 MB transposed adjacency (0/1)
static __device__ float d_xd[3 * B_ * N_];              // x·w*_x per node
static __device__ __nv_bfloat16 d_Uhi[B_ * N_ * 256];   // 8 MB: [g|h] hi part
static __device__ __nv_bfloat16 d_Ulo[B_ * N_ * 256];   // 8 MB: [g|h] lo part
static __device__ __nv_bfloat16 d_AThi[B_ * N_ * N_];   // 32 MB: attn^T hi  [j][i]
static __device__ __nv_bfloat16 d_ATlo[B_ * N_ * N_];   // 32 MB: attn^T lo

// ---------------------------------------------------------------------------
__device__ __forceinline__ uint32_t smem_u32(const void* p) {
    uint32_t a;
    asm("{ .reg .u64 t; cvta.to.shared.u64 t, %1; cvt.u32.u64 %0, t; }" : "=r"(a) : "l"(p));
    return a;
}
__device__ __forceinline__ void ldsm_x4(uint32_t* r, uint32_t addr) {
    asm volatile("ldmatrix.sync.aligned.m8n8.x4.shared.b16 {%0,%1,%2,%3}, [%4];"
                 : "=r"(r[0]), "=r"(r[1]), "=r"(r[2]), "=r"(r[3]) : "r"(addr));
}
__device__ __forceinline__ void ldsm_x4_t(uint32_t* r, uint32_t addr) {
    asm volatile("ldmatrix.sync.aligned.m8n8.x4.trans.shared.b16 {%0,%1,%2,%3}, [%4];"
                 : "=r"(r[0]), "=r"(r[1]), "=r"(r[2]), "=r"(r[3]) : "r"(addr));
}
__device__ __forceinline__ void mma16816(float* d, const uint32_t* a,
                                         uint32_t b0, uint32_t b1) {
    asm volatile(
        "mma.sync.aligned.m16n8k16.row.col.f32.bf16.bf16.f32 "
        "{%0,%1,%2,%3}, {%4,%5,%6,%7}, {%8,%9}, {%0,%1,%2,%3};"
        : "+f"(d[0]), "+f"(d[1]), "+f"(d[2]), "+f"(d[3])
        : "r"(a[0]), "r"(a[1]), "r"(a[2]), "r"(a[3]), "r"(b0), "r"(b1));
}

// fp32 -> bf16 hi/lo split (packed pairs)
__device__ __forceinline__ void split2(float v0, float v1, uint32_t& hi, uint32_t& lo) {
    __nv_bfloat16 h0 = __float2bfloat16(v0), h1 = __float2bfloat16(v1);
    __nv_bfloat16 l0 = __float2bfloat16(v0 - __bfloat162float(h0));
    __nv_bfloat16 l1 = __float2bfloat16(v1 - __bfloat162float(h1));
    __nv_bfloat162 H = __halves2bfloat162(h0, h1);
    __nv_bfloat162 L = __halves2bfloat162(l0, l1);
    hi = *(uint32_t*)&H; lo = *(uint32_t*)&L;
}

// FMA-only exp
__device__ __forceinline__ float fexp(float x) {
    x = fmaxf(x, -87.0f);
    float y = x * 1.44269504089f;
    float n = rintf(y);
    float t = (y - n) * 0.69314718056f;
    float p = 1.38888889e-3f;
    p = fmaf(p, t, 8.33333333e-3f);
    p = fmaf(p, t, 4.16666667e-2f);
    p = fmaf(p, t, 1.66666667e-1f);
    p = fmaf(p, t, 0.5f);
    p = fmaf(p, t, 1.0f);
    p = fmaf(p, t, 1.0f);
    return p * __int_as_float(((int)n + 127) << 23);
}

// ---------------------------------------------------------------------------
// K0: per-node gate input dots
// ---------------------------------------------------------------------------
__global__ void k_xdots(const float* __restrict__ x,
                        const float* __restrict__ wix,
                        const float* __restrict__ wfx,
                        const float* __restrict__ wox) {
    int row  = blockIdx.x * 8 + (threadIdx.x >> 5);
    int lane = threadIdx.x & 31;
    float4 xv = *(const float4*)(x + (size_t)row * D_ + lane * 4);
    float4 wi = *(const float4*)(wix + lane * 4);
    float4 wf = *(const float4*)(wfx + lane * 4);
    float4 wo = *(const float4*)(wox + lane * 4);
    float s0 = xv.x * wi.x + xv.y * wi.y + xv.z * wi.z + xv.w * wi.w;
    float s1 = xv.x * wf.x + xv.y * wf.y + xv.z * wf.z + xv.w * wf.w;
    float s2 = xv.x * wo.x + xv.y * wo.y + xv.z * wo.z + xv.w * wo.w;
#pragma unroll
    for (int o = 16; o > 0; o >>= 1) {
        s0 += __shfl_xor_sync(0xffffffffu, s0, o);
        s1 += __shfl_xor_sync(0xffffffffu, s1, o);
        s2 += __shfl_xor_sync(0xffffffffu, s2, o);
    }
    if (lane == 0) {
        d_xd[row]               = s0;
        d_xd[B_ * N_ + row]     = s1;
        d_xd[2 * B_ * N_ + row] = s2;
    }
}

// ---------------------------------------------------------------------------
// K1: h = x·Ww^T + Wb ; write d_h fp32 AND bf16 hi/lo into U cols [128,256)
// ---------------------------------------------------------------------------
__global__ void __launch_bounds__(256, 2) k_gemm_h(const float* __restrict__ x,
                                                   const float* __restrict__ Ww,
                                                   const float* __restrict__ Wb) {
    __shared__ float Xt[32 * 132];
    __shared__ float Wt[32 * 132];
    int r0 = blockIdx.x * 128;
    int t = threadIdx.x, tx = t & 15, ty = t >> 4;
    float acc[8][8];
#pragma unroll
    for (int i = 0; i < 8; i++)
#pragma unroll
        for (int j = 0; j < 8; j++) acc[i][j] = 0.f;

#pragma unroll 1
    for (int kc = 0; kc < 128; kc += 32) {
        for (int idx = t; idx < 128 * 32; idx += 256) {
            int kk = idx & 31, row = idx >> 5;
            Xt[kk * 132 + row] = x[(size_t)(r0 + row) * 128 + kc + kk];
        }
        for (int idx = t; idx < 128 * 32; idx += 256) {
            int kk = idx & 31, dc = idx >> 5;
            Wt[kk * 132 + dc] = Ww[dc * 128 + kc + kk];
        }
        __syncthreads();
#pragma unroll
        for (int kk = 0; kk < 32; kk++) {
            float a[8], b[8];
            *(float4*)&a[0] = *(const float4*)&Xt[kk * 132 + ty * 8];
            *(float4*)&a[4] = *(const float4*)&Xt[kk * 132 + ty * 8 + 4];
            *(float4*)&b[0] = *(const float4*)&Wt[kk * 132 + tx * 8];
            *(float4*)&b[4] = *(const float4*)&Wt[kk * 132 + tx * 8 + 4];
#pragma unroll
            for (int i = 0; i < 8; i++)
#pragma unroll
                for (int j = 0; j < 8; j++) acc[i][j] += a[i] * b[j];
        }
        __syncthreads();
    }
#pragma unroll
    for (int i = 0; i < 8; i++) {
        int r = r0 + ty * 8 + i;
#pragma unroll
        for (int jv = 0; jv < 8; jv += 4) {
            int c = tx * 8 + jv;
            float4 o;
            o.x = acc[i][jv + 0] + Wb[c + 0];
            o.y = acc[i][jv + 1] + Wb[c + 1];
            o.z = acc[i][jv + 2] + Wb[c + 2];
            o.w = acc[i][jv + 3] + Wb[c + 3];
            *(float4*)&d_h[(size_t)r * 128 + c] = o;
            uint32_t h01, l01, h23, l23;
            split2(o.x, o.y, h01, l01);
            split2(o.z, o.w, h23, l23);
            uint32_t* uh = (uint32_t*)&d_Uhi[(size_t)r * 256 + 128 + c];
            uint32_t* ul = (uint32_t*)&d_Ulo[(size_t)r * 256 + 128 + c];
            uh[0] = h01; uh[1] = h23; ul[0] = l01; ul[1] = l23;
        }
    }
}

// ---------------------------------------------------------------------------
// K2: g = h·A ; bf16 hi/lo into U cols [0,128)
// ---------------------------------------------------------------------------
__global__ void __launch_bounds__(256, 2) k_gemm_g(const float* __restrict__ A) {
    __shared__ float Ht[32 * 132];
    __shared__ float At[32 * 132];
    int r0 = blockIdx.x * 128;
    int t = threadIdx.x, tx = t & 15, ty = t >> 4;
    float acc[8][8];
#pragma unroll
    for (int i = 0; i < 8; i++)
#pragma unroll
        for (int j = 0; j < 8; j++) acc[i][j] = 0.f;

#pragma unroll 1
    for (int kc = 0; kc < 128; kc += 32) {
        for (int idx = t; idx < 128 * 32; idx += 256) {
            int kk = idx & 31, row = idx >> 5;
            Ht[kk * 132 + row] = d_h[(size_t)(r0 + row) * 128 + kc + kk];
        }
        for (int idx = t; idx < 32 * 128; idx += 256) {
            int l = idx & 127, kk = idx >> 7;
            At[kk * 132 + l] = A[(kc + kk) * 128 + l];
        }
        __syncthreads();
#pragma unroll
        for (int kk = 0; kk < 32; kk++) {
            float a[8], b[8];
            *(float4*)&a[0] = *(const float4*)&Ht[kk * 132 + ty * 8];
            *(float4*)&a[4] = *(const float4*)&Ht[kk * 132 + ty * 8 + 4];
            *(float4*)&b[0] = *(const float4*)&At[kk * 132 + tx * 8];
            *(float4*)&b[4] = *(const float4*)&At[kk * 132 + tx * 8 + 4];
#pragma unroll
            for (int i = 0; i < 8; i++)
#pragma unroll
                for (int j = 0; j < 8; j++) acc[i][j] += a[i] * b[j];
        }
        __syncthreads();
    }
#pragma unroll
    for (int i = 0; i < 8; i++) {
        int r = r0 + ty * 8 + i;
#pragma unroll
        for (int jv = 0; jv < 8; jv += 4) {
            int c = tx * 8 + jv;
            uint32_t h01, l01, h23, l23;
            split2(acc[i][jv + 0], acc[i][jv + 1], h01, l01);
            split2(acc[i][jv + 2], acc[i][jv + 3], h23, l23);
            uint32_t* uh = (uint32_t*)&d_Uhi[(size_t)r * 256 + c];
            uint32_t* ul = (uint32_t*)&d_Ulo[(size_t)r * 256 + c];
            uh[0] = h01; uh[1] = h23; ul[0] = l01; ul[1] = l23;
        }
    }
}

// ---------------------------------------------------------------------------
// K3: scores via mma.sync (bf16 hi/lo, fp32 accum). e = U·V^T, K=256,
// V = half-swapped U. One 128x128 tile pair (J<=K) per block, 8 warps 32x64.
// ---------------------------------------------------------------------------
#define SC_TILE_B (128 * 24 * 2)     // 6144 B per operand tile
#define SC_SMEM   (128 * 133 * 4)    // 68096 B stash (covers 4*6144 operands)

__global__ void __launch_bounds__(256) k_scores_mma() {
    extern __shared__ char sc[];
    uint32_t sbase = smem_u32(sc);
    __nv_bfloat16* sAhi = (__nv_bfloat16*)(sc);
    __nv_bfloat16* sAlo = (__nv_bfloat16*)(sc + SC_TILE_B);
    __nv_bfloat16* sBhi = (__nv_bfloat16*)(sc + 2 * SC_TILE_B);
    __nv_bfloat16* sBlo = (__nv_bfloat16*)(sc + 3 * SC_TILE_B);

    int t = threadIdx.x, lane = t & 31, wid = t >> 5;
    int wm = wid & 3, wn = wid >> 2;

    int b = blockIdx.y;
    int rem = blockIdx.x;
    int J = 0;
    while (rem >= 8 - J) { rem -= 8 - J; J++; }
    int K = J + rem;
    int j0 = J * 128, k0 = K * 128;

    const __nv_bfloat16* Uh = d_Uhi + (size_t)b * N_ * 256;
    const __nv_bfloat16* Ul = d_Ulo + (size_t)b * N_ * 256;

    float acc[2][8][4];
#pragma unroll
    for (int i = 0; i < 2; i++)
#pragma unroll
        for (int j = 0; j < 8; j++)
#pragma unroll
            for (int q = 0; q < 4; q++) acc[i][j][q] = 0.f;

    int lrow = t >> 1, lhalf = t & 1;
    uint32_t s_off = (uint32_t)(lrow * 24 + lhalf * 8) * 2;

    uint32_t a_off[2];
#pragma unroll
    for (int mf = 0; mf < 2; mf++) {
        int rr = wm * 32 + mf * 16 + (lane & 15);
        a_off[mf] = (uint32_t)(rr * 24 + (lane >> 4) * 8) * 2;
    }
    uint32_t b_off[4];
#pragma unroll
    for (int nb = 0; nb < 4; nb++) {
        int rr = wn * 64 + nb * 16 + ((lane >> 4) << 3) + (lane & 7);
        b_off[nb] = (uint32_t)(rr * 24 + ((lane >> 3) & 1) * 8) * 2;
    }

#pragma unroll 1
    for (int ch = 0; ch < 16; ch++) {
        int ca = ch * 16;
        int cb = (ca + 128) & 255;
        {
            const uint4* gAh = (const uint4*)(Uh + (size_t)(j0 + lrow) * 256 + ca) + lhalf;
            const uint4* gAl = (const uint4*)(Ul + (size_t)(j0 + lrow) * 256 + ca) + lhalf;
            const uint4* gBh = (const uint4*)(Uh + (size_t)(k0 + lrow) * 256 + cb) + lhalf;
            const uint4* gBl = (const uint4*)(Ul + (size_t)(k0 + lrow) * 256 + cb) + lhalf;
            *(uint4*)((char*)sAhi + s_off) = *gAh;
            *(uint4*)((char*)sAlo + s_off) = *gAl;
            *(uint4*)((char*)sBhi + s_off) = *gBh;
            *(uint4*)((char*)sBlo + s_off) = *gBl;
        }
        __syncthreads();

        uint32_t ah[2][4], al[2][4];
#pragma unroll
        for (int mf = 0; mf < 2; mf++) {
            ldsm_x4(ah[mf], sbase + a_off[mf]);
            ldsm_x4(al[mf], sbase + SC_TILE_B + a_off[mf]);
        }
#pragma unroll
        for (int nb = 0; nb < 4; nb++) {
            uint32_t bh[4], bl[4];
            ldsm_x4(bh, sbase + 2 * SC_TILE_B + b_off[nb]);
            ldsm_x4(bl, sbase + 3 * SC_TILE_B + b_off[nb]);
#pragma unroll
            for (int mf = 0; mf < 2; mf++) {
#pragma unroll
                for (int sub = 0; sub < 2; sub++) {
                    float* d = acc[mf][nb * 2 + sub];
                    mma16816(d, ah[mf], bh[sub * 2], bh[sub * 2 + 1]);
                    mma16816(d, ah[mf], bl[sub * 2], bl[sub * 2 + 1]);
                    mma16816(d, al[mf], bh[sub * 2], bh[sub * 2 + 1]);
                }
            }
        }
        __syncthreads();
    }

    float* st = (float*)sc;
    int g = lane >> 2, tg = lane & 3;
#pragma unroll
    for (int mf = 0; mf < 2; mf++) {
        int rbase = wm * 32 + mf * 16;
#pragma unroll
        for (int n8 = 0; n8 < 8; n8++) {
            int cbase = wn * 64 + n8 * 8 + tg * 2;
            float* d = acc[mf][n8];
            st[(rbase + g) * 133 + cbase]         = d[0];
            st[(rbase + g) * 133 + cbase + 1]     = d[1];
            st[(rbase + g + 8) * 133 + cbase]     = d[2];
            st[(rbase + g + 8) * 133 + cbase + 1] = d[3];
        }
    }
    __syncthreads();

    float* Sb = d_S + (size_t)b * N_ * N_;
    {
        int row = t >> 1, chalf = (t & 1) * 64;
        const float* srow = st + row * 133 + chalf;
        float4* dst = (float4*)&Sb[(size_t)(j0 + row) * N_ + k0 + chalf];
#pragma unroll
        for (int q = 0; q < 16; q++) {
            float4 o;
            o.x = srow[q * 4 + 0]; o.y = srow[q * 4 + 1];
            o.z = srow[q * 4 + 2]; o.w = srow[q * 4 + 3];
            dst[q] = o;
        }
    }
    if (J != K) {
        int r = t & 127, c0 = t >> 7;
#pragma unroll 1
        for (int i = 0; i < 64; i++) {
            int c = c0 + i * 2;
            Sb[(size_t)(k0 + c) * N_ + j0 + r] = st[r * 133 + c];
        }
    }
}

// ---------------------------------------------------------------------------
// K4: transpose adj -> bf16 d_adjT (values 0/1, exact)
// ---------------------------------------------------------------------------
__global__ void k_adjT(const float* __restrict__ adj) {
    __shared__ float tile[32][33];
    int b = blockIdx.z;
    int x0 = blockIdx.x * 32, y0 = blockIdx.y * 32;
    const float* ab = adj + (size_t)b * N_ * N_;
    __nv_bfloat16* tb = d_adjT + (size_t)b * N_ * N_;
    int tx = threadIdx.x, ty = threadIdx.y;
#pragma unroll
    for (int i = 0; i < 32; i += 8)
        tile[ty + i][tx] = ab[(size_t)(y0 + ty + i) * N_ + x0 + tx];
    __syncthreads();
#pragma unroll
    for (int i = 0; i < 32; i += 8)
        tb[(size_t)(x0 + ty + i) * N_ + y0 + tx] = __float2bfloat16(tile[tx][ty + i]);
}

// ---------------------------------------------------------------------------
// K5: fused masked softmax; emits attn^T as bf16 hi/lo for the MMA consumer.
// ---------------------------------------------------------------------------
__global__ void __launch_bounds__(256) k_sm() {
    __shared__ float red_m[8], red_s[8];
    int b = blockIdx.y, r = blockIdx.x, t = threadIdx.x;
    const float* Mrow = d_S + ((size_t)b * N_ + r) * N_;
    const __nv_bfloat16* Arow = d_adjT + ((size_t)b * N_ + r) * N_;
    __nv_bfloat16* Oh = d_AThi + ((size_t)b * N_ + r) * N_;
    __nv_bfloat16* Ol = d_ATlo + ((size_t)b * N_ + r) * N_;

    float4 e4 = *(const float4*)&Mrow[t * 4];
    uint2 a2 = *(const uint2*)&Arow[t * 4];
    __nv_bfloat162 a01 = *(__nv_bfloat162*)&a2.x;
    __nv_bfloat162 a23 = *(__nv_bfloat162*)&a2.y;
    float ax = __bfloat162float(a01.x), ay = __bfloat162float(a01.y);
    float az = __bfloat162float(a23.x), aw = __bfloat162float(a23.y);

    float v0 = (ax > 0.f) ? e4.x : 0.f;
    float v1 = (ay > 0.f) ? e4.y : 0.f;
    float v2 = (az > 0.f) ? e4.z : 0.f;
    float v3 = (aw > 0.f) ? e4.w : 0.f;

    float lm = fmaxf(fmaxf(v0, v1), fmaxf(v2, v3));
#pragma unroll
    for (int o = 16; o > 0; o >>= 1)
        lm = fmaxf(lm, __shfl_xor_sync(0xffffffffu, lm, o));
    if ((t & 31) == 0) red_m[t >> 5] = lm;
    __syncthreads();
    float m = red_m[0];
#pragma unroll
    for (int i = 1; i < 8; i++) m = fmaxf(m, red_m[i]);

    float p0 = fexp(v0 - m), p1 = fexp(v1 - m);
    float p2 = fexp(v2 - m), p3 = fexp(v3 - m);
    float ls = (p0 + p1) + (p2 + p3);
#pragma unroll
    for (int o = 16; o > 0; o >>= 1)
        ls += __shfl_xor_sync(0xffffffffu, ls, o);
    if ((t & 31) == 0) red_s[t >> 5] = ls;
    __syncthreads();
    float Z = red_s[0];
#pragma unroll
    for (int i = 1; i < 8; i++) Z += red_s[i];
    float inv = 1.0f / Z;

    float r0 = p0 * inv * ax, r1 = p1 * inv * ay;
    float r2 = p2 * inv * az, r3 = p3 * inv * aw;
    uint32_t h01, l01, h23, l23;
    split2(r0, r1, h01, l01);
    split2(r2, r3, h23, l23);
    uint2 ho; ho.x = h01; ho.y = h23;
    uint2 lo; lo.x = l01; lo.y = l23;
    *(uint2*)&Oh[t * 4] = ho;
    *(uint2*)&Ol[t * 4] = lo;
}

// ---------------------------------------------------------------------------
// K6: h' = relu(att @ h) via mma.sync; A = attn^T [k=j][m=i] (ldmatrix.trans),
// B = h [k=j][n=d] hi/lo from d_Uhi/d_Ulo cols [128,256) (ldmatrix.trans).
// Gates fused in fragment epilogue. 128x128 tile, K=1024, KC=32.
// ---------------------------------------------------------------------------
__global__ void __launch_bounds__(256) k_out_mma(const float* __restrict__ x,
                                                 const float* __restrict__ wiu,
                                                 const float* __restrict__ wfu,
                                                 const float* __restrict__ wou,
                                                 float* __restrict__ out) {
    __shared__ __align__(16) __nv_bfloat16 sA[2][32 * 136];   // [hi/lo][k][m]
    __shared__ __align__(16) __nv_bfloat16 sB[2][32 * 136];   // [hi/lo][k][n]
    __shared__ float red[3][128];
    __shared__ float wu[3][128];

    int b = blockIdx.y, i0 = blockIdx.x * 128;
    int t = threadIdx.x, lane = t & 31, wid = t >> 5;
    int wm = wid & 3, wn = wid >> 2;
    if (t < 128) {
        wu[0][t] = wiu[t]; wu[1][t] = wfu[t]; wu[2][t] = wou[t];
        red[0][t] = 0.f; red[1][t] = 0.f; red[2][t] = 0.f;
    }

    const __nv_bfloat16* ATh = d_AThi + (size_t)b * N_ * N_;
    const __nv_bfloat16* ATl = d_ATlo + (size_t)b * N_ * N_;
    const __nv_bfloat16* Hh  = d_Uhi + (size_t)b * N_ * 256 + 128;
    const __nv_bfloat16* Hl  = d_Ulo + (size_t)b * N_ * 256 + 128;

    uint32_t sbA = smem_u32(sA), sbB = smem_u32(sB);
    const uint32_t LO_A = 32 * 136 * 2;   // bytes to sA[1]
    const uint32_t LO_B = 32 * 136 * 2;

    float acc[2][8][4];
#pragma unroll
    for (int i = 0; i < 2; i++)
#pragma unroll
        for (int j = 0; j < 8; j++)
#pragma unroll
            for (int q = 0; q < 4; q++) acc[i][j][q] = 0.f;

    // trans-ldmatrix per-lane offsets (within a [k][*] tile, stride 136)
    int krA = (lane & 7) + ((lane >> 4) << 3);
    int mcA = wm * 32 + ((lane >> 3) & 1) * 8;
    int krB = (lane & 7) + (((lane >> 3) & 1) << 3);
    int ncB = wn * 64 + ((lane >> 4) << 3);

    // chunk fill mapping: 512 vec8 slots, 2 per thread
    int frow0 = t >> 4, fc0 = (t & 15) * 8;          // slots 0..255
    int frow1 = (t + 256) >> 4, fc1 = fc0;           // slots 256..511

#pragma unroll 1
    for (int kc = 0; kc < N_; kc += 32) {
        {
            uint32_t so0 = (uint32_t)(frow0 * 136 + fc0) * 2;
            uint32_t so1 = (uint32_t)(frow1 * 136 + fc1) * 2;
            size_t ga0 = (size_t)(kc + frow0) * N_ + i0 + fc0;
            size_t ga1 = (size_t)(kc + frow1) * N_ + i0 + fc1;
            size_t gb0 = (size_t)(kc + frow0) * 256 + fc0;
            size_t gb1 = (size_t)(kc + frow1) * 256 + fc1;
            *(uint4*)((char*)sA[0] + so0) = *(const uint4*)(ATh + ga0);
            *(uint4*)((char*)sA[0] + so1) = *(const uint4*)(ATh + ga1);
            *(uint4*)((char*)sA[1] + so0) = *(const uint4*)(ATl + ga0);
            *(uint4*)((char*)sA[1] + so1) = *(const uint4*)(ATl + ga1);
            *(uint4*)((char*)sB[0] + so0) = *(const uint4*)(Hh + gb0);
            *(uint4*)((char*)sB[0] + so1) = *(const uint4*)(Hh + gb1);
            *(uint4*)((char*)sB[1] + so0) = *(const uint4*)(Hl + gb0);
            *(uint4*)((char*)sB[1] + so1) = *(const uint4*)(Hl + gb1);
        }
        __syncthreads();

#pragma unroll
        for (int s = 0; s < 2; s++) {
            uint32_t ah[2][4], al[2][4];
#pragma unroll
            for (int mf = 0; mf < 2; mf++) {
                uint32_t off = (uint32_t)((s * 16 + krA) * 136 + mcA + mf * 16) * 2;
                ldsm_x4_t(ah[mf], sbA + off);
                ldsm_x4_t(al[mf], sbA + LO_A + off);
            }
#pragma unroll
            for (int np = 0; np < 4; np++) {
                uint32_t boff = (uint32_t)((s * 16 + krB) * 136 + ncB + np * 16) * 2;
                uint32_t bh[4], bl[4];
                ldsm_x4_t(bh, sbB + boff);
                ldsm_x4_t(bl, sbB + LO_B + boff);
#pragma unroll
                for (int mf = 0; mf < 2; mf++) {
#pragma unroll
                    for (int sub = 0; sub < 2; sub++) {
                        float* d = acc[mf][np * 2 + sub];
                        mma16816(d, ah[mf], bh[sub * 2], bh[sub * 2 + 1]);
                        mma16816(d, ah[mf], bl[sub * 2], bl[sub * 2 + 1]);
                        mma16816(d, al[mf], bh[sub * 2], bh[sub * 2 + 1]);
                    }
                }
            }
        }
        __syncthreads();
    }

    // relu + gate partial dots (per thread over its 16 columns)
    int g = lane >> 2, q = lane & 3;
    float pp[2][2][3];
#pragma unroll
    for (int mf = 0; mf < 2; mf++)
#pragma unroll
        for (int rh = 0; rh < 2; rh++)
#pragma unroll
            for (int gg = 0; gg < 3; gg++) pp[mf][rh][gg] = 0.f;

#pragma unroll
    for (int mf = 0; mf < 2; mf++) {
#pragma unroll
        for (int n8 = 0; n8 < 8; n8++) {
            int c = wn * 64 + n8 * 8 + q * 2;
            float wa0 = wu[0][c], wb0 = wu[0][c + 1];
            float wa1 = wu[1][c], wb1 = wu[1][c + 1];
            float wa2 = wu[2][c], wb2 = wu[2][c + 1];
            float* d = acc[mf][n8];
            float v0 = fmaxf(d[0], 0.f), v1 = fmaxf(d[1], 0.f);
            float v2 = fmaxf(d[2], 0.f), v3 = fmaxf(d[3], 0.f);
            d[0] = v0; d[1] = v1; d[2] = v2; d[3] = v3;
            pp[mf][0][0] += v0 * wa0 + v1 * wb0;
            pp[mf][0][1] += v0 * wa1 + v1 * wb1;
            pp[mf][0][2] += v0 * wa2 + v1 * wb2;
            pp[mf][1][0] += v2 * wa0 + v3 * wb0;
            pp[mf][1][1] += v2 * wa1 + v3 * wb1;
            pp[mf][1][2] += v2 * wa2 + v3 * wb2;
        }
    }
#pragma unroll
    for (int mf = 0; mf < 2; mf++)
#pragma unroll
        for (int rh = 0; rh < 2; rh++) {
            float s0 = pp[mf][rh][0], s1 = pp[mf][rh][1], s2 = pp[mf][rh][2];
            s0 += __shfl_xor_sync(0xffffffffu, s0, 1);
            s0 += __shfl_xor_sync(0xffffffffu, s0, 2);
            s1 += __shfl_xor_sync(0xffffffffu, s1, 1);
            s1 += __shfl_xor_sync(0xffffffffu, s1, 2);
            s2 += __shfl_xor_sync(0xffffffffu, s2, 1);
            s2 += __shfl_xor_sync(0xffffffffu, s2, 2);
            if (q == 0) {
                int r = wm * 32 + mf * 16 + rh * 8 + g;
                atomicAdd(&red[0][r], s0);
                atomicAdd(&red[1][r], s1);
                atomicAdd(&red[2][r], s2);
            }
        }
    __syncthreads();

    int nb = b * N_ + i0;
#pragma unroll
    for (int mf = 0; mf < 2; mf++) {
#pragma unroll
        for (int rh = 0; rh < 2; rh++) {
            int r = wm * 32 + mf * 16 + rh * 8 + g;
            float zi = red[0][r] + d_xd[nb + r];
            float zf = red[1][r] + d_xd[B_ * N_ + nb + r];
            float zo = red[2][r] + d_xd[2 * B_ * N_ + nb + r];
            float ic = 1.f / (1.f + fexp(-zi));
            float fc = 1.f / (1.f + fexp(-zf));
            float oc = 1.f / (1.f + fexp(-zo));
            const float* xr = x + (size_t)(nb + r) * 128;
            float* orow = out + (size_t)(nb + r) * 128;
#pragma unroll
            for (int n8 = 0; n8 < 8; n8++) {
                int c = wn * 64 + n8 * 8 + q * 2;
                float2 xv = *(const float2*)&xr[c];
                float v0 = acc[mf][n8][rh * 2 + 0];
                float v1 = acc[mf][n8][rh * 2 + 1];
                float2 o;
                o.x = oc * tanhf(ic * v0 + fc * xv.x);
                o.y = oc * tanhf(ic * v1 + fc * xv.y);
                *(float2*)&orow[c] = o;
            }
        }
    }
}

// ---------------------------------------------------------------------------
extern "C" void kernel_launch(void* const* d_in, const int* in_sizes, int n_in,
                              void* d_out, int out_size) {
    const float* x   = (const float*)d_in[0];
    const float* adj = (const float*)d_in[1];
    const float* Ww  = (const float*)d_in[2];
    const float* Wb  = (const float*)d_in[3];
    const float* A   = (const float*)d_in[4];
    const float* wiu = (const float*)d_in[5];
    const float* wix = (const float*)d_in[6];
    const float* wfu = (const float*)d_in[7];
    const float* wfx = (const float*)d_in[8];
    const float* wou = (const float*)d_in[9];
    const float* wox = (const float*)d_in[10];
    float* out = (float*)d_out;

    static int attr_set = 0;
    if (!attr_set) {
        cudaFuncSetAttribute(k_scores_mma, cudaFuncAttributeMaxDynamicSharedMemorySize, SC_SMEM);
        attr_set = 1;
    }

    {
        dim3 g(N_ / 32, N_ / 32, B_);
        k_adjT<<<g, dim3(32, 8)>>>(adj);
    }
    k_xdots<<<B_ * N_ / 8, 256>>>(x, wix, wfx, wox);
    k_gemm_h<<<B_ * N_ / 128, 256>>>(x, Ww, Wb);
    k_gemm_g<<<B_ * N_ / 128, 256>>>(A);
    {
        dim3 g(36, B_);
        k_scores_mma<<<g, 256, SC_SMEM>>>();
    }
    {
        dim3 g(N_, B_);
        k_sm<<<g, 256>>>();
    }
    {
        dim3 g(N_ / 128, B_);
        k_out_mma<<<g, 256>>>(x, wiu, wfu, wou, out);
    }
}

// round 9
// speedup vs baseline: 3.2436x; 1.0598x over previous
#include <cuda_runtime.h>
#include <cuda_bf16.h>
#include <math.h>
#include <stdint.h>

#define B_ 16
#define N_ 1024
#define D_ 128

// Scratch (device globals — allocation-free per harness rules)
static __device__ float d_h[B_ * N_ * D_];              // 8 MB fp32
static __device__ float d_S[B_ * N_ * N_];              // 64 MB: e scores (fp32)
static __device__ __nv_bfloat16 d_adjT[B_ * N_ * N_];   // 32 MB transposed adjacency (0/1)
static __device__ float d_xd[3 * B_ * N_];              // x·w*_x per node
static __device__ __nv_bfloat16 d_Uhi[B_ * N_ * 256];   // 8 MB: [g|h] hi part
static __device__ __nv_bfloat16 d_Ulo[B_ * N_ * 256];   // 8 MB: [g|h] lo part
static __device__ __nv_bfloat16 d_AThi[B_ * N_ * N_];   // 32 MB: attn^T hi  [j][i]
static __device__ __nv_bfloat16 d_ATlo[B_ * N_ * N_];   // 32 MB: attn^T lo

// ---------------------------------------------------------------------------
__device__ __forceinline__ uint32_t smem_u32(const void* p) {
    uint32_t a;
    asm("{ .reg .u64 t; cvta.to.shared.u64 t, %1; cvt.u32.u64 %0, t; }" : "=r"(a) : "l"(p));
    return a;
}
__device__ __forceinline__ void ldsm_x4(uint32_t* r, uint32_t addr) {
    asm volatile("ldmatrix.sync.aligned.m8n8.x4.shared.b16 {%0,%1,%2,%3}, [%4];"
                 : "=r"(r[0]), "=r"(r[1]), "=r"(r[2]), "=r"(r[3]) : "r"(addr));
}
__device__ __forceinline__ void ldsm_x4_t(uint32_t* r, uint32_t addr) {
    asm volatile("ldmatrix.sync.aligned.m8n8.x4.trans.shared.b16 {%0,%1,%2,%3}, [%4];"
                 : "=r"(r[0]), "=r"(r[1]), "=r"(r[2]), "=r"(r[3]) : "r"(addr));
}
__device__ __forceinline__ void mma16816(float* d, const uint32_t* a,
                                         uint32_t b0, uint32_t b1) {
    asm volatile(
        "mma.sync.aligned.m16n8k16.row.col.f32.bf16.bf16.f32 "
        "{%0,%1,%2,%3}, {%4,%5,%6,%7}, {%8,%9}, {%0,%1,%2,%3};"
        : "+f"(d[0]), "+f"(d[1]), "+f"(d[2]), "+f"(d[3])
        : "r"(a[0]), "r"(a[1]), "r"(a[2]), "r"(a[3]), "r"(b0), "r"(b1));
}
#define CP_ASYNC16(sa, gp) \
    asm volatile("cp.async.cg.shared.global [%0], [%1], 16;" :: "r"(sa), "l"(gp))
#define CP_COMMIT() asm volatile("cp.async.commit_group;" ::: "memory")
#define CP_WAIT(n)  asm volatile("cp.async.wait_group %0;" :: "n"(n) : "memory")

// fp32 -> bf16 hi/lo split (packed pairs)
__device__ __forceinline__ void split2(float v0, float v1, uint32_t& hi, uint32_t& lo) {
    __nv_bfloat16 h0 = __float2bfloat16(v0), h1 = __float2bfloat16(v1);
    __nv_bfloat16 l0 = __float2bfloat16(v0 - __bfloat162float(h0));
    __nv_bfloat16 l1 = __float2bfloat16(v1 - __bfloat162float(h1));
    __nv_bfloat162 H = __halves2bfloat162(h0, h1);
    __nv_bfloat162 L = __halves2bfloat162(l0, l1);
    hi = *(uint32_t*)&H; lo = *(uint32_t*)&L;
}

// FMA-only exp
__device__ __forceinline__ float fexp(float x) {
    x = fmaxf(x, -87.0f);
    float y = x * 1.44269504089f;
    float n = rintf(y);
    float t = (y - n) * 0.69314718056f;
    float p = 1.38888889e-3f;
    p = fmaf(p, t, 8.33333333e-3f);
    p = fmaf(p, t, 4.16666667e-2f);
    p = fmaf(p, t, 1.66666667e-1f);
    p = fmaf(p, t, 0.5f);
    p = fmaf(p, t, 1.0f);
    p = fmaf(p, t, 1.0f);
    return p * __int_as_float(((int)n + 127) << 23);
}

// ---------------------------------------------------------------------------
// K0: per-node gate input dots
// ---------------------------------------------------------------------------
__global__ void k_xdots(const float* __restrict__ x,
                        const float* __restrict__ wix,
                        const float* __restrict__ wfx,
                        const float* __restrict__ wox) {
    int row  = blockIdx.x * 8 + (threadIdx.x >> 5);
    int lane = threadIdx.x & 31;
    float4 xv = *(const float4*)(x + (size_t)row * D_ + lane * 4);
    float4 wi = *(const float4*)(wix + lane * 4);
    float4 wf = *(const float4*)(wfx + lane * 4);
    float4 wo = *(const float4*)(wox + lane * 4);
    float s0 = xv.x * wi.x + xv.y * wi.y + xv.z * wi.z + xv.w * wi.w;
    float s1 = xv.x * wf.x + xv.y * wf.y + xv.z * wf.z + xv.w * wf.w;
    float s2 = xv.x * wo.x + xv.y * wo.y + xv.z * wo.z + xv.w * wo.w;
#pragma unroll
    for (int o = 16; o > 0; o >>= 1) {
        s0 += __shfl_xor_sync(0xffffffffu, s0, o);
        s1 += __shfl_xor_sync(0xffffffffu, s1, o);
        s2 += __shfl_xor_sync(0xffffffffu, s2, o);
    }
    if (lane == 0) {
        d_xd[row]               = s0;
        d_xd[B_ * N_ + row]     = s1;
        d_xd[2 * B_ * N_ + row] = s2;
    }
}

// ---------------------------------------------------------------------------
// K1: h = x·Ww^T + Wb ; 64-row tiles (grid 256 -> 2 CTAs/SM).
// Writes d_h fp32 AND bf16 hi/lo into U cols [128,256).
// ---------------------------------------------------------------------------
__global__ void __launch_bounds__(256, 2) k_gemm_h(const float* __restrict__ x,
                                                   const float* __restrict__ Ww,
                                                   const float* __restrict__ Wb) {
    __shared__ float Xt[32 * 68];    // [kk][row 0..63]
    __shared__ float Wt[32 * 132];   // [kk][dcol]
    int r0 = blockIdx.x * 64;
    int t = threadIdx.x, tx = t & 15, ty = t >> 4;
    float acc[4][8];
#pragma unroll
    for (int i = 0; i < 4; i++)
#pragma unroll
        for (int j = 0; j < 8; j++) acc[i][j] = 0.f;

#pragma unroll 1
    for (int kc = 0; kc < 128; kc += 32) {
        for (int idx = t; idx < 64 * 32; idx += 256) {
            int kk = idx & 31, row = idx >> 5;
            Xt[kk * 68 + row] = x[(size_t)(r0 + row) * 128 + kc + kk];
        }
        for (int idx = t; idx < 128 * 32; idx += 256) {
            int kk = idx & 31, dc = idx >> 5;
            Wt[kk * 132 + dc] = Ww[dc * 128 + kc + kk];
        }
        __syncthreads();
#pragma unroll
        for (int kk = 0; kk < 32; kk++) {
            float a[4], b[8];
            *(float4*)&a[0] = *(const float4*)&Xt[kk * 68 + ty * 4];
            *(float4*)&b[0] = *(const float4*)&Wt[kk * 132 + tx * 8];
            *(float4*)&b[4] = *(const float4*)&Wt[kk * 132 + tx * 8 + 4];
#pragma unroll
            for (int i = 0; i < 4; i++)
#pragma unroll
                for (int j = 0; j < 8; j++) acc[i][j] += a[i] * b[j];
        }
        __syncthreads();
    }
#pragma unroll
    for (int i = 0; i < 4; i++) {
        int r = r0 + ty * 4 + i;
#pragma unroll
        for (int jv = 0; jv < 8; jv += 4) {
            int c = tx * 8 + jv;
            float4 o;
            o.x = acc[i][jv + 0] + Wb[c + 0];
            o.y = acc[i][jv + 1] + Wb[c + 1];
            o.z = acc[i][jv + 2] + Wb[c + 2];
            o.w = acc[i][jv + 3] + Wb[c + 3];
            *(float4*)&d_h[(size_t)r * 128 + c] = o;
            uint32_t h01, l01, h23, l23;
            split2(o.x, o.y, h01, l01);
            split2(o.z, o.w, h23, l23);
            uint32_t* uh = (uint32_t*)&d_Uhi[(size_t)r * 256 + 128 + c];
            uint32_t* ul = (uint32_t*)&d_Ulo[(size_t)r * 256 + 128 + c];
            uh[0] = h01; uh[1] = h23; ul[0] = l01; ul[1] = l23;
        }
    }
}

// ---------------------------------------------------------------------------
// K2: g = h·A ; 64-row tiles; bf16 hi/lo into U cols [0,128)
// ---------------------------------------------------------------------------
__global__ void __launch_bounds__(256, 2) k_gemm_g(const float* __restrict__ A) {
    __shared__ float Ht[32 * 68];
    __shared__ float At[32 * 132];
    int r0 = blockIdx.x * 64;
    int t = threadIdx.x, tx = t & 15, ty = t >> 4;
    float acc[4][8];
#pragma unroll
    for (int i = 0; i < 4; i++)
#pragma unroll
        for (int j = 0; j < 8; j++) acc[i][j] = 0.f;

#pragma unroll 1
    for (int kc = 0; kc < 128; kc += 32) {
        for (int idx = t; idx < 64 * 32; idx += 256) {
            int kk = idx & 31, row = idx >> 5;
            Ht[kk * 68 + row] = d_h[(size_t)(r0 + row) * 128 + kc + kk];
        }
        for (int idx = t; idx < 32 * 128; idx += 256) {
            int l = idx & 127, kk = idx >> 7;
            At[kk * 132 + l] = A[(kc + kk) * 128 + l];
        }
        __syncthreads();
#pragma unroll
        for (int kk = 0; kk < 32; kk++) {
            float a[4], b[8];
            *(float4*)&a[0] = *(const float4*)&Ht[kk * 68 + ty * 4];
            *(float4*)&b[0] = *(const float4*)&At[kk * 132 + tx * 8];
            *(float4*)&b[4] = *(const float4*)&At[kk * 132 + tx * 8 + 4];
#pragma unroll
            for (int i = 0; i < 4; i++)
#pragma unroll
                for (int j = 0; j < 8; j++) acc[i][j] += a[i] * b[j];
        }
        __syncthreads();
    }
#pragma unroll
    for (int i = 0; i < 4; i++) {
        int r = r0 + ty * 4 + i;
#pragma unroll
        for (int jv = 0; jv < 8; jv += 4) {
            int c = tx * 8 + jv;
            uint32_t h01, l01, h23, l23;
            split2(acc[i][jv + 0], acc[i][jv + 1], h01, l01);
            split2(acc[i][jv + 2], acc[i][jv + 3], h23, l23);
            uint32_t* uh = (uint32_t*)&d_Uhi[(size_t)r * 256 + c];
            uint32_t* ul = (uint32_t*)&d_Ulo[(size_t)r * 256 + c];
            uh[0] = h01; uh[1] = h23; ul[0] = l01; ul[1] = l23;
        }
    }
}

// ---------------------------------------------------------------------------
// K3: scores via mma.sync (bf16 hi/lo). e = U·V^T, K=256, V = half-swapped U.
// One 128x128 tile pair (J<=K) per block, 8 warps 32x64.
// Double-buffered cp.async pipeline (2 stages x 4 tiles of 6144B).
// ---------------------------------------------------------------------------
#define SC_TILE_B  (128 * 24 * 2)                   // 6144 B per operand tile
#define SC_STAGE_B (4 * SC_TILE_B)                  // 24576 B per stage
#define SC_SMEM    (128 * 133 * 4)                  // 68096 B (stash > 2 stages)

__global__ void __launch_bounds__(256) k_scores_mma() {
    extern __shared__ char sc[];
    uint32_t sbase = smem_u32(sc);

    int t = threadIdx.x, lane = t & 31, wid = t >> 5;
    int wm = wid & 3, wn = wid >> 2;

    int b = blockIdx.y;
    int rem = blockIdx.x;
    int J = 0;
    while (rem >= 8 - J) { rem -= 8 - J; J++; }
    int K = J + rem;
    int j0 = J * 128, k0 = K * 128;

    const __nv_bfloat16* Uh = d_Uhi + (size_t)b * N_ * 256;
    const __nv_bfloat16* Ul = d_Ulo + (size_t)b * N_ * 256;

    float acc[2][8][4];
#pragma unroll
    for (int i = 0; i < 2; i++)
#pragma unroll
        for (int j = 0; j < 8; j++)
#pragma unroll
            for (int q = 0; q < 4; q++) acc[i][j][q] = 0.f;

    int lrow = t >> 1, lhalf = t & 1;
    uint32_t s_off = (uint32_t)(lrow * 24 + lhalf * 8) * 2;

    uint32_t a_off[2];
#pragma unroll
    for (int mf = 0; mf < 2; mf++) {
        int rr = wm * 32 + mf * 16 + (lane & 15);
        a_off[mf] = (uint32_t)(rr * 24 + (lane >> 4) * 8) * 2;
    }
    uint32_t b_off[4];
#pragma unroll
    for (int nb = 0; nb < 4; nb++) {
        int rr = wn * 64 + nb * 16 + ((lane >> 4) << 3) + (lane & 7);
        b_off[nb] = (uint32_t)(rr * 24 + ((lane >> 3) & 1) * 8) * 2;
    }

    // issue cp.async loads for chunk ch into stage st
    auto load_chunk = [&](int ch, int st) {
        int ca = ch * 16;
        int cb = (ca + 128) & 255;
        uint32_t sb = sbase + st * SC_STAGE_B + s_off;
        const char* gAh = (const char*)(Uh + (size_t)(j0 + lrow) * 256 + ca) + lhalf * 16;
        const char* gAl = (const char*)(Ul + (size_t)(j0 + lrow) * 256 + ca) + lhalf * 16;
        const char* gBh = (const char*)(Uh + (size_t)(k0 + lrow) * 256 + cb) + lhalf * 16;
        const char* gBl = (const char*)(Ul + (size_t)(k0 + lrow) * 256 + cb) + lhalf * 16;
        CP_ASYNC16(sb,                 gAh);
        CP_ASYNC16(sb + SC_TILE_B,     gAl);
        CP_ASYNC16(sb + 2 * SC_TILE_B, gBh);
        CP_ASYNC16(sb + 3 * SC_TILE_B, gBl);
    };

    load_chunk(0, 0);
    CP_COMMIT();

#pragma unroll 1
    for (int ch = 0; ch < 16; ch++) {
        if (ch + 1 < 16) {
            load_chunk(ch + 1, (ch + 1) & 1);
            CP_COMMIT();
            CP_WAIT(1);
        } else {
            CP_WAIT(0);
        }
        __syncthreads();

        uint32_t stb = sbase + (ch & 1) * SC_STAGE_B;
        uint32_t ah[2][4], al[2][4];
#pragma unroll
        for (int mf = 0; mf < 2; mf++) {
            ldsm_x4(ah[mf], stb + a_off[mf]);
            ldsm_x4(al[mf], stb + SC_TILE_B + a_off[mf]);
        }
#pragma unroll
        for (int nb = 0; nb < 4; nb++) {
            uint32_t bh[4], bl[4];
            ldsm_x4(bh, stb + 2 * SC_TILE_B + b_off[nb]);
            ldsm_x4(bl, stb + 3 * SC_TILE_B + b_off[nb]);
#pragma unroll
            for (int mf = 0; mf < 2; mf++) {
#pragma unroll
                for (int sub = 0; sub < 2; sub++) {
                    float* d = acc[mf][nb * 2 + sub];
                    mma16816(d, ah[mf], bh[sub * 2], bh[sub * 2 + 1]);
                    mma16816(d, ah[mf], bl[sub * 2], bl[sub * 2 + 1]);
                    mma16816(d, al[mf], bh[sub * 2], bh[sub * 2 + 1]);
                }
            }
        }
        __syncthreads();
    }

    float* st = (float*)sc;
    int g = lane >> 2, tg = lane & 3;
#pragma unroll
    for (int mf = 0; mf < 2; mf++) {
        int rbase = wm * 32 + mf * 16;
#pragma unroll
        for (int n8 = 0; n8 < 8; n8++) {
            int cbase = wn * 64 + n8 * 8 + tg * 2;
            float* d = acc[mf][n8];
            st[(rbase + g) * 133 + cbase]         = d[0];
            st[(rbase + g) * 133 + cbase + 1]     = d[1];
            st[(rbase + g + 8) * 133 + cbase]     = d[2];
            st[(rbase + g + 8) * 133 + cbase + 1] = d[3];
        }
    }
    __syncthreads();

    float* Sb = d_S + (size_t)b * N_ * N_;
    {
        int row = t >> 1, chalf = (t & 1) * 64;
        const float* srow = st + row * 133 + chalf;
        float4* dst = (float4*)&Sb[(size_t)(j0 + row) * N_ + k0 + chalf];
#pragma unroll
        for (int q = 0; q < 16; q++) {
            float4 o;
            o.x = srow[q * 4 + 0]; o.y = srow[q * 4 + 1];
            o.z = srow[q * 4 + 2]; o.w = srow[q * 4 + 3];
            dst[q] = o;
        }
    }
    if (J != K) {
        int r = t & 127, c0 = t >> 7;
#pragma unroll 1
        for (int i = 0; i < 64; i++) {
            int c = c0 + i * 2;
            Sb[(size_t)(k0 + c) * N_ + j0 + r] = st[r * 133 + c];
        }
    }
}

// ---------------------------------------------------------------------------
// K4: transpose adj -> bf16 d_adjT (values 0/1, exact)
// ---------------------------------------------------------------------------
__global__ void k_adjT(const float* __restrict__ adj) {
    __shared__ float tile[32][33];
    int b = blockIdx.z;
    int x0 = blockIdx.x * 32, y0 = blockIdx.y * 32;
    const float* ab = adj + (size_t)b * N_ * N_;
    __nv_bfloat16* tb = d_adjT + (size_t)b * N_ * N_;
    int tx = threadIdx.x, ty = threadIdx.y;
#pragma unroll
    for (int i = 0; i < 32; i += 8)
        tile[ty + i][tx] = ab[(size_t)(y0 + ty + i) * N_ + x0 + tx];
    __syncthreads();
#pragma unroll
    for (int i = 0; i < 32; i += 8)
        tb[(size_t)(x0 + ty + i) * N_ + y0 + tx] = __float2bfloat16(tile[tx][ty + i]);
}

// ---------------------------------------------------------------------------
// K5: fused masked softmax; emits attn^T as bf16 hi/lo for the MMA consumer.
// ---------------------------------------------------------------------------
__global__ void __launch_bounds__(256) k_sm() {
    __shared__ float red_m[8], red_s[8];
    int b = blockIdx.y, r = blockIdx.x, t = threadIdx.x;
    const float* Mrow = d_S + ((size_t)b * N_ + r) * N_;
    const __nv_bfloat16* Arow = d_adjT + ((size_t)b * N_ + r) * N_;
    __nv_bfloat16* Oh = d_AThi + ((size_t)b * N_ + r) * N_;
    __nv_bfloat16* Ol = d_ATlo + ((size_t)b * N_ + r) * N_;

    float4 e4 = *(const float4*)&Mrow[t * 4];
    uint2 a2 = *(const uint2*)&Arow[t * 4];
    __nv_bfloat162 a01 = *(__nv_bfloat162*)&a2.x;
    __nv_bfloat162 a23 = *(__nv_bfloat162*)&a2.y;
    float ax = __bfloat162float(a01.x), ay = __bfloat162float(a01.y);
    float az = __bfloat162float(a23.x), aw = __bfloat162float(a23.y);

    float v0 = (ax > 0.f) ? e4.x : 0.f;
    float v1 = (ay > 0.f) ? e4.y : 0.f;
    float v2 = (az > 0.f) ? e4.z : 0.f;
    float v3 = (aw > 0.f) ? e4.w : 0.f;

    float lm = fmaxf(fmaxf(v0, v1), fmaxf(v2, v3));
#pragma unroll
    for (int o = 16; o > 0; o >>= 1)
        lm = fmaxf(lm, __shfl_xor_sync(0xffffffffu, lm, o));
    if ((t & 31) == 0) red_m[t >> 5] = lm;
    __syncthreads();
    float m = red_m[0];
#pragma unroll
    for (int i = 1; i < 8; i++) m = fmaxf(m, red_m[i]);

    float p0 = fexp(v0 - m), p1 = fexp(v1 - m);
    float p2 = fexp(v2 - m), p3 = fexp(v3 - m);
    float ls = (p0 + p1) + (p2 + p3);
#pragma unroll
    for (int o = 16; o > 0; o >>= 1)
        ls += __shfl_xor_sync(0xffffffffu, ls, o);
    if ((t & 31) == 0) red_s[t >> 5] = ls;
    __syncthreads();
    float Z = red_s[0];
#pragma unroll
    for (int i = 1; i < 8; i++) Z += red_s[i];
    float inv = 1.0f / Z;

    float r0 = p0 * inv * ax, r1 = p1 * inv * ay;
    float r2 = p2 * inv * az, r3 = p3 * inv * aw;
    uint32_t h01, l01, h23, l23;
    split2(r0, r1, h01, l01);
    split2(r2, r3, h23, l23);
    uint2 ho; ho.x = h01; ho.y = h23;
    uint2 lo; lo.x = l01; lo.y = l23;
    *(uint2*)&Oh[t * 4] = ho;
    *(uint2*)&Ol[t * 4] = lo;
}

// ---------------------------------------------------------------------------
// K6: h' = relu(att @ h) via mma.sync (trans-ldmatrix operands), gates fused.
// Double-buffered cp.async pipeline. Dynamic smem: 2 stages x 4 tiles of
// 32x136 bf16 (8704B) = 69632B.
// ---------------------------------------------------------------------------
#define KO_TILE_B  (32 * 136 * 2)                   // 8704 B
#define KO_STAGE_B (4 * KO_TILE_B)                  // 34816 B
#define KO_SMEM    (2 * KO_STAGE_B)                 // 69632 B

__global__ void __launch_bounds__(256) k_out_mma(const float* __restrict__ x,
                                                 const float* __restrict__ wiu,
                                                 const float* __restrict__ wfu,
                                                 const float* __restrict__ wou,
                                                 float* __restrict__ out) {
    extern __shared__ char ko[];
    __shared__ float red[3][128];
    __shared__ float wu[3][128];

    int b = blockIdx.y, i0 = blockIdx.x * 128;
    int t = threadIdx.x, lane = t & 31, wid = t >> 5;
    int wm = wid & 3, wn = wid >> 2;
    if (t < 128) {
        wu[0][t] = wiu[t]; wu[1][t] = wfu[t]; wu[2][t] = wou[t];
        red[0][t] = 0.f; red[1][t] = 0.f; red[2][t] = 0.f;
    }

    const __nv_bfloat16* ATh = d_AThi + (size_t)b * N_ * N_;
    const __nv_bfloat16* ATl = d_ATlo + (size_t)b * N_ * N_;
    const __nv_bfloat16* Hh  = d_Uhi + (size_t)b * N_ * 256 + 128;
    const __nv_bfloat16* Hl  = d_Ulo + (size_t)b * N_ * 256 + 128;

    uint32_t sb0 = smem_u32(ko);

    float acc[2][8][4];
#pragma unroll
    for (int i = 0; i < 2; i++)
#pragma unroll
        for (int j = 0; j < 8; j++)
#pragma unroll
            for (int q = 0; q < 4; q++) acc[i][j][q] = 0.f;

    // trans-ldmatrix per-lane offsets (within a [k][*] tile, stride 136)
    int krA = (lane & 7) + ((lane >> 4) << 3);
    int mcA = wm * 32 + ((lane >> 3) & 1) * 8;
    int krB = (lane & 7) + (((lane >> 3) & 1) << 3);
    int ncB = wn * 64 + ((lane >> 4) << 3);

    // chunk fill mapping: 512 vec8 slots, 2 per thread
    int frow0 = t >> 4, fc0 = (t & 15) * 8;
    int frow1 = (t + 256) >> 4;

    auto load_chunk = [&](int kc, int st) {
        uint32_t base = sb0 + st * KO_STAGE_B;
        uint32_t so0 = (uint32_t)(frow0 * 136 + fc0) * 2;
        uint32_t so1 = (uint32_t)(frow1 * 136 + fc0) * 2;
        const char* ga0 = (const char*)(ATh + (size_t)(kc + frow0) * N_ + i0 + fc0);
        const char* ga1 = (const char*)(ATh + (size_t)(kc + frow1) * N_ + i0 + fc0);
        const char* gal0 = (const char*)(ATl + (size_t)(kc + frow0) * N_ + i0 + fc0);
        const char* gal1 = (const char*)(ATl + (size_t)(kc + frow1) * N_ + i0 + fc0);
        const char* gb0 = (const char*)(Hh + (size_t)(kc + frow0) * 256 + fc0);
        const char* gb1 = (const char*)(Hh + (size_t)(kc + frow1) * 256 + fc0);
        const char* gbl0 = (const char*)(Hl + (size_t)(kc + frow0) * 256 + fc0);
        const char* gbl1 = (const char*)(Hl + (size_t)(kc + frow1) * 256 + fc0);
        CP_ASYNC16(base + so0,                  ga0);
        CP_ASYNC16(base + so1,                  ga1);
        CP_ASYNC16(base + KO_TILE_B + so0,      gal0);
        CP_ASYNC16(base + KO_TILE_B + so1,      gal1);
        CP_ASYNC16(base + 2 * KO_TILE_B + so0,  gb0);
        CP_ASYNC16(base + 2 * KO_TILE_B + so1,  gb1);
        CP_ASYNC16(base + 3 * KO_TILE_B + so0,  gbl0);
        CP_ASYNC16(base + 3 * KO_TILE_B + so1,  gbl1);
    };

    load_chunk(0, 0);
    CP_COMMIT();

#pragma unroll 1
    for (int it = 0; it < 32; it++) {
        if (it + 1 < 32) {
            load_chunk((it + 1) * 32, (it + 1) & 1);
            CP_COMMIT();
            CP_WAIT(1);
        } else {
            CP_WAIT(0);
        }
        __syncthreads();

        uint32_t base = sb0 + (it & 1) * KO_STAGE_B;
#pragma unroll
        for (int s = 0; s < 2; s++) {
            uint32_t ah[2][4], al[2][4];
#pragma unroll
            for (int mf = 0; mf < 2; mf++) {
                uint32_t off = (uint32_t)((s * 16 + krA) * 136 + mcA + mf * 16) * 2;
                ldsm_x4_t(ah[mf], base + off);
                ldsm_x4_t(al[mf], base + KO_TILE_B + off);
            }
#pragma unroll
            for (int np = 0; np < 4; np++) {
                uint32_t boff = (uint32_t)((s * 16 + krB) * 136 + ncB + np * 16) * 2;
                uint32_t bh[4], bl[4];
                ldsm_x4_t(bh, base + 2 * KO_TILE_B + boff);
                ldsm_x4_t(bl, base + 3 * KO_TILE_B + boff);
#pragma unroll
                for (int mf = 0; mf < 2; mf++) {
#pragma unroll
                    for (int sub = 0; sub < 2; sub++) {
                        float* d = acc[mf][np * 2 + sub];
                        mma16816(d, ah[mf], bh[sub * 2], bh[sub * 2 + 1]);
                        mma16816(d, ah[mf], bl[sub * 2], bl[sub * 2 + 1]);
                        mma16816(d, al[mf], bh[sub * 2], bh[sub * 2 + 1]);
                    }
                }
            }
        }
        __syncthreads();
    }

    // relu + gate partial dots
    int g = lane >> 2, q = lane & 3;
    float pp[2][2][3];
#pragma unroll
    for (int mf = 0; mf < 2; mf++)
#pragma unroll
        for (int rh = 0; rh < 2; rh++)
#pragma unroll
            for (int gg = 0; gg < 3; gg++) pp[mf][rh][gg] = 0.f;

#pragma unroll
    for (int mf = 0; mf < 2; mf++) {
#pragma unroll
        for (int n8 = 0; n8 < 8; n8++) {
            int c = wn * 64 + n8 * 8 + q * 2;
            float wa0 = wu[0][c], wb0 = wu[0][c + 1];
            float wa1 = wu[1][c], wb1 = wu[1][c + 1];
            float wa2 = wu[2][c], wb2 = wu[2][c + 1];
            float* d = acc[mf][n8];
            float v0 = fmaxf(d[0], 0.f), v1 = fmaxf(d[1], 0.f);
            float v2 = fmaxf(d[2], 0.f), v3 = fmaxf(d[3], 0.f);
            d[0] = v0; d[1] = v1; d[2] = v2; d[3] = v3;
            pp[mf][0][0] += v0 * wa0 + v1 * wb0;
            pp[mf][0][1] += v0 * wa1 + v1 * wb1;
            pp[mf][0][2] += v0 * wa2 + v1 * wb2;
            pp[mf][1][0] += v2 * wa0 + v3 * wb0;
            pp[mf][1][1] += v2 * wa1 + v3 * wb1;
            pp[mf][1][2] += v2 * wa2 + v3 * wb2;
        }
    }
#pragma unroll
    for (int mf = 0; mf < 2; mf++)
#pragma unroll
        for (int rh = 0; rh < 2; rh++) {
            float s0 = pp[mf][rh][0], s1 = pp[mf][rh][1], s2 = pp[mf][rh][2];
            s0 += __shfl_xor_sync(0xffffffffu, s0, 1);
            s0 += __shfl_xor_sync(0xffffffffu, s0, 2);
            s1 += __shfl_xor_sync(0xffffffffu, s1, 1);
            s1 += __shfl_xor_sync(0xffffffffu, s1, 2);
            s2 += __shfl_xor_sync(0xffffffffu, s2, 1);
            s2 += __shfl_xor_sync(0xffffffffu, s2, 2);
            if (q == 0) {
                int r = wm * 32 + mf * 16 + rh * 8 + g;
                atomicAdd(&red[0][r], s0);
                atomicAdd(&red[1][r], s1);
                atomicAdd(&red[2][r], s2);
            }
        }
    __syncthreads();

    int nb = b * N_ + i0;
#pragma unroll
    for (int mf = 0; mf < 2; mf++) {
#pragma unroll
        for (int rh = 0; rh < 2; rh++) {
            int r = wm * 32 + mf * 16 + rh * 8 + g;
            float zi = red[0][r] + d_xd[nb + r];
            float zf = red[1][r] + d_xd[B_ * N_ + nb + r];
            float zo = red[2][r] + d_xd[2 * B_ * N_ + nb + r];
            float ic = 1.f / (1.f + fexp(-zi));
            float fc = 1.f / (1.f + fexp(-zf));
            float oc = 1.f / (1.f + fexp(-zo));
            const float* xr = x + (size_t)(nb + r) * 128;
            float* orow = out + (size_t)(nb + r) * 128;
#pragma unroll
            for (int n8 = 0; n8 < 8; n8++) {
                int c = wn * 64 + n8 * 8 + q * 2;
                float2 xv = *(const float2*)&xr[c];
                float v0 = acc[mf][n8][rh * 2 + 0];
                float v1 = acc[mf][n8][rh * 2 + 1];
                float2 o;
                o.x = oc * tanhf(ic * v0 + fc * xv.x);
                o.y = oc * tanhf(ic * v1 + fc * xv.y);
                *(float2*)&orow[c] = o;
            }
        }
    }
}

// ---------------------------------------------------------------------------
extern "C" void kernel_launch(void* const* d_in, const int* in_sizes, int n_in,
                              void* d_out, int out_size) {
    const float* x   = (const float*)d_in[0];
    const float* adj = (const float*)d_in[1];
    const float* Ww  = (const float*)d_in[2];
    const float* Wb  = (const float*)d_in[3];
    const float* A   = (const float*)d_in[4];
    const float* wiu = (const float*)d_in[5];
    const float* wix = (const float*)d_in[6];
    const float* wfu = (const float*)d_in[7];
    const float* wfx = (const float*)d_in[8];
    const float* wou = (const float*)d_in[9];
    const float* wox = (const float*)d_in[10];
    float* out = (float*)d_out;

    static int attr_set = 0;
    if (!attr_set) {
        cudaFuncSetAttribute(k_scores_mma, cudaFuncAttributeMaxDynamicSharedMemorySize, SC_SMEM);
        cudaFuncSetAttribute(k_out_mma, cudaFuncAttributeMaxDynamicSharedMemorySize, KO_SMEM);
        attr_set = 1;
    }

    {
        dim3 g(N_ / 32, N_ / 32, B_);
        k_adjT<<<g, dim3(32, 8)>>>(adj);
    }
    k_xdots<<<B_ * N_ / 8, 256>>>(x, wix, wfx, wox);
    k_gemm_h<<<B_ * N_ / 64, 256>>>(x, Ww, Wb);
    k_gemm_g<<<B_ * N_ / 64, 256>>>(A);
    {
        dim3 g(36, B_);
        k_scores_mma<<<g, 256, SC_SMEM>>>();
    }
    {
        dim3 g(N_, B_);
        k_sm<<<g, 256>>>();
    }
    {
        dim3 g(N_ / 128, B_);
        k_out_mma<<<g, 256, KO_SMEM>>>(x, wiu, wfu, wou, out);
    }
}

// round 10
// speedup vs baseline: 3.7911x; 1.1688x over previous
#include <cuda_runtime.h>
#include <cuda_bf16.h>
#include <math.h>
#include <stdint.h>

#define B_ 16
#define N_ 1024
#define D_ 128

// Scratch (device globals — allocation-free per harness rules)
static __device__ float d_S[B_ * N_ * N_];              // 64 MB: e scores (fp32)
static __device__ __nv_bfloat16 d_adjT[B_ * N_ * N_];   // 32 MB transposed adjacency (0/1)
static __device__ float d_xd[3 * B_ * N_];              // x·w*_x per node
static __device__ __nv_bfloat16 d_Uhi[B_ * N_ * 256];   // 8 MB: [g|h] hi part
static __device__ __nv_bfloat16 d_Ulo[B_ * N_ * 256];   // 8 MB: [g|h] lo part
static __device__ __nv_bfloat16 d_AThi[B_ * N_ * N_];   // 32 MB: attn^T hi  [j][i]
static __device__ __nv_bfloat16 d_ATlo[B_ * N_ * N_];   // 32 MB: attn^T lo
static __device__ __nv_bfloat16 d_Xhi[B_ * N_ * D_];    // 4 MB: x hi
static __device__ __nv_bfloat16 d_Xlo[B_ * N_ * D_];    // 4 MB: x lo
static __device__ __nv_bfloat16 d_Whi[D_ * D_];         // Ww [n][k] hi
static __device__ __nv_bfloat16 d_Wlo[D_ * D_];
static __device__ __nv_bfloat16 d_Amhi[D_ * D_];        // A [k][n] hi
static __device__ __nv_bfloat16 d_Amlo[D_ * D_];

// ---------------------------------------------------------------------------
__device__ __forceinline__ uint32_t smem_u32(const void* p) {
    uint32_t a;
    asm("{ .reg .u64 t; cvta.to.shared.u64 t, %1; cvt.u32.u64 %0, t; }" : "=r"(a) : "l"(p));
    return a;
}
__device__ __forceinline__ void ldsm_x4(uint32_t* r, uint32_t addr) {
    asm volatile("ldmatrix.sync.aligned.m8n8.x4.shared.b16 {%0,%1,%2,%3}, [%4];"
                 : "=r"(r[0]), "=r"(r[1]), "=r"(r[2]), "=r"(r[3]) : "r"(addr));
}
__device__ __forceinline__ void ldsm_x4_t(uint32_t* r, uint32_t addr) {
    asm volatile("ldmatrix.sync.aligned.m8n8.x4.trans.shared.b16 {%0,%1,%2,%3}, [%4];"
                 : "=r"(r[0]), "=r"(r[1]), "=r"(r[2]), "=r"(r[3]) : "r"(addr));
}
__device__ __forceinline__ void mma16816(float* d, const uint32_t* a,
                                         uint32_t b0, uint32_t b1) {
    asm volatile(
        "mma.sync.aligned.m16n8k16.row.col.f32.bf16.bf16.f32 "
        "{%0,%1,%2,%3}, {%4,%5,%6,%7}, {%8,%9}, {%0,%1,%2,%3};"
        : "+f"(d[0]), "+f"(d[1]), "+f"(d[2]), "+f"(d[3])
        : "r"(a[0]), "r"(a[1]), "r"(a[2]), "r"(a[3]), "r"(b0), "r"(b1));
}
#define CP_ASYNC16(sa, gp) \
    asm volatile("cp.async.cg.shared.global [%0], [%1], 16;" :: "r"(sa), "l"(gp))
#define CP_COMMIT() asm volatile("cp.async.commit_group;" ::: "memory")
#define CP_WAIT(n)  asm volatile("cp.async.wait_group %0;" :: "n"(n) : "memory")

// fp32 -> bf16 hi/lo split (packed pairs)
__device__ __forceinline__ void split2(float v0, float v1, uint32_t& hi, uint32_t& lo) {
    __nv_bfloat16 h0 = __float2bfloat16(v0), h1 = __float2bfloat16(v1);
    __nv_bfloat16 l0 = __float2bfloat16(v0 - __bfloat162float(h0));
    __nv_bfloat16 l1 = __float2bfloat16(v1 - __bfloat162float(h1));
    __nv_bfloat162 H = __halves2bfloat162(h0, h1);
    __nv_bfloat162 L = __halves2bfloat162(l0, l1);
    hi = *(uint32_t*)&H; lo = *(uint32_t*)&L;
}

// FMA-only exp
__device__ __forceinline__ float fexp(float x) {
    x = fmaxf(x, -87.0f);
    float y = x * 1.44269504089f;
    float n = rintf(y);
    float t = (y - n) * 0.69314718056f;
    float p = 1.38888889e-3f;
    p = fmaf(p, t, 8.33333333e-3f);
    p = fmaf(p, t, 4.16666667e-2f);
    p = fmaf(p, t, 1.66666667e-1f);
    p = fmaf(p, t, 0.5f);
    p = fmaf(p, t, 1.0f);
    p = fmaf(p, t, 1.0f);
    return p * __int_as_float(((int)n + 127) << 23);
}

// ---------------------------------------------------------------------------
// K0a: split x -> bf16 hi/lo
// ---------------------------------------------------------------------------
__global__ void k_split_x(const float* __restrict__ x) {
    size_t i = ((size_t)blockIdx.x * 256 + threadIdx.x) * 4;
    float4 v = *(const float4*)(x + i);
    uint32_t h01, l01, h23, l23;
    split2(v.x, v.y, h01, l01);
    split2(v.z, v.w, h23, l23);
    uint2 h; h.x = h01; h.y = h23;
    uint2 l; l.x = l01; l.y = l23;
    *(uint2*)&d_Xhi[i] = h;
    *(uint2*)&d_Xlo[i] = l;
}

// K0b: split Ww and A -> bf16 hi/lo (tiny)
__global__ void k_split_w(const float* __restrict__ Ww, const float* __restrict__ A) {
    int i = blockIdx.x * 256 + threadIdx.x;   // 0..16383
    float wv = Ww[i];
    __nv_bfloat16 wh = __float2bfloat16(wv);
    d_Whi[i] = wh;
    d_Wlo[i] = __float2bfloat16(wv - __bfloat162float(wh));
    float av = A[i];
    __nv_bfloat16 ah = __float2bfloat16(av);
    d_Amhi[i] = ah;
    d_Amlo[i] = __float2bfloat16(av - __bfloat162float(ah));
}

// ---------------------------------------------------------------------------
// K0c: per-node gate input dots
// ---------------------------------------------------------------------------
__global__ void k_xdots(const float* __restrict__ x,
                        const float* __restrict__ wix,
                        const float* __restrict__ wfx,
                        const float* __restrict__ wox) {
    int row  = blockIdx.x * 8 + (threadIdx.x >> 5);
    int lane = threadIdx.x & 31;
    float4 xv = *(const float4*)(x + (size_t)row * D_ + lane * 4);
    float4 wi = *(const float4*)(wix + lane * 4);
    float4 wf = *(const float4*)(wfx + lane * 4);
    float4 wo = *(const float4*)(wox + lane * 4);
    float s0 = xv.x * wi.x + xv.y * wi.y + xv.z * wi.z + xv.w * wi.w;
    float s1 = xv.x * wf.x + xv.y * wf.y + xv.z * wf.z + xv.w * wf.w;
    float s2 = xv.x * wo.x + xv.y * wo.y + xv.z * wo.z + xv.w * wo.w;
#pragma unroll
    for (int o = 16; o > 0; o >>= 1) {
        s0 += __shfl_xor_sync(0xffffffffu, s0, o);
        s1 += __shfl_xor_sync(0xffffffffu, s1, o);
        s2 += __shfl_xor_sync(0xffffffffu, s2, o);
    }
    if (lane == 0) {
        d_xd[row]               = s0;
        d_xd[B_ * N_ + row]     = s1;
        d_xd[2 * B_ * N_ + row] = s2;
    }
}

// ---------------------------------------------------------------------------
// K1: h = x·Ww^T + Wb via mma.sync (bf16 hi/lo). Writes U cols [128,256)
// hi/lo directly from fragments. A = x [m][k] (non-trans), B = Ww [n][k]
// (non-trans). 128x128 tile, K=128, 2-stage cp.async.
// ---------------------------------------------------------------------------
#define GH_TILE_B  (128 * 24 * 2)      // 6144 B
#define GH_STAGE_B (4 * GH_TILE_B)     // 24576 B
#define GH_SMEM    (2 * GH_STAGE_B)    // 49152 B

__global__ void __launch_bounds__(256) k_gemm_h_mma(const float* __restrict__ Wb) {
    extern __shared__ char gh[];
    __shared__ float wb[128];
    uint32_t sbase = smem_u32(gh);
    int t = threadIdx.x, lane = t & 31, wid = t >> 5;
    int wm = wid & 3, wn = wid >> 2;
    if (t < 128) wb[t] = Wb[t];
    int j0 = blockIdx.x * 128;

    float acc[2][8][4];
#pragma unroll
    for (int i = 0; i < 2; i++)
#pragma unroll
        for (int j = 0; j < 8; j++)
#pragma unroll
            for (int q = 0; q < 4; q++) acc[i][j][q] = 0.f;

    int lrow = t >> 1, lhalf = t & 1;
    uint32_t s_off = (uint32_t)(lrow * 24 + lhalf * 8) * 2;

    uint32_t a_off[2];
#pragma unroll
    for (int mf = 0; mf < 2; mf++) {
        int rr = wm * 32 + mf * 16 + (lane & 15);
        a_off[mf] = (uint32_t)(rr * 24 + (lane >> 4) * 8) * 2;
    }
    uint32_t b_off[4];
#pragma unroll
    for (int nb = 0; nb < 4; nb++) {
        int rr = wn * 64 + nb * 16 + ((lane >> 4) << 3) + (lane & 7);
        b_off[nb] = (uint32_t)(rr * 24 + ((lane >> 3) & 1) * 8) * 2;
    }

    auto load_chunk = [&](int ch, int st) {
        uint32_t sb = sbase + st * GH_STAGE_B + s_off;
        const char* gxh = (const char*)(d_Xhi + (size_t)(j0 + lrow) * 128 + ch * 16) + lhalf * 16;
        const char* gxl = (const char*)(d_Xlo + (size_t)(j0 + lrow) * 128 + ch * 16) + lhalf * 16;
        const char* gwh = (const char*)(d_Whi + lrow * 128 + ch * 16) + lhalf * 16;
        const char* gwl = (const char*)(d_Wlo + lrow * 128 + ch * 16) + lhalf * 16;
        CP_ASYNC16(sb,                 gxh);
        CP_ASYNC16(sb + GH_TILE_B,     gxl);
        CP_ASYNC16(sb + 2 * GH_TILE_B, gwh);
        CP_ASYNC16(sb + 3 * GH_TILE_B, gwl);
    };

    load_chunk(0, 0);
    CP_COMMIT();

#pragma unroll 1
    for (int ch = 0; ch < 8; ch++) {
        if (ch + 1 < 8) {
            load_chunk(ch + 1, (ch + 1) & 1);
            CP_COMMIT();
            CP_WAIT(1);
        } else {
            CP_WAIT(0);
        }
        __syncthreads();

        uint32_t stb = sbase + (ch & 1) * GH_STAGE_B;
        uint32_t ah[2][4], al[2][4];
#pragma unroll
        for (int mf = 0; mf < 2; mf++) {
            ldsm_x4(ah[mf], stb + a_off[mf]);
            ldsm_x4(al[mf], stb + GH_TILE_B + a_off[mf]);
        }
#pragma unroll
        for (int nb = 0; nb < 4; nb++) {
            uint32_t bh[4], bl[4];
            ldsm_x4(bh, stb + 2 * GH_TILE_B + b_off[nb]);
            ldsm_x4(bl, stb + 3 * GH_TILE_B + b_off[nb]);
#pragma unroll
            for (int mf = 0; mf < 2; mf++) {
#pragma unroll
                for (int sub = 0; sub < 2; sub++) {
                    float* d = acc[mf][nb * 2 + sub];
                    mma16816(d, ah[mf], bh[sub * 2], bh[sub * 2 + 1]);
                    mma16816(d, ah[mf], bl[sub * 2], bl[sub * 2 + 1]);
                    mma16816(d, al[mf], bh[sub * 2], bh[sub * 2 + 1]);
                }
            }
        }
        __syncthreads();
    }

    // epilogue: +bias, split, write U cols [128,256)
    int g = lane >> 2, q = lane & 3;
#pragma unroll
    for (int mf = 0; mf < 2; mf++) {
#pragma unroll
        for (int n8 = 0; n8 < 8; n8++) {
            int c = wn * 64 + n8 * 8 + q * 2;
            float* d = acc[mf][n8];
            int r0 = j0 + wm * 32 + mf * 16 + g;
            float b0 = wb[c], b1 = wb[c + 1];
            uint32_t hi, lo;
            split2(d[0] + b0, d[1] + b1, hi, lo);
            *(uint32_t*)&d_Uhi[(size_t)r0 * 256 + 128 + c] = hi;
            *(uint32_t*)&d_Ulo[(size_t)r0 * 256 + 128 + c] = lo;
            split2(d[2] + b0, d[3] + b1, hi, lo);
            *(uint32_t*)&d_Uhi[(size_t)(r0 + 8) * 256 + 128 + c] = hi;
            *(uint32_t*)&d_Ulo[(size_t)(r0 + 8) * 256 + 128 + c] = lo;
        }
    }
}

// ---------------------------------------------------------------------------
// K2: g = h·A via mma.sync. A-op = h hi/lo (U cols [128,256), [m][k],
// non-trans), B-op = A matrix [k][n] row-major (trans ldmatrix).
// Writes U cols [0,128).
// ---------------------------------------------------------------------------
#define GG_ATILE_B (128 * 24 * 2)                       // 6144 B
#define GG_BTILE_B (16 * 136 * 2)                       // 4352 B
#define GG_STAGE_B (2 * GG_ATILE_B + 2 * GG_BTILE_B)    // 20992 B
#define GG_SMEM    (2 * GG_STAGE_B)                     // 41984 B

__global__ void __launch_bounds__(256) k_gemm_g_mma() {
    extern __shared__ char gg[];
    uint32_t sbase = smem_u32(gg);
    int t = threadIdx.x, lane = t & 31, wid = t >> 5;
    int wm = wid & 3, wn = wid >> 2;
    int j0 = blockIdx.x * 128;

    float acc[2][8][4];
#pragma unroll
    for (int i = 0; i < 2; i++)
#pragma unroll
        for (int j = 0; j < 8; j++)
#pragma unroll
            for (int q = 0; q < 4; q++) acc[i][j][q] = 0.f;

    int lrow = t >> 1, lhalf = t & 1;
    uint32_t sa_off = (uint32_t)(lrow * 24 + lhalf * 8) * 2;
    int frow = t >> 4, fc = (t & 15) * 8;
    uint32_t sb_off = (uint32_t)(frow * 136 + fc) * 2;

    uint32_t a_off[2];
#pragma unroll
    for (int mf = 0; mf < 2; mf++) {
        int rr = wm * 32 + mf * 16 + (lane & 15);
        a_off[mf] = (uint32_t)(rr * 24 + (lane >> 4) * 8) * 2;
    }
    int krB = (lane & 7) + (((lane >> 3) & 1) << 3);
    int ncB = wn * 64 + ((lane >> 4) << 3);

    auto load_chunk = [&](int ch, int st) {
        uint32_t base = sbase + st * GG_STAGE_B;
        const char* guh = (const char*)(d_Uhi + (size_t)(j0 + lrow) * 256 + 128 + ch * 16) + lhalf * 16;
        const char* gul = (const char*)(d_Ulo + (size_t)(j0 + lrow) * 256 + 128 + ch * 16) + lhalf * 16;
        const char* gah = (const char*)(d_Amhi + (ch * 16 + frow) * 128 + fc);
        const char* gal = (const char*)(d_Amlo + (ch * 16 + frow) * 128 + fc);
        CP_ASYNC16(base + sa_off,                 guh);
        CP_ASYNC16(base + GG_ATILE_B + sa_off,    gul);
        CP_ASYNC16(base + 2 * GG_ATILE_B + sb_off,                gah);
        CP_ASYNC16(base + 2 * GG_ATILE_B + GG_BTILE_B + sb_off,   gal);
    };

    load_chunk(0, 0);
    CP_COMMIT();

#pragma unroll 1
    for (int ch = 0; ch < 8; ch++) {
        if (ch + 1 < 8) {
            load_chunk(ch + 1, (ch + 1) & 1);
            CP_COMMIT();
            CP_WAIT(1);
        } else {
            CP_WAIT(0);
        }
        __syncthreads();

        uint32_t base = sbase + (ch & 1) * GG_STAGE_B;
        uint32_t ah[2][4], al[2][4];
#pragma unroll
        for (int mf = 0; mf < 2; mf++) {
            ldsm_x4(ah[mf], base + a_off[mf]);
            ldsm_x4(al[mf], base + GG_ATILE_B + a_off[mf]);
        }
#pragma unroll
        for (int np = 0; np < 4; np++) {
            uint32_t boff = (uint32_t)(krB * 136 + ncB + np * 16) * 2;
            uint32_t bh[4], bl[4];
            ldsm_x4_t(bh, base + 2 * GG_ATILE_B + boff);
            ldsm_x4_t(bl, base + 2 * GG_ATILE_B + GG_BTILE_B + boff);
#pragma unroll
            for (int mf = 0; mf < 2; mf++) {
#pragma unroll
                for (int sub = 0; sub < 2; sub++) {
                    float* d = acc[mf][np * 2 + sub];
                    mma16816(d, ah[mf], bh[sub * 2], bh[sub * 2 + 1]);
                    mma16816(d, ah[mf], bl[sub * 2], bl[sub * 2 + 1]);
                    mma16816(d, al[mf], bh[sub * 2], bh[sub * 2 + 1]);
                }
            }
        }
        __syncthreads();
    }

    // epilogue: split, write U cols [0,128)
    int g = lane >> 2, q = lane & 3;
#pragma unroll
    for (int mf = 0; mf < 2; mf++) {
#pragma unroll
        for (int n8 = 0; n8 < 8; n8++) {
            int c = wn * 64 + n8 * 8 + q * 2;
            float* d = acc[mf][n8];
            int r0 = j0 + wm * 32 + mf * 16 + g;
            uint32_t hi, lo;
            split2(d[0], d[1], hi, lo);
            *(uint32_t*)&d_Uhi[(size_t)r0 * 256 + c] = hi;
            *(uint32_t*)&d_Ulo[(size_t)r0 * 256 + c] = lo;
            split2(d[2], d[3], hi, lo);
            *(uint32_t*)&d_Uhi[(size_t)(r0 + 8) * 256 + c] = hi;
            *(uint32_t*)&d_Ulo[(size_t)(r0 + 8) * 256 + c] = lo;
        }
    }
}

// ---------------------------------------------------------------------------
// K3: scores via mma.sync (bf16 hi/lo). e = U·V^T, K=256, V = half-swapped U.
// One 128x128 tile pair (J<=K) per block, 2-stage cp.async.
// ---------------------------------------------------------------------------
#define SC_TILE_B  (128 * 24 * 2)                   // 6144 B per operand tile
#define SC_STAGE_B (4 * SC_TILE_B)                  // 24576 B per stage
#define SC_SMEM    (128 * 133 * 4)                  // 68096 B (stash > 2 stages)

__global__ void __launch_bounds__(256) k_scores_mma() {
    extern __shared__ char sc[];
    uint32_t sbase = smem_u32(sc);

    int t = threadIdx.x, lane = t & 31, wid = t >> 5;
    int wm = wid & 3, wn = wid >> 2;

    int b = blockIdx.y;
    int rem = blockIdx.x;
    int J = 0;
    while (rem >= 8 - J) { rem -= 8 - J; J++; }
    int K = J + rem;
    int j0 = J * 128, k0 = K * 128;

    const __nv_bfloat16* Uh = d_Uhi + (size_t)b * N_ * 256;
    const __nv_bfloat16* Ul = d_Ulo + (size_t)b * N_ * 256;

    float acc[2][8][4];
#pragma unroll
    for (int i = 0; i < 2; i++)
#pragma unroll
        for (int j = 0; j < 8; j++)
#pragma unroll
            for (int q = 0; q < 4; q++) acc[i][j][q] = 0.f;

    int lrow = t >> 1, lhalf = t & 1;
    uint32_t s_off = (uint32_t)(lrow * 24 + lhalf * 8) * 2;

    uint32_t a_off[2];
#pragma unroll
    for (int mf = 0; mf < 2; mf++) {
        int rr = wm * 32 + mf * 16 + (lane & 15);
        a_off[mf] = (uint32_t)(rr * 24 + (lane >> 4) * 8) * 2;
    }
    uint32_t b_off[4];
#pragma unroll
    for (int nb = 0; nb < 4; nb++) {
        int rr = wn * 64 + nb * 16 + ((lane >> 4) << 3) + (lane & 7);
        b_off[nb] = (uint32_t)(rr * 24 + ((lane >> 3) & 1) * 8) * 2;
    }

    auto load_chunk = [&](int ch, int st) {
        int ca = ch * 16;
        int cb = (ca + 128) & 255;
        uint32_t sb = sbase + st * SC_STAGE_B + s_off;
        const char* gAh = (const char*)(Uh + (size_t)(j0 + lrow) * 256 + ca) + lhalf * 16;
        const char* gAl = (const char*)(Ul + (size_t)(j0 + lrow) * 256 + ca) + lhalf * 16;
        const char* gBh = (const char*)(Uh + (size_t)(k0 + lrow) * 256 + cb) + lhalf * 16;
        const char* gBl = (const char*)(Ul + (size_t)(k0 + lrow) * 256 + cb) + lhalf * 16;
        CP_ASYNC16(sb,                 gAh);
        CP_ASYNC16(sb + SC_TILE_B,     gAl);
        CP_ASYNC16(sb + 2 * SC_TILE_B, gBh);
        CP_ASYNC16(sb + 3 * SC_TILE_B, gBl);
    };

    load_chunk(0, 0);
    CP_COMMIT();

#pragma unroll 1
    for (int ch = 0; ch < 16; ch++) {
        if (ch + 1 < 16) {
            load_chunk(ch + 1, (ch + 1) & 1);
            CP_COMMIT();
            CP_WAIT(1);
        } else {
            CP_WAIT(0);
        }
        __syncthreads();

        uint32_t stb = sbase + (ch & 1) * SC_STAGE_B;
        uint32_t ah[2][4], al[2][4];
#pragma unroll
        for (int mf = 0; mf < 2; mf++) {
            ldsm_x4(ah[mf], stb + a_off[mf]);
            ldsm_x4(al[mf], stb + SC_TILE_B + a_off[mf]);
        }
#pragma unroll
        for (int nb = 0; nb < 4; nb++) {
            uint32_t bh[4], bl[4];
            ldsm_x4(bh, stb + 2 * SC_TILE_B + b_off[nb]);
            ldsm_x4(bl, stb + 3 * SC_TILE_B + b_off[nb]);
#pragma unroll
            for (int mf = 0; mf < 2; mf++) {
#pragma unroll
                for (int sub = 0; sub < 2; sub++) {
                    float* d = acc[mf][nb * 2 + sub];
                    mma16816(d, ah[mf], bh[sub * 2], bh[sub * 2 + 1]);
                    mma16816(d, ah[mf], bl[sub * 2], bl[sub * 2 + 1]);
                    mma16816(d, al[mf], bh[sub * 2], bh[sub * 2 + 1]);
                }
            }
        }
        __syncthreads();
    }

    float* st = (float*)sc;
    int g = lane >> 2, tg = lane & 3;
#pragma unroll
    for (int mf = 0; mf < 2; mf++) {
        int rbase = wm * 32 + mf * 16;
#pragma unroll
        for (int n8 = 0; n8 < 8; n8++) {
            int cbase = wn * 64 + n8 * 8 + tg * 2;
            float* d = acc[mf][n8];
            st[(rbase + g) * 133 + cbase]         = d[0];
            st[(rbase + g) * 133 + cbase + 1]     = d[1];
            st[(rbase + g + 8) * 133 + cbase]     = d[2];
            st[(rbase + g + 8) * 133 + cbase + 1] = d[3];
        }
    }
    __syncthreads();

    float* Sb = d_S + (size_t)b * N_ * N_;
    {
        int row = t >> 1, chalf = (t & 1) * 64;
        const float* srow = st + row * 133 + chalf;
        float4* dst = (float4*)&Sb[(size_t)(j0 + row) * N_ + k0 + chalf];
#pragma unroll
        for (int q = 0; q < 16; q++) {
            float4 o;
            o.x = srow[q * 4 + 0]; o.y = srow[q * 4 + 1];
            o.z = srow[q * 4 + 2]; o.w = srow[q * 4 + 3];
            dst[q] = o;
        }
    }
    if (J != K) {
        int r = t & 127, c0 = t >> 7;
#pragma unroll 1
        for (int i = 0; i < 64; i++) {
            int c = c0 + i * 2;
            Sb[(size_t)(k0 + c) * N_ + j0 + r] = st[r * 133 + c];
        }
    }
}

// ---------------------------------------------------------------------------
// K4: transpose adj -> bf16 d_adjT (values 0/1, exact)
// ---------------------------------------------------------------------------
__global__ void k_adjT(const float* __restrict__ adj) {
    __shared__ float tile[32][33];
    int b = blockIdx.z;
    int x0 = blockIdx.x * 32, y0 = blockIdx.y * 32;
    const float* ab = adj + (size_t)b * N_ * N_;
    __nv_bfloat16* tb = d_adjT + (size_t)b * N_ * N_;
    int tx = threadIdx.x, ty = threadIdx.y;
#pragma unroll
    for (int i = 0; i < 32; i += 8)
        tile[ty + i][tx] = ab[(size_t)(y0 + ty + i) * N_ + x0 + tx];
    __syncthreads();
#pragma unroll
    for (int i = 0; i < 32; i += 8)
        tb[(size_t)(x0 + ty + i) * N_ + y0 + tx] = __float2bfloat16(tile[tx][ty + i]);
}

// ---------------------------------------------------------------------------
// K5: fused masked softmax; emits attn^T as bf16 hi/lo.
// ---------------------------------------------------------------------------
__global__ void __launch_bounds__(256) k_sm() {
    __shared__ float red_m[8], red_s[8];
    int b = blockIdx.y, r = blockIdx.x, t = threadIdx.x;
    const float* Mrow = d_S + ((size_t)b * N_ + r) * N_;
    const __nv_bfloat16* Arow = d_adjT + ((size_t)b * N_ + r) * N_;
    __nv_bfloat16* Oh = d_AThi + ((size_t)b * N_ + r) * N_;
    __nv_bfloat16* Ol = d_ATlo + ((size_t)b * N_ + r) * N_;

    float4 e4 = *(const float4*)&Mrow[t * 4];
    uint2 a2 = *(const uint2*)&Arow[t * 4];
    __nv_bfloat162 a01 = *(__nv_bfloat162*)&a2.x;
    __nv_bfloat162 a23 = *(__nv_bfloat162*)&a2.y;
    float ax = __bfloat162float(a01.x), ay = __bfloat162float(a01.y);
    float az = __bfloat162float(a23.x), aw = __bfloat162float(a23.y);

    float v0 = (ax > 0.f) ? e4.x : 0.f;
    float v1 = (ay > 0.f) ? e4.y : 0.f;
    float v2 = (az > 0.f) ? e4.z : 0.f;
    float v3 = (aw > 0.f) ? e4.w : 0.f;

    float lm = fmaxf(fmaxf(v0, v1), fmaxf(v2, v3));
#pragma unroll
    for (int o = 16; o > 0; o >>= 1)
        lm = fmaxf(lm, __shfl_xor_sync(0xffffffffu, lm, o));
    if ((t & 31) == 0) red_m[t >> 5] = lm;
    __syncthreads();
    float m = red_m[0];
#pragma unroll
    for (int i = 1; i < 8; i++) m = fmaxf(m, red_m[i]);

    float p0 = fexp(v0 - m), p1 = fexp(v1 - m);
    float p2 = fexp(v2 - m), p3 = fexp(v3 - m);
    float ls = (p0 + p1) + (p2 + p3);
#pragma unroll
    for (int o = 16; o > 0; o >>= 1)
        ls += __shfl_xor_sync(0xffffffffu, ls, o);
    if ((t & 31) == 0) red_s[t >> 5] = ls;
    __syncthreads();
    float Z = red_s[0];
#pragma unroll
    for (int i = 1; i < 8; i++) Z += red_s[i];
    float inv = 1.0f / Z;

    float r0 = p0 * inv * ax, r1 = p1 * inv * ay;
    float r2 = p2 * inv * az, r3 = p3 * inv * aw;
    uint32_t h01, l01, h23, l23;
    split2(r0, r1, h01, l01);
    split2(r2, r3, h23, l23);
    uint2 ho; ho.x = h01; ho.y = h23;
    uint2 lo; lo.x = l01; lo.y = l23;
    *(uint2*)&Oh[t * 4] = ho;
    *(uint2*)&Ol[t * 4] = lo;
}

// ---------------------------------------------------------------------------
// K6: h' = relu(att @ h) via mma.sync (trans-ldmatrix operands), gates fused.
// 2-stage cp.async. Dynamic smem 69632 B.
// ---------------------------------------------------------------------------
#define KO_TILE_B  (32 * 136 * 2)                   // 8704 B
#define KO_STAGE_B (4 * KO_TILE_B)                  // 34816 B
#define KO_SMEM    (2 * KO_STAGE_B)                 // 69632 B

__global__ void __launch_bounds__(256) k_out_mma(const float* __restrict__ x,
                                                 const float* __restrict__ wiu,
                                                 const float* __restrict__ wfu,
                                                 const float* __restrict__ wou,
                                                 float* __restrict__ out) {
    extern __shared__ char ko[];
    __shared__ float red[3][128];
    __shared__ float wu[3][128];

    int b = blockIdx.y, i0 = blockIdx.x * 128;
    int t = threadIdx.x, lane = t & 31, wid = t >> 5;
    int wm = wid & 3, wn = wid >> 2;
    if (t < 128) {
        wu[0][t] = wiu[t]; wu[1][t] = wfu[t]; wu[2][t] = wou[t];
        red[0][t] = 0.f; red[1][t] = 0.f; red[2][t] = 0.f;
    }

    const __nv_bfloat16* ATh = d_AThi + (size_t)b * N_ * N_;
    const __nv_bfloat16* ATl = d_ATlo + (size_t)b * N_ * N_;
    const __nv_bfloat16* Hh  = d_Uhi + (size_t)b * N_ * 256 + 128;
    const __nv_bfloat16* Hl  = d_Ulo + (size_t)b * N_ * 256 + 128;

    uint32_t sb0 = smem_u32(ko);

    float acc[2][8][4];
#pragma unroll
    for (int i = 0; i < 2; i++)
#pragma unroll
        for (int j = 0; j < 8; j++)
#pragma unroll
            for (int q = 0; q < 4; q++) acc[i][j][q] = 0.f;

    int krA = (lane & 7) + ((lane >> 4) << 3);
    int mcA = wm * 32 + ((lane >> 3) & 1) * 8;
    int krB = (lane & 7) + (((lane >> 3) & 1) << 3);
    int ncB = wn * 64 + ((lane >> 4) << 3);

    int frow0 = t >> 4, fc0 = (t & 15) * 8;
    int frow1 = (t + 256) >> 4;

    auto load_chunk = [&](int kc, int st) {
        uint32_t base = sb0 + st * KO_STAGE_B;
        uint32_t so0 = (uint32_t)(frow0 * 136 + fc0) * 2;
        uint32_t so1 = (uint32_t)(frow1 * 136 + fc0) * 2;
        const char* ga0 = (const char*)(ATh + (size_t)(kc + frow0) * N_ + i0 + fc0);
        const char* ga1 = (const char*)(ATh + (size_t)(kc + frow1) * N_ + i0 + fc0);
        const char* gal0 = (const char*)(ATl + (size_t)(kc + frow0) * N_ + i0 + fc0);
        const char* gal1 = (const char*)(ATl + (size_t)(kc + frow1) * N_ + i0 + fc0);
        const char* gb0 = (const char*)(Hh + (size_t)(kc + frow0) * 256 + fc0);
        const char* gb1 = (const char*)(Hh + (size_t)(kc + frow1) * 256 + fc0);
        const char* gbl0 = (const char*)(Hl + (size_t)(kc + frow0) * 256 + fc0);
        const char* gbl1 = (const char*)(Hl + (size_t)(kc + frow1) * 256 + fc0);
        CP_ASYNC16(base + so0,                  ga0);
        CP_ASYNC16(base + so1,                  ga1);
        CP_ASYNC16(base + KO_TILE_B + so0,      gal0);
        CP_ASYNC16(base + KO_TILE_B + so1,      gal1);
        CP_ASYNC16(base + 2 * KO_TILE_B + so0,  gb0);
        CP_ASYNC16(base + 2 * KO_TILE_B + so1,  gb1);
        CP_ASYNC16(base + 3 * KO_TILE_B + so0,  gbl0);
        CP_ASYNC16(base + 3 * KO_TILE_B + so1,  gbl1);
    };

    load_chunk(0, 0);
    CP_COMMIT();

#pragma unroll 1
    for (int it = 0; it < 32; it++) {
        if (it + 1 < 32) {
            load_chunk((it + 1) * 32, (it + 1) & 1);
            CP_COMMIT();
            CP_WAIT(1);
        } else {
            CP_WAIT(0);
        }
        __syncthreads();

        uint32_t base = sb0 + (it & 1) * KO_STAGE_B;
#pragma unroll
        for (int s = 0; s < 2; s++) {
            uint32_t ah[2][4], al[2][4];
#pragma unroll
            for (int mf = 0; mf < 2; mf++) {
                uint32_t off = (uint32_t)((s * 16 + krA) * 136 + mcA + mf * 16) * 2;
                ldsm_x4_t(ah[mf], base + off);
                ldsm_x4_t(al[mf], base + KO_TILE_B + off);
            }
#pragma unroll
            for (int np = 0; np < 4; np++) {
                uint32_t boff = (uint32_t)((s * 16 + krB) * 136 + ncB + np * 16) * 2;
                uint32_t bh[4], bl[4];
                ldsm_x4_t(bh, base + 2 * KO_TILE_B + boff);
                ldsm_x4_t(bl, base + 3 * KO_TILE_B + boff);
#pragma unroll
                for (int mf = 0; mf < 2; mf++) {
#pragma unroll
                    for (int sub = 0; sub < 2; sub++) {
                        float* d = acc[mf][np * 2 + sub];
                        mma16816(d, ah[mf], bh[sub * 2], bh[sub * 2 + 1]);
                        mma16816(d, ah[mf], bl[sub * 2], bl[sub * 2 + 1]);
                        mma16816(d, al[mf], bh[sub * 2], bh[sub * 2 + 1]);
                    }
                }
            }
        }
        __syncthreads();
    }

    int g = lane >> 2, q = lane & 3;
    float pp[2][2][3];
#pragma unroll
    for (int mf = 0; mf < 2; mf++)
#pragma unroll
        for (int rh = 0; rh < 2; rh++)
#pragma unroll
            for (int gg = 0; gg < 3; gg++) pp[mf][rh][gg] = 0.f;

#pragma unroll
    for (int mf = 0; mf < 2; mf++) {
#pragma unroll
        for (int n8 = 0; n8 < 8; n8++) {
            int c = wn * 64 + n8 * 8 + q * 2;
            float wa0 = wu[0][c], wb0 = wu[0][c + 1];
            float wa1 = wu[1][c], wb1 = wu[1][c + 1];
            float wa2 = wu[2][c], wb2 = wu[2][c + 1];
            float* d = acc[mf][n8];
            float v0 = fmaxf(d[0], 0.f), v1 = fmaxf(d[1], 0.f);
            float v2 = fmaxf(d[2], 0.f), v3 = fmaxf(d[3], 0.f);
            d[0] = v0; d[1] = v1; d[2] = v2; d[3] = v3;
            pp[mf][0][0] += v0 * wa0 + v1 * wb0;
            pp[mf][0][1] += v0 * wa1 + v1 * wb1;
            pp[mf][0][2] += v0 * wa2 + v1 * wb2;
            pp[mf][1][0] += v2 * wa0 + v3 * wb0;
            pp[mf][1][1] += v2 * wa1 + v3 * wb1;
            pp[mf][1][2] += v2 * wa2 + v3 * wb2;
        }
    }
#pragma unroll
    for (int mf = 0; mf < 2; mf++)
#pragma unroll
        for (int rh = 0; rh < 2; rh++) {
            float s0 = pp[mf][rh][0], s1 = pp[mf][rh][1], s2 = pp[mf][rh][2];
            s0 += __shfl_xor_sync(0xffffffffu, s0, 1);
            s0 += __shfl_xor_sync(0xffffffffu, s0, 2);
            s1 += __shfl_xor_sync(0xffffffffu, s1, 1);
            s1 += __shfl_xor_sync(0xffffffffu, s1, 2);
            s2 += __shfl_xor_sync(0xffffffffu, s2, 1);
            s2 += __shfl_xor_sync(0xffffffffu, s2, 2);
            if (q == 0) {
                int r = wm * 32 + mf * 16 + rh * 8 + g;
                atomicAdd(&red[0][r], s0);
                atomicAdd(&red[1][r], s1);
                atomicAdd(&red[2][r], s2);
            }
        }
    __syncthreads();

    int nb = b * N_ + i0;
#pragma unroll
    for (int mf = 0; mf < 2; mf++) {
#pragma unroll
        for (int rh = 0; rh < 2; rh++) {
            int r = wm * 32 + mf * 16 + rh * 8 + g;
            float zi = red[0][r] + d_xd[nb + r];
            float zf = red[1][r] + d_xd[B_ * N_ + nb + r];
            float zo = red[2][r] + d_xd[2 * B_ * N_ + nb + r];
            float ic = 1.f / (1.f + fexp(-zi));
            float fc = 1.f / (1.f + fexp(-zf));
            float oc = 1.f / (1.f + fexp(-zo));
            const float* xr = x + (size_t)(nb + r) * 128;
            float* orow = out + (size_t)(nb + r) * 128;
#pragma unroll
            for (int n8 = 0; n8 < 8; n8++) {
                int c = wn * 64 + n8 * 8 + q * 2;
                float2 xv = *(const float2*)&xr[c];
                float v0 = acc[mf][n8][rh * 2 + 0];
                float v1 = acc[mf][n8][rh * 2 + 1];
                float2 o;
                o.x = oc * tanhf(ic * v0 + fc * xv.x);
                o.y = oc * tanhf(ic * v1 + fc * xv.y);
                *(float2*)&orow[c] = o;
            }
        }
    }
}

// ---------------------------------------------------------------------------
extern "C" void kernel_launch(void* const* d_in, const int* in_sizes, int n_in,
                              void* d_out, int out_size) {
    const float* x   = (const float*)d_in[0];
    const float* adj = (const float*)d_in[1];
    const float* Ww  = (const float*)d_in[2];
    const float* Wb  = (const float*)d_in[3];
    const float* A   = (const float*)d_in[4];
    const float* wiu = (const float*)d_in[5];
    const float* wix = (const float*)d_in[6];
    const float* wfu = (const float*)d_in[7];
    const float* wfx = (const float*)d_in[8];
    const float* wou = (const float*)d_in[9];
    const float* wox = (const float*)d_in[10];
    float* out = (float*)d_out;

    static int attr_set = 0;
    if (!attr_set) {
        cudaFuncSetAttribute(k_scores_mma, cudaFuncAttributeMaxDynamicSharedMemorySize, SC_SMEM);
        cudaFuncSetAttribute(k_out_mma, cudaFuncAttributeMaxDynamicSharedMemorySize, KO_SMEM);
        cudaFuncSetAttribute(k_gemm_h_mma, cudaFuncAttributeMaxDynamicSharedMemorySize, GH_SMEM);
        cudaFuncSetAttribute(k_gemm_g_mma, cudaFuncAttributeMaxDynamicSharedMemorySize, GG_SMEM);
        attr_set = 1;
    }

    {
        dim3 g(N_ / 32, N_ / 32, B_);
        k_adjT<<<g, dim3(32, 8)>>>(adj);
    }
    k_xdots<<<B_ * N_ / 8, 256>>>(x, wix, wfx, wox);
    k_split_x<<<B_ * N_ * D_ / 1024, 256>>>(x);
    k_split_w<<<D_ * D_ / 256, 256>>>(Ww, A);
    k_gemm_h_mma<<<B_ * N_ / 128, 256, GH_SMEM>>>(Wb);
    k_gemm_g_mma<<<B_ * N_ / 128, 256, GG_SMEM>>>();
    {
        dim3 g(36, B_);
        k_scores_mma<<<g, 256, SC_SMEM>>>();
    }
    {
        dim3 g(N_, B_);
        k_sm<<<g, 256>>>();
    }
    {
        dim3 g(N_ / 128, B_);
        k_out_mma<<<g, 256, KO_SMEM>>>(x, wiu, wfu, wou, out);
    }
}

// round 11
// speedup vs baseline: 3.9027x; 1.0294x over previous
#include <cuda_runtime.h>
#include <cuda_bf16.h>
#include <math.h>
#include <stdint.h>

#define B_ 16
#define N_ 1024
#define D_ 128

// Scratch (device globals — allocation-free per harness rules)
static __device__ float d_S[B_ * N_ * N_];              // 64 MB: e scores (fp32)
static __device__ uint32_t d_adjM[B_ * N_ * (N_ / 32)]; // 2 MB: transposed adj bitmask
static __device__ float d_xd[3 * B_ * N_];              // x·w*_x per node
static __device__ __nv_bfloat16 d_Uhi[B_ * N_ * 256];   // 8 MB: [g|h] hi part
static __device__ __nv_bfloat16 d_Ulo[B_ * N_ * 256];   // 8 MB: [g|h] lo part
static __device__ __nv_bfloat16 d_AThi[B_ * N_ * N_];   // 32 MB: attn^T hi  [j][i]
static __device__ __nv_bfloat16 d_ATlo[B_ * N_ * N_];   // 32 MB: attn^T lo
static __device__ __nv_bfloat16 d_Xhi[B_ * N_ * D_];    // 4 MB: x hi
static __device__ __nv_bfloat16 d_Xlo[B_ * N_ * D_];    // 4 MB: x lo
static __device__ __nv_bfloat16 d_Whi[D_ * D_];         // Ww [n][k] hi
static __device__ __nv_bfloat16 d_Wlo[D_ * D_];
static __device__ __nv_bfloat16 d_Amhi[D_ * D_];        // A [k][n] hi
static __device__ __nv_bfloat16 d_Amlo[D_ * D_];

// ---------------------------------------------------------------------------
__device__ __forceinline__ uint32_t smem_u32(const void* p) {
    uint32_t a;
    asm("{ .reg .u64 t; cvta.to.shared.u64 t, %1; cvt.u32.u64 %0, t; }" : "=r"(a) : "l"(p));
    return a;
}
__device__ __forceinline__ void ldsm_x4(uint32_t* r, uint32_t addr) {
    asm volatile("ldmatrix.sync.aligned.m8n8.x4.shared.b16 {%0,%1,%2,%3}, [%4];"
                 : "=r"(r[0]), "=r"(r[1]), "=r"(r[2]), "=r"(r[3]) : "r"(addr));
}
__device__ __forceinline__ void ldsm_x4_t(uint32_t* r, uint32_t addr) {
    asm volatile("ldmatrix.sync.aligned.m8n8.x4.trans.shared.b16 {%0,%1,%2,%3}, [%4];"
                 : "=r"(r[0]), "=r"(r[1]), "=r"(r[2]), "=r"(r[3]) : "r"(addr));
}
__device__ __forceinline__ void mma16816(float* d, const uint32_t* a,
                                         uint32_t b0, uint32_t b1) {
    asm volatile(
        "mma.sync.aligned.m16n8k16.row.col.f32.bf16.bf16.f32 "
        "{%0,%1,%2,%3}, {%4,%5,%6,%7}, {%8,%9}, {%0,%1,%2,%3};"
        : "+f"(d[0]), "+f"(d[1]), "+f"(d[2]), "+f"(d[3])
        : "r"(a[0]), "r"(a[1]), "r"(a[2]), "r"(a[3]), "r"(b0), "r"(b1));
}
#define CP_ASYNC16(sa, gp) \
    asm volatile("cp.async.cg.shared.global [%0], [%1], 16;" :: "r"(sa), "l"(gp))
#define CP_COMMIT() asm volatile("cp.async.commit_group;" ::: "memory")
#define CP_WAIT(n)  asm volatile("cp.async.wait_group %0;" :: "n"(n) : "memory")

// fp32 -> bf16 hi/lo split (packed pairs)
__device__ __forceinline__ void split2(float v0, float v1, uint32_t& hi, uint32_t& lo) {
    __nv_bfloat16 h0 = __float2bfloat16(v0), h1 = __float2bfloat16(v1);
    __nv_bfloat16 l0 = __float2bfloat16(v0 - __bfloat162float(h0));
    __nv_bfloat16 l1 = __float2bfloat16(v1 - __bfloat162float(h1));
    __nv_bfloat162 H = __halves2bfloat162(h0, h1);
    __nv_bfloat162 L = __halves2bfloat162(l0, l1);
    hi = *(uint32_t*)&H; lo = *(uint32_t*)&L;
}

// FMA-only exp
__device__ __forceinline__ float fexp(float x) {
    x = fmaxf(x, -87.0f);
    float y = x * 1.44269504089f;
    float n = rintf(y);
    float t = (y - n) * 0.69314718056f;
    float p = 1.38888889e-3f;
    p = fmaf(p, t, 8.33333333e-3f);
    p = fmaf(p, t, 4.16666667e-2f);
    p = fmaf(p, t, 1.66666667e-1f);
    p = fmaf(p, t, 0.5f);
    p = fmaf(p, t, 1.0f);
    p = fmaf(p, t, 1.0f);
    return p * __int_as_float(((int)n + 127) << 23);
}

// ---------------------------------------------------------------------------
// K0: fused prep — per-node gate dots + x hi/lo split; blocks 0..63 also
// split Ww and A.
// ---------------------------------------------------------------------------
__global__ void k_prep(const float* __restrict__ x,
                       const float* __restrict__ wix,
                       const float* __restrict__ wfx,
                       const float* __restrict__ wox,
                       const float* __restrict__ Ww,
                       const float* __restrict__ A) {
    int t = threadIdx.x;
    int row  = blockIdx.x * 8 + (t >> 5);
    int lane = t & 31;
    float4 xv = *(const float4*)(x + (size_t)row * D_ + lane * 4);
    float4 wi = *(const float4*)(wix + lane * 4);
    float4 wf = *(const float4*)(wfx + lane * 4);
    float4 wo = *(const float4*)(wox + lane * 4);
    float s0 = xv.x * wi.x + xv.y * wi.y + xv.z * wi.z + xv.w * wi.w;
    float s1 = xv.x * wf.x + xv.y * wf.y + xv.z * wf.z + xv.w * wf.w;
    float s2 = xv.x * wo.x + xv.y * wo.y + xv.z * wo.z + xv.w * wo.w;
#pragma unroll
    for (int o = 16; o > 0; o >>= 1) {
        s0 += __shfl_xor_sync(0xffffffffu, s0, o);
        s1 += __shfl_xor_sync(0xffffffffu, s1, o);
        s2 += __shfl_xor_sync(0xffffffffu, s2, o);
    }
    if (lane == 0) {
        d_xd[row]               = s0;
        d_xd[B_ * N_ + row]     = s1;
        d_xd[2 * B_ * N_ + row] = s2;
    }
    // x split (x row already in registers)
    {
        uint32_t h01, l01, h23, l23;
        split2(xv.x, xv.y, h01, l01);
        split2(xv.z, xv.w, h23, l23);
        uint2 h; h.x = h01; h.y = h23;
        uint2 l; l.x = l01; l.y = l23;
        size_t off = (size_t)row * D_ + lane * 4;
        *(uint2*)&d_Xhi[off] = h;
        *(uint2*)&d_Xlo[off] = l;
    }
    // W / A splits (first 64 blocks cover 16384 elements)
    if (blockIdx.x < 64) {
        int i = blockIdx.x * 256 + t;
        float wv = Ww[i];
        __nv_bfloat16 wh = __float2bfloat16(wv);
        d_Whi[i] = wh;
        d_Wlo[i] = __float2bfloat16(wv - __bfloat162float(wh));
        float av = A[i];
        __nv_bfloat16 ah = __float2bfloat16(av);
        d_Amhi[i] = ah;
        d_Amlo[i] = __float2bfloat16(av - __bfloat162float(ah));
    }
}

// ---------------------------------------------------------------------------
// K1: h = x·Ww^T + Wb via mma.sync. Writes U cols [128,256) hi/lo.
// ---------------------------------------------------------------------------
#define GH_TILE_B  (128 * 24 * 2)      // 6144 B
#define GH_STAGE_B (4 * GH_TILE_B)     // 24576 B
#define GH_SMEM    (2 * GH_STAGE_B)    // 49152 B

__global__ void __launch_bounds__(256) k_gemm_h_mma(const float* __restrict__ Wb) {
    extern __shared__ char gh[];
    __shared__ float wb[128];
    uint32_t sbase = smem_u32(gh);
    int t = threadIdx.x, lane = t & 31, wid = t >> 5;
    int wm = wid & 3, wn = wid >> 2;
    if (t < 128) wb[t] = Wb[t];
    int j0 = blockIdx.x * 128;

    float acc[2][8][4];
#pragma unroll
    for (int i = 0; i < 2; i++)
#pragma unroll
        for (int j = 0; j < 8; j++)
#pragma unroll
            for (int q = 0; q < 4; q++) acc[i][j][q] = 0.f;

    int lrow = t >> 1, lhalf = t & 1;
    uint32_t s_off = (uint32_t)(lrow * 24 + lhalf * 8) * 2;

    uint32_t a_off[2];
#pragma unroll
    for (int mf = 0; mf < 2; mf++) {
        int rr = wm * 32 + mf * 16 + (lane & 15);
        a_off[mf] = (uint32_t)(rr * 24 + (lane >> 4) * 8) * 2;
    }
    uint32_t b_off[4];
#pragma unroll
    for (int nb = 0; nb < 4; nb++) {
        int rr = wn * 64 + nb * 16 + ((lane >> 4) << 3) + (lane & 7);
        b_off[nb] = (uint32_t)(rr * 24 + ((lane >> 3) & 1) * 8) * 2;
    }

    auto load_chunk = [&](int ch, int st) {
        uint32_t sb = sbase + st * GH_STAGE_B + s_off;
        const char* gxh = (const char*)(d_Xhi + (size_t)(j0 + lrow) * 128 + ch * 16) + lhalf * 16;
        const char* gxl = (const char*)(d_Xlo + (size_t)(j0 + lrow) * 128 + ch * 16) + lhalf * 16;
        const char* gwh = (const char*)(d_Whi + lrow * 128 + ch * 16) + lhalf * 16;
        const char* gwl = (const char*)(d_Wlo + lrow * 128 + ch * 16) + lhalf * 16;
        CP_ASYNC16(sb,                 gxh);
        CP_ASYNC16(sb + GH_TILE_B,     gxl);
        CP_ASYNC16(sb + 2 * GH_TILE_B, gwh);
        CP_ASYNC16(sb + 3 * GH_TILE_B, gwl);
    };

    load_chunk(0, 0);
    CP_COMMIT();

#pragma unroll 1
    for (int ch = 0; ch < 8; ch++) {
        if (ch + 1 < 8) {
            load_chunk(ch + 1, (ch + 1) & 1);
            CP_COMMIT();
            CP_WAIT(1);
        } else {
            CP_WAIT(0);
        }
        __syncthreads();

        uint32_t stb = sbase + (ch & 1) * GH_STAGE_B;
        uint32_t ah[2][4], al[2][4];
#pragma unroll
        for (int mf = 0; mf < 2; mf++) {
            ldsm_x4(ah[mf], stb + a_off[mf]);
            ldsm_x4(al[mf], stb + GH_TILE_B + a_off[mf]);
        }
#pragma unroll
        for (int nb = 0; nb < 4; nb++) {
            uint32_t bh[4], bl[4];
            ldsm_x4(bh, stb + 2 * GH_TILE_B + b_off[nb]);
            ldsm_x4(bl, stb + 3 * GH_TILE_B + b_off[nb]);
#pragma unroll
            for (int mf = 0; mf < 2; mf++) {
#pragma unroll
                for (int sub = 0; sub < 2; sub++) {
                    float* d = acc[mf][nb * 2 + sub];
                    mma16816(d, ah[mf], bh[sub * 2], bh[sub * 2 + 1]);
                    mma16816(d, ah[mf], bl[sub * 2], bl[sub * 2 + 1]);
                    mma16816(d, al[mf], bh[sub * 2], bh[sub * 2 + 1]);
                }
            }
        }
        __syncthreads();
    }

    int g = lane >> 2, q = lane & 3;
#pragma unroll
    for (int mf = 0; mf < 2; mf++) {
#pragma unroll
        for (int n8 = 0; n8 < 8; n8++) {
            int c = wn * 64 + n8 * 8 + q * 2;
            float* d = acc[mf][n8];
            int r0 = j0 + wm * 32 + mf * 16 + g;
            float b0 = wb[c], b1 = wb[c + 1];
            uint32_t hi, lo;
            split2(d[0] + b0, d[1] + b1, hi, lo);
            *(uint32_t*)&d_Uhi[(size_t)r0 * 256 + 128 + c] = hi;
            *(uint32_t*)&d_Ulo[(size_t)r0 * 256 + 128 + c] = lo;
            split2(d[2] + b0, d[3] + b1, hi, lo);
            *(uint32_t*)&d_Uhi[(size_t)(r0 + 8) * 256 + 128 + c] = hi;
            *(uint32_t*)&d_Ulo[(size_t)(r0 + 8) * 256 + 128 + c] = lo;
        }
    }
}

// ---------------------------------------------------------------------------
// K2: g = h·A via mma.sync. Writes U cols [0,128).
// ---------------------------------------------------------------------------
#define GG_ATILE_B (128 * 24 * 2)                       // 6144 B
#define GG_BTILE_B (16 * 136 * 2)                       // 4352 B
#define GG_STAGE_B (2 * GG_ATILE_B + 2 * GG_BTILE_B)    // 20992 B
#define GG_SMEM    (2 * GG_STAGE_B)                     // 41984 B

__global__ void __launch_bounds__(256) k_gemm_g_mma() {
    extern __shared__ char gg[];
    uint32_t sbase = smem_u32(gg);
    int t = threadIdx.x, lane = t & 31, wid = t >> 5;
    int wm = wid & 3, wn = wid >> 2;
    int j0 = blockIdx.x * 128;

    float acc[2][8][4];
#pragma unroll
    for (int i = 0; i < 2; i++)
#pragma unroll
        for (int j = 0; j < 8; j++)
#pragma unroll
            for (int q = 0; q < 4; q++) acc[i][j][q] = 0.f;

    int lrow = t >> 1, lhalf = t & 1;
    uint32_t sa_off = (uint32_t)(lrow * 24 + lhalf * 8) * 2;
    int frow = t >> 4, fc = (t & 15) * 8;
    uint32_t sb_off = (uint32_t)(frow * 136 + fc) * 2;

    uint32_t a_off[2];
#pragma unroll
    for (int mf = 0; mf < 2; mf++) {
        int rr = wm * 32 + mf * 16 + (lane & 15);
        a_off[mf] = (uint32_t)(rr * 24 + (lane >> 4) * 8) * 2;
    }
    int krB = (lane & 7) + (((lane >> 3) & 1) << 3);
    int ncB = wn * 64 + ((lane >> 4) << 3);

    auto load_chunk = [&](int ch, int st) {
        uint32_t base = sbase + st * GG_STAGE_B;
        const char* guh = (const char*)(d_Uhi + (size_t)(j0 + lrow) * 256 + 128 + ch * 16) + lhalf * 16;
        const char* gul = (const char*)(d_Ulo + (size_t)(j0 + lrow) * 256 + 128 + ch * 16) + lhalf * 16;
        const char* gah = (const char*)(d_Amhi + (ch * 16 + frow) * 128 + fc);
        const char* gal = (const char*)(d_Amlo + (ch * 16 + frow) * 128 + fc);
        CP_ASYNC16(base + sa_off,                 guh);
        CP_ASYNC16(base + GG_ATILE_B + sa_off,    gul);
        CP_ASYNC16(base + 2 * GG_ATILE_B + sb_off,                gah);
        CP_ASYNC16(base + 2 * GG_ATILE_B + GG_BTILE_B + sb_off,   gal);
    };

    load_chunk(0, 0);
    CP_COMMIT();

#pragma unroll 1
    for (int ch = 0; ch < 8; ch++) {
        if (ch + 1 < 8) {
            load_chunk(ch + 1, (ch + 1) & 1);
            CP_COMMIT();
            CP_WAIT(1);
        } else {
            CP_WAIT(0);
        }
        __syncthreads();

        uint32_t base = sbase + (ch & 1) * GG_STAGE_B;
        uint32_t ah[2][4], al[2][4];
#pragma unroll
        for (int mf = 0; mf < 2; mf++) {
            ldsm_x4(ah[mf], base + a_off[mf]);
            ldsm_x4(al[mf], base + GG_ATILE_B + a_off[mf]);
        }
#pragma unroll
        for (int np = 0; np < 4; np++) {
            uint32_t boff = (uint32_t)(krB * 136 + ncB + np * 16) * 2;
            uint32_t bh[4], bl[4];
            ldsm_x4_t(bh, base + 2 * GG_ATILE_B + boff);
            ldsm_x4_t(bl, base + 2 * GG_ATILE_B + GG_BTILE_B + boff);
#pragma unroll
            for (int mf = 0; mf < 2; mf++) {
#pragma unroll
                for (int sub = 0; sub < 2; sub++) {
                    float* d = acc[mf][np * 2 + sub];
                    mma16816(d, ah[mf], bh[sub * 2], bh[sub * 2 + 1]);
                    mma16816(d, ah[mf], bl[sub * 2], bl[sub * 2 + 1]);
                    mma16816(d, al[mf], bh[sub * 2], bh[sub * 2 + 1]);
                }
            }
        }
        __syncthreads();
    }

    int g = lane >> 2, q = lane & 3;
#pragma unroll
    for (int mf = 0; mf < 2; mf++) {
#pragma unroll
        for (int n8 = 0; n8 < 8; n8++) {
            int c = wn * 64 + n8 * 8 + q * 2;
            float* d = acc[mf][n8];
            int r0 = j0 + wm * 32 + mf * 16 + g;
            uint32_t hi, lo;
            split2(d[0], d[1], hi, lo);
            *(uint32_t*)&d_Uhi[(size_t)r0 * 256 + c] = hi;
            *(uint32_t*)&d_Ulo[(size_t)r0 * 256 + c] = lo;
            split2(d[2], d[3], hi, lo);
            *(uint32_t*)&d_Uhi[(size_t)(r0 + 8) * 256 + c] = hi;
            *(uint32_t*)&d_Ulo[(size_t)(r0 + 8) * 256 + c] = lo;
        }
    }
}

// ---------------------------------------------------------------------------
// K3: scores via mma.sync. e = U·V^T, K=256, V = half-swapped U.
// 3-stage cp.async pipeline.
// ---------------------------------------------------------------------------
#define SC_TILE_B  (128 * 24 * 2)                   // 6144 B per operand tile
#define SC_STAGE_B (4 * SC_TILE_B)                  // 24576 B per stage
#define SC_SMEM    (3 * SC_STAGE_B)                 // 73728 B (stash 68096 fits)

__global__ void __launch_bounds__(256) k_scores_mma() {
    extern __shared__ char sc[];
    uint32_t sbase = smem_u32(sc);

    int t = threadIdx.x, lane = t & 31, wid = t >> 5;
    int wm = wid & 3, wn = wid >> 2;

    int b = blockIdx.y;
    int rem = blockIdx.x;
    int J = 0;
    while (rem >= 8 - J) { rem -= 8 - J; J++; }
    int K = J + rem;
    int j0 = J * 128, k0 = K * 128;

    const __nv_bfloat16* Uh = d_Uhi + (size_t)b * N_ * 256;
    const __nv_bfloat16* Ul = d_Ulo + (size_t)b * N_ * 256;

    float acc[2][8][4];
#pragma unroll
    for (int i = 0; i < 2; i++)
#pragma unroll
        for (int j = 0; j < 8; j++)
#pragma unroll
            for (int q = 0; q < 4; q++) acc[i][j][q] = 0.f;

    int lrow = t >> 1, lhalf = t & 1;
    uint32_t s_off = (uint32_t)(lrow * 24 + lhalf * 8) * 2;

    uint32_t a_off[2];
#pragma unroll
    for (int mf = 0; mf < 2; mf++) {
        int rr = wm * 32 + mf * 16 + (lane & 15);
        a_off[mf] = (uint32_t)(rr * 24 + (lane >> 4) * 8) * 2;
    }
    uint32_t b_off[4];
#pragma unroll
    for (int nb = 0; nb < 4; nb++) {
        int rr = wn * 64 + nb * 16 + ((lane >> 4) << 3) + (lane & 7);
        b_off[nb] = (uint32_t)(rr * 24 + ((lane >> 3) & 1) * 8) * 2;
    }

    auto load_chunk = [&](int ch, int st) {
        int ca = ch * 16;
        int cb = (ca + 128) & 255;
        uint32_t sb = sbase + st * SC_STAGE_B + s_off;
        const char* gAh = (const char*)(Uh + (size_t)(j0 + lrow) * 256 + ca) + lhalf * 16;
        const char* gAl = (const char*)(Ul + (size_t)(j0 + lrow) * 256 + ca) + lhalf * 16;
        const char* gBh = (const char*)(Uh + (size_t)(k0 + lrow) * 256 + cb) + lhalf * 16;
        const char* gBl = (const char*)(Ul + (size_t)(k0 + lrow) * 256 + cb) + lhalf * 16;
        CP_ASYNC16(sb,                 gAh);
        CP_ASYNC16(sb + SC_TILE_B,     gAl);
        CP_ASYNC16(sb + 2 * SC_TILE_B, gBh);
        CP_ASYNC16(sb + 3 * SC_TILE_B, gBl);
    };

    load_chunk(0, 0); CP_COMMIT();
    load_chunk(1, 1); CP_COMMIT();

#pragma unroll 1
    for (int ch = 0; ch < 16; ch++) {
        if (ch + 2 < 16) {
            load_chunk(ch + 2, (ch + 2) % 3);
            CP_COMMIT();
            CP_WAIT(2);
        } else if (ch + 1 < 16) {
            CP_WAIT(1);
        } else {
            CP_WAIT(0);
        }
        __syncthreads();

        uint32_t stb = sbase + (ch % 3) * SC_STAGE_B;
        uint32_t ah[2][4], al[2][4];
#pragma unroll
        for (int mf = 0; mf < 2; mf++) {
            ldsm_x4(ah[mf], stb + a_off[mf]);
            ldsm_x4(al[mf], stb + SC_TILE_B + a_off[mf]);
        }
#pragma unroll
        for (int nb = 0; nb < 4; nb++) {
            uint32_t bh[4], bl[4];
            ldsm_x4(bh, stb + 2 * SC_TILE_B + b_off[nb]);
            ldsm_x4(bl, stb + 3 * SC_TILE_B + b_off[nb]);
#pragma unroll
            for (int mf = 0; mf < 2; mf++) {
#pragma unroll
                for (int sub = 0; sub < 2; sub++) {
                    float* d = acc[mf][nb * 2 + sub];
                    mma16816(d, ah[mf], bh[sub * 2], bh[sub * 2 + 1]);
                    mma16816(d, ah[mf], bl[sub * 2], bl[sub * 2 + 1]);
                    mma16816(d, al[mf], bh[sub * 2], bh[sub * 2 + 1]);
                }
            }
        }
        __syncthreads();
    }

    float* st = (float*)sc;
    int g = lane >> 2, tg = lane & 3;
#pragma unroll
    for (int mf = 0; mf < 2; mf++) {
        int rbase = wm * 32 + mf * 16;
#pragma unroll
        for (int n8 = 0; n8 < 8; n8++) {
            int cbase = wn * 64 + n8 * 8 + tg * 2;
            float* d = acc[mf][n8];
            st[(rbase + g) * 133 + cbase]         = d[0];
            st[(rbase + g) * 133 + cbase + 1]     = d[1];
            st[(rbase + g + 8) * 133 + cbase]     = d[2];
            st[(rbase + g + 8) * 133 + cbase + 1] = d[3];
        }
    }
    __syncthreads();

    float* Sb = d_S + (size_t)b * N_ * N_;
    {
        int row = t >> 1, chalf = (t & 1) * 64;
        const float* srow = st + row * 133 + chalf;
        float4* dst = (float4*)&Sb[(size_t)(j0 + row) * N_ + k0 + chalf];
#pragma unroll
        for (int q = 0; q < 16; q++) {
            float4 o;
            o.x = srow[q * 4 + 0]; o.y = srow[q * 4 + 1];
            o.z = srow[q * 4 + 2]; o.w = srow[q * 4 + 3];
            dst[q] = o;
        }
    }
    if (J != K) {
        int r = t & 127, c0 = t >> 7;
#pragma unroll 1
        for (int i = 0; i < 64; i++) {
            int c = c0 + i * 2;
            Sb[(size_t)(k0 + c) * N_ + j0 + r] = st[r * 133 + c];
        }
    }
}

// ---------------------------------------------------------------------------
// K4: transpose adj -> bitmask. adjM[b][x][w] bit k = adj[b][w*32+k][x].
// ---------------------------------------------------------------------------
__global__ void k_adjT(const float* __restrict__ adj) {
    __shared__ float tile[32][33];
    int b = blockIdx.z;
    int x0 = blockIdx.x * 32, y0 = blockIdx.y * 32;
    const float* ab = adj + (size_t)b * N_ * N_;
    int tx = threadIdx.x, ty = threadIdx.y;
#pragma unroll
    for (int i = 0; i < 32; i += 8)
        tile[ty + i][tx] = ab[(size_t)(y0 + ty + i) * N_ + x0 + tx];
    __syncthreads();
    // warp ty handles out-rows x = ty + i*8; lane tx supplies bit tx
#pragma unroll
    for (int i = 0; i < 4; i++) {
        int xr = ty + i * 8;
        uint32_t m = __ballot_sync(0xffffffffu, tile[tx][xr] > 0.f);
        if (tx == 0)
            d_adjM[((size_t)b * N_ + x0 + xr) * (N_ / 32) + (y0 >> 5)] = m;
    }
}

// ---------------------------------------------------------------------------
// K5: fused masked softmax; bitmask mask; emits attn^T bf16 hi/lo.
// ---------------------------------------------------------------------------
__global__ void __launch_bounds__(256) k_sm() {
    __shared__ float red_m[8], red_s[8];
    int b = blockIdx.y, r = blockIdx.x, t = threadIdx.x;
    const float* Mrow = d_S + ((size_t)b * N_ + r) * N_;
    const uint32_t* Mask = d_adjM + ((size_t)b * N_ + r) * (N_ / 32);
    __nv_bfloat16* Oh = d_AThi + ((size_t)b * N_ + r) * N_;
    __nv_bfloat16* Ol = d_ATlo + ((size_t)b * N_ + r) * N_;

    float4 e4 = *(const float4*)&Mrow[t * 4];
    uint32_t w = Mask[t >> 3];
    int sh = (t & 7) * 4;
    bool m0 = (w >> sh) & 1, m1 = (w >> (sh + 1)) & 1;
    bool m2 = (w >> (sh + 2)) & 1, m3 = (w >> (sh + 3)) & 1;

    float v0 = m0 ? e4.x : 0.f;
    float v1 = m1 ? e4.y : 0.f;
    float v2 = m2 ? e4.z : 0.f;
    float v3 = m3 ? e4.w : 0.f;

    float lm = fmaxf(fmaxf(v0, v1), fmaxf(v2, v3));
#pragma unroll
    for (int o = 16; o > 0; o >>= 1)
        lm = fmaxf(lm, __shfl_xor_sync(0xffffffffu, lm, o));
    if ((t & 31) == 0) red_m[t >> 5] = lm;
    __syncthreads();
    float m = red_m[0];
#pragma unroll
    for (int i = 1; i < 8; i++) m = fmaxf(m, red_m[i]);

    float p0 = fexp(v0 - m), p1 = fexp(v1 - m);
    float p2 = fexp(v2 - m), p3 = fexp(v3 - m);
    float ls = (p0 + p1) + (p2 + p3);
#pragma unroll
    for (int o = 16; o > 0; o >>= 1)
        ls += __shfl_xor_sync(0xffffffffu, ls, o);
    if ((t & 31) == 0) red_s[t >> 5] = ls;
    __syncthreads();
    float Z = red_s[0];
#pragma unroll
    for (int i = 1; i < 8; i++) Z += red_s[i];
    float inv = 1.0f / Z;

    float r0 = m0 ? p0 * inv : 0.f;
    float r1 = m1 ? p1 * inv : 0.f;
    float r2 = m2 ? p2 * inv : 0.f;
    float r3 = m3 ? p3 * inv : 0.f;
    uint32_t h01, l01, h23, l23;
    split2(r0, r1, h01, l01);
    split2(r2, r3, h23, l23);
    uint2 ho; ho.x = h01; ho.y = h23;
    uint2 lo; lo.x = l01; lo.y = l23;
    *(uint2*)&Oh[t * 4] = ho;
    *(uint2*)&Ol[t * 4] = lo;
}

// ---------------------------------------------------------------------------
// K6: h' = relu(att @ h) via mma.sync, gates fused. 3-stage cp.async.
// ---------------------------------------------------------------------------
#define KO_TILE_B  (32 * 136 * 2)                   // 8704 B
#define KO_STAGE_B (4 * KO_TILE_B)                  // 34816 B
#define KO_SMEM    (3 * KO_STAGE_B)                 // 104448 B

__global__ void __launch_bounds__(256) k_out_mma(const float* __restrict__ x,
                                                 const float* __restrict__ wiu,
                                                 const float* __restrict__ wfu,
                                                 const float* __restrict__ wou,
                                                 float* __restrict__ out) {
    extern __shared__ char ko[];
    __shared__ float red[3][128];
    __shared__ float wu[3][128];

    int b = blockIdx.y, i0 = blockIdx.x * 128;
    int t = threadIdx.x, lane = t & 31, wid = t >> 5;
    int wm = wid & 3, wn = wid >> 2;
    if (t < 128) {
        wu[0][t] = wiu[t]; wu[1][t] = wfu[t]; wu[2][t] = wou[t];
        red[0][t] = 0.f; red[1][t] = 0.f; red[2][t] = 0.f;
    }

    const __nv_bfloat16* ATh = d_AThi + (size_t)b * N_ * N_;
    const __nv_bfloat16* ATl = d_ATlo + (size_t)b * N_ * N_;
    const __nv_bfloat16* Hh  = d_Uhi + (size_t)b * N_ * 256 + 128;
    const __nv_bfloat16* Hl  = d_Ulo + (size_t)b * N_ * 256 + 128;

    uint32_t sb0 = smem_u32(ko);

    float acc[2][8][4];
#pragma unroll
    for (int i = 0; i < 2; i++)
#pragma unroll
        for (int j = 0; j < 8; j++)
#pragma unroll
            for (int q = 0; q < 4; q++) acc[i][j][q] = 0.f;

    int krA = (lane & 7) + ((lane >> 4) << 3);
    int mcA = wm * 32 + ((lane >> 3) & 1) * 8;
    int krB = (lane & 7) + (((lane >> 3) & 1) << 3);
    int ncB = wn * 64 + ((lane >> 4) << 3);

    int frow0 = t >> 4, fc0 = (t & 15) * 8;
    int frow1 = (t + 256) >> 4;

    auto load_chunk = [&](int kc, int st) {
        uint32_t base = sb0 + st * KO_STAGE_B;
        uint32_t so0 = (uint32_t)(frow0 * 136 + fc0) * 2;
        uint32_t so1 = (uint32_t)(frow1 * 136 + fc0) * 2;
        const char* ga0 = (const char*)(ATh + (size_t)(kc + frow0) * N_ + i0 + fc0);
        const char* ga1 = (const char*)(ATh + (size_t)(kc + frow1) * N_ + i0 + fc0);
        const char* gal0 = (const char*)(ATl + (size_t)(kc + frow0) * N_ + i0 + fc0);
        const char* gal1 = (const char*)(ATl + (size_t)(kc + frow1) * N_ + i0 + fc0);
        const char* gb0 = (const char*)(Hh + (size_t)(kc + frow0) * 256 + fc0);
        const char* gb1 = (const char*)(Hh + (size_t)(kc + frow1) * 256 + fc0);
        const char* gbl0 = (const char*)(Hl + (size_t)(kc + frow0) * 256 + fc0);
        const char* gbl1 = (const char*)(Hl + (size_t)(kc + frow1) * 256 + fc0);
        CP_ASYNC16(base + so0,                  ga0);
        CP_ASYNC16(base + so1,                  ga1);
        CP_ASYNC16(base + KO_TILE_B + so0,      gal0);
        CP_ASYNC16(base + KO_TILE_B + so1,      gal1);
        CP_ASYNC16(base + 2 * KO_TILE_B + so0,  gb0);
        CP_ASYNC16(base + 2 * KO_TILE_B + so1,  gb1);
        CP_ASYNC16(base + 3 * KO_TILE_B + so0,  gbl0);
        CP_ASYNC16(base + 3 * KO_TILE_B + so1,  gbl1);
    };

    load_chunk(0, 0);  CP_COMMIT();
    load_chunk(32, 1); CP_COMMIT();

#pragma unroll 1
    for (int it = 0; it < 32; it++) {
        if (it + 2 < 32) {
            load_chunk((it + 2) * 32, (it + 2) % 3);
            CP_COMMIT();
            CP_WAIT(2);
        } else if (it + 1 < 32) {
            CP_WAIT(1);
        } else {
            CP_WAIT(0);
        }
        __syncthreads();

        uint32_t base = sb0 + (it % 3) * KO_STAGE_B;
#pragma unroll
        for (int s = 0; s < 2; s++) {
            uint32_t ah[2][4], al[2][4];
#pragma unroll
            for (int mf = 0; mf < 2; mf++) {
                uint32_t off = (uint32_t)((s * 16 + krA) * 136 + mcA + mf * 16) * 2;
                ldsm_x4_t(ah[mf], base + off);
                ldsm_x4_t(al[mf], base + KO_TILE_B + off);
            }
#pragma unroll
            for (int np = 0; np < 4; np++) {
                uint32_t boff = (uint32_t)((s * 16 + krB) * 136 + ncB + np * 16) * 2;
                uint32_t bh[4], bl[4];
                ldsm_x4_t(bh, base + 2 * KO_TILE_B + boff);
                ldsm_x4_t(bl, base + 3 * KO_TILE_B + boff);
#pragma unroll
                for (int mf = 0; mf < 2; mf++) {
#pragma unroll
                    for (int sub = 0; sub < 2; sub++) {
                        float* d = acc[mf][np * 2 + sub];
                        mma16816(d, ah[mf], bh[sub * 2], bh[sub * 2 + 1]);
                        mma16816(d, ah[mf], bl[sub * 2], bl[sub * 2 + 1]);
                        mma16816(d, al[mf], bh[sub * 2], bh[sub * 2 + 1]);
                    }
                }
            }
        }
        __syncthreads();
    }

    int g = lane >> 2, q = lane & 3;
    float pp[2][2][3];
#pragma unroll
    for (int mf = 0; mf < 2; mf++)
#pragma unroll
        for (int rh = 0; rh < 2; rh++)
#pragma unroll
            for (int gg = 0; gg < 3; gg++) pp[mf][rh][gg] = 0.f;

#pragma unroll
    for (int mf = 0; mf < 2; mf++) {
#pragma unroll
        for (int n8 = 0; n8 < 8; n8++) {
            int c = wn * 64 + n8 * 8 + q * 2;
            float wa0 = wu[0][c], wb0 = wu[0][c + 1];
            float wa1 = wu[1][c], wb1 = wu[1][c + 1];
            float wa2 = wu[2][c], wb2 = wu[2][c + 1];
            float* d = acc[mf][n8];
            float v0 = fmaxf(d[0], 0.f), v1 = fmaxf(d[1], 0.f);
            float v2 = fmaxf(d[2], 0.f), v3 = fmaxf(d[3], 0.f);
            d[0] = v0; d[1] = v1; d[2] = v2; d[3] = v3;
            pp[mf][0][0] += v0 * wa0 + v1 * wb0;
            pp[mf][0][1] += v0 * wa1 + v1 * wb1;
            pp[mf][0][2] += v0 * wa2 + v1 * wb2;
            pp[mf][1][0] += v2 * wa0 + v3 * wb0;
            pp[mf][1][1] += v2 * wa1 + v3 * wb1;
            pp[mf][1][2] += v2 * wa2 + v3 * wb2;
        }
    }
#pragma unroll
    for (int mf = 0; mf < 2; mf++)
#pragma unroll
        for (int rh = 0; rh < 2; rh++) {
            float s0 = pp[mf][rh][0], s1 = pp[mf][rh][1], s2 = pp[mf][rh][2];
            s0 += __shfl_xor_sync(0xffffffffu, s0, 1);
            s0 += __shfl_xor_sync(0xffffffffu, s0, 2);
            s1 += __shfl_xor_sync(0xffffffffu, s1, 1);
            s1 += __shfl_xor_sync(0xffffffffu, s1, 2);
            s2 += __shfl_xor_sync(0xffffffffu, s2, 1);
            s2 += __shfl_xor_sync(0xffffffffu, s2, 2);
            if (q == 0) {
                int r = wm * 32 + mf * 16 + rh * 8 + g;
                atomicAdd(&red[0][r], s0);
                atomicAdd(&red[1][r], s1);
                atomicAdd(&red[2][r], s2);
            }
        }
    __syncthreads();

    int nb = b * N_ + i0;
#pragma unroll
    for (int mf = 0; mf < 2; mf++) {
#pragma unroll
        for (int rh = 0; rh < 2; rh++) {
            int r = wm * 32 + mf * 16 + rh * 8 + g;
            float zi = red[0][r] + d_xd[nb + r];
            float zf = red[1][r] + d_xd[B_ * N_ + nb + r];
            float zo = red[2][r] + d_xd[2 * B_ * N_ + nb + r];
            float ic = 1.f / (1.f + fexp(-zi));
            float fc = 1.f / (1.f + fexp(-zf));
            float oc = 1.f / (1.f + fexp(-zo));
            const float* xr = x + (size_t)(nb + r) * 128;
            float* orow = out + (size_t)(nb + r) * 128;
#pragma unroll
            for (int n8 = 0; n8 < 8; n8++) {
                int c = wn * 64 + n8 * 8 + q * 2;
                float2 xv = *(const float2*)&xr[c];
                float v0 = acc[mf][n8][rh * 2 + 0];
                float v1 = acc[mf][n8][rh * 2 + 1];
                float2 o;
                o.x = oc * tanhf(ic * v0 + fc * xv.x);
                o.y = oc * tanhf(ic * v1 + fc * xv.y);
                *(float2*)&orow[c] = o;
            }
        }
    }
}

// ---------------------------------------------------------------------------
extern "C" void kernel_launch(void* const* d_in, const int* in_sizes, int n_in,
                              void* d_out, int out_size) {
    const float* x   = (const float*)d_in[0];
    const float* adj = (const float*)d_in[1];
    const float* Ww  = (const float*)d_in[2];
    const float* Wb  = (const float*)d_in[3];
    const float* A   = (const float*)d_in[4];
    const float* wiu = (const float*)d_in[5];
    const float* wix = (const float*)d_in[6];
    const float* wfu = (const float*)d_in[7];
    const float* wfx = (const float*)d_in[8];
    const float* wou = (const float*)d_in[9];
    const float* wox = (const float*)d_in[10];
    float* out = (float*)d_out;

    static int attr_set = 0;
    if (!attr_set) {
        cudaFuncSetAttribute(k_scores_mma, cudaFuncAttributeMaxDynamicSharedMemorySize, SC_SMEM);
        cudaFuncSetAttribute(k_out_mma, cudaFuncAttributeMaxDynamicSharedMemorySize, KO_SMEM);
        cudaFuncSetAttribute(k_gemm_h_mma, cudaFuncAttributeMaxDynamicSharedMemorySize, GH_SMEM);
        cudaFuncSetAttribute(k_gemm_g_mma, cudaFuncAttributeMaxDynamicSharedMemorySize, GG_SMEM);
        attr_set = 1;
    }

    k_prep<<<B_ * N_ / 8, 256>>>(x, wix, wfx, wox, Ww, A);
    k_gemm_h_mma<<<B_ * N_ / 128, 256, GH_SMEM>>>(Wb);
    k_gemm_g_mma<<<B_ * N_ / 128, 256, GG_SMEM>>>();
    {
        dim3 g(36, B_);
        k_scores_mma<<<g, 256, SC_SMEM>>>();
    }
    {
        dim3 g(N_ / 32, N_ / 32, B_);
        k_adjT<<<g, dim3(32, 8)>>>(adj);
    }
    {
        dim3 g(N_, B_);
        k_sm<<<g, 256>>>();
    }
    {
        dim3 g(N_ / 128, B_);
        k_out_mma<<<g, 256, KO_SMEM>>>(x, wiu, wfu, wou, out);
    }
}

// round 13
// speedup vs baseline: 3.9597x; 1.0146x over previous
#include <cuda_runtime.h>
#include <cuda_bf16.h>
#include <math.h>
#include <stdint.h>

#define B_ 16
#define N_ 1024
#define D_ 128

// Scratch (device globals — allocation-free per harness rules)
static __device__ float d_S[B_ * N_ * N_];              // 64 MB: e scores (fp32)
static __device__ uint32_t d_adjM[B_ * N_ * (N_ / 32)]; // 2 MB: transposed adj bitmask
static __device__ float d_xd[3 * B_ * N_];              // x·w*_x per node
static __device__ __nv_bfloat16 d_Uhi[B_ * N_ * 256];   // 8 MB: [g|h] hi part
static __device__ __nv_bfloat16 d_Ulo[B_ * N_ * 256];   // 8 MB: [g|h] lo part
static __device__ __nv_bfloat16 d_AThi[B_ * N_ * N_];   // 32 MB: attn^T hi  [j][i]
static __device__ __nv_bfloat16 d_ATlo[B_ * N_ * N_];   // 32 MB: attn^T lo
static __device__ __nv_bfloat16 d_Xhi[B_ * N_ * D_];    // 4 MB: x hi
static __device__ __nv_bfloat16 d_Xlo[B_ * N_ * D_];    // 4 MB: x lo
static __device__ __nv_bfloat16 d_Whi[D_ * D_];         // Ww [n][k] hi
static __device__ __nv_bfloat16 d_Wlo[D_ * D_];
static __device__ __nv_bfloat16 d_Amhi[D_ * D_];        // A [k][n] hi
static __device__ __nv_bfloat16 d_Amlo[D_ * D_];

// ---------------------------------------------------------------------------
__device__ __forceinline__ uint32_t smem_u32(const void* p) {
    uint32_t a;
    asm("{ .reg .u64 t; cvta.to.shared.u64 t, %1; cvt.u32.u64 %0, t; }" : "=r"(a) : "l"(p));
    return a;
}
__device__ __forceinline__ void ldsm_x4(uint32_t* r, uint32_t addr) {
    asm volatile("ldmatrix.sync.aligned.m8n8.x4.shared.b16 {%0,%1,%2,%3}, [%4];"
                 : "=r"(r[0]), "=r"(r[1]), "=r"(r[2]), "=r"(r[3]) : "r"(addr));
}
__device__ __forceinline__ void ldsm_x4_t(uint32_t* r, uint32_t addr) {
    asm volatile("ldmatrix.sync.aligned.m8n8.x4.trans.shared.b16 {%0,%1,%2,%3}, [%4];"
                 : "=r"(r[0]), "=r"(r[1]), "=r"(r[2]), "=r"(r[3]) : "r"(addr));
}
__device__ __forceinline__ void mma16816(float* d, const uint32_t* a,
                                         uint32_t b0, uint32_t b1) {
    asm volatile(
        "mma.sync.aligned.m16n8k16.row.col.f32.bf16.bf16.f32 "
        "{%0,%1,%2,%3}, {%4,%5,%6,%7}, {%8,%9}, {%0,%1,%2,%3};"
        : "+f"(d[0]), "+f"(d[1]), "+f"(d[2]), "+f"(d[3])
        : "r"(a[0]), "r"(a[1]), "r"(a[2]), "r"(a[3]), "r"(b0), "r"(b1));
}
#define CP_ASYNC16(sa, gp) \
    asm volatile("cp.async.cg.shared.global [%0], [%1], 16;" :: "r"(sa), "l"(gp))
#define CP_COMMIT() asm volatile("cp.async.commit_group;" ::: "memory")
#define CP_WAIT(n)  asm volatile("cp.async.wait_group %0;" :: "n"(n) : "memory")

// fp32 -> bf16 hi/lo split (packed pairs)
__device__ __forceinline__ void split2(float v0, float v1, uint32_t& hi, uint32_t& lo) {
    __nv_bfloat16 h0 = __float2bfloat16(v0), h1 = __float2bfloat16(v1);
    __nv_bfloat16 l0 = __float2bfloat16(v0 - __bfloat162float(h0));
    __nv_bfloat16 l1 = __float2bfloat16(v1 - __bfloat162float(h1));
    __nv_bfloat162 H = __halves2bfloat162(h0, h1);
    __nv_bfloat162 L = __halves2bfloat162(l0, l1);
    hi = *(uint32_t*)&H; lo = *(uint32_t*)&L;
}

// FMA-only exp
__device__ __forceinline__ float fexp(float x) {
    x = fmaxf(x, -87.0f);
    float y = x * 1.44269504089f;
    float n = rintf(y);
    float t = (y - n) * 0.69314718056f;
    float p = 1.38888889e-3f;
    p = fmaf(p, t, 8.33333333e-3f);
    p = fmaf(p, t, 4.16666667e-2f);
    p = fmaf(p, t, 1.66666667e-1f);
    p = fmaf(p, t, 0.5f);
    p = fmaf(p, t, 1.0f);
    p = fmaf(p, t, 1.0f);
    return p * __int_as_float(((int)n + 127) << 23);
}

// ---------------------------------------------------------------------------
// K0: fused prep — per-node gate dots + x hi/lo split; blocks 0..63 also
// split Ww and A.
// ---------------------------------------------------------------------------
__global__ void k_prep(const float* __restrict__ x,
                       const float* __restrict__ wix,
                       const float* __restrict__ wfx,
                       const float* __restrict__ wox,
                       const float* __restrict__ Ww,
                       const float* __restrict__ A) {
    int t = threadIdx.x;
    int row  = blockIdx.x * 8 + (t >> 5);
    int lane = t & 31;
    float4 xv = *(const float4*)(x + (size_t)row * D_ + lane * 4);
    float4 wi = *(const float4*)(wix + lane * 4);
    float4 wf = *(const float4*)(wfx + lane * 4);
    float4 wo = *(const float4*)(wox + lane * 4);
    float s0 = xv.x * wi.x + xv.y * wi.y + xv.z * wi.z + xv.w * wi.w;
    float s1 = xv.x * wf.x + xv.y * wf.y + xv.z * wf.z + xv.w * wf.w;
    float s2 = xv.x * wo.x + xv.y * wo.y + xv.z * wo.z + xv.w * wo.w;
#pragma unroll
    for (int o = 16; o > 0; o >>= 1) {
        s0 += __shfl_xor_sync(0xffffffffu, s0, o);
        s1 += __shfl_xor_sync(0xffffffffu, s1, o);
        s2 += __shfl_xor_sync(0xffffffffu, s2, o);
    }
    if (lane == 0) {
        d_xd[row]               = s0;
        d_xd[B_ * N_ + row]     = s1;
        d_xd[2 * B_ * N_ + row] = s2;
    }
    {
        uint32_t h01, l01, h23, l23;
        split2(xv.x, xv.y, h01, l01);
        split2(xv.z, xv.w, h23, l23);
        uint2 h; h.x = h01; h.y = h23;
        uint2 l; l.x = l01; l.y = l23;
        size_t off = (size_t)row * D_ + lane * 4;
        *(uint2*)&d_Xhi[off] = h;
        *(uint2*)&d_Xlo[off] = l;
    }
    if (blockIdx.x < 64) {
        int i = blockIdx.x * 256 + t;
        float wv = Ww[i];
        __nv_bfloat16 wh = __float2bfloat16(wv);
        d_Whi[i] = wh;
        d_Wlo[i] = __float2bfloat16(wv - __bfloat162float(wh));
        float av = A[i];
        __nv_bfloat16 ah = __float2bfloat16(av);
        d_Amhi[i] = ah;
        d_Amlo[i] = __float2bfloat16(av - __bfloat162float(ah));
    }
}

// ---------------------------------------------------------------------------
// K1: h = x·Ww^T + Wb via mma.sync. Writes U cols [128,256) hi/lo.
// 3-stage single-barrier cp.async pipeline.
// ---------------------------------------------------------------------------
#define GH_TILE_B  (128 * 24 * 2)      // 6144 B
#define GH_STAGE_B (4 * GH_TILE_B)     // 24576 B
#define GH_SMEM    (3 * GH_STAGE_B)    // 73728 B

__global__ void __launch_bounds__(256) k_gemm_h_mma(const float* __restrict__ Wb) {
    extern __shared__ char gh[];
    __shared__ float wb[128];
    uint32_t sbase = smem_u32(gh);
    int t = threadIdx.x, lane = t & 31, wid = t >> 5;
    int wm = wid & 3, wn = wid >> 2;
    if (t < 128) wb[t] = Wb[t];
    int j0 = blockIdx.x * 128;

    float acc[2][8][4];
#pragma unroll
    for (int i = 0; i < 2; i++)
#pragma unroll
        for (int j = 0; j < 8; j++)
#pragma unroll
            for (int q = 0; q < 4; q++) acc[i][j][q] = 0.f;

    int lrow = t >> 1, lhalf = t & 1;
    uint32_t s_off = (uint32_t)(lrow * 24 + lhalf * 8) * 2;

    uint32_t a_off[2];
#pragma unroll
    for (int mf = 0; mf < 2; mf++) {
        int rr = wm * 32 + mf * 16 + (lane & 15);
        a_off[mf] = (uint32_t)(rr * 24 + (lane >> 4) * 8) * 2;
    }
    uint32_t b_off[4];
#pragma unroll
    for (int nb = 0; nb < 4; nb++) {
        int rr = wn * 64 + nb * 16 + ((lane >> 4) << 3) + (lane & 7);
        b_off[nb] = (uint32_t)(rr * 24 + ((lane >> 3) & 1) * 8) * 2;
    }

    auto load_chunk = [&](int ch, int st) {
        uint32_t sb = sbase + st * GH_STAGE_B + s_off;
        const char* gxh = (const char*)(d_Xhi + (size_t)(j0 + lrow) * 128 + ch * 16) + lhalf * 16;
        const char* gxl = (const char*)(d_Xlo + (size_t)(j0 + lrow) * 128 + ch * 16) + lhalf * 16;
        const char* gwh = (const char*)(d_Whi + lrow * 128 + ch * 16) + lhalf * 16;
        const char* gwl = (const char*)(d_Wlo + lrow * 128 + ch * 16) + lhalf * 16;
        CP_ASYNC16(sb,                 gxh);
        CP_ASYNC16(sb + GH_TILE_B,     gxl);
        CP_ASYNC16(sb + 2 * GH_TILE_B, gwh);
        CP_ASYNC16(sb + 3 * GH_TILE_B, gwl);
    };

    load_chunk(0, 0); CP_COMMIT();
    load_chunk(1, 1); CP_COMMIT();

#pragma unroll 1
    for (int ch = 0; ch < 8; ch++) {
        if (ch < 7) CP_WAIT(1); else CP_WAIT(0);
        __syncthreads();
        if (ch + 2 < 8) { load_chunk(ch + 2, (ch + 2) % 3); CP_COMMIT(); }

        uint32_t stb = sbase + (ch % 3) * GH_STAGE_B;
        uint32_t ah[2][4], al[2][4];
#pragma unroll
        for (int mf = 0; mf < 2; mf++) {
            ldsm_x4(ah[mf], stb + a_off[mf]);
            ldsm_x4(al[mf], stb + GH_TILE_B + a_off[mf]);
        }
#pragma unroll
        for (int nb = 0; nb < 4; nb++) {
            uint32_t bh[4], bl[4];
            ldsm_x4(bh, stb + 2 * GH_TILE_B + b_off[nb]);
            ldsm_x4(bl, stb + 3 * GH_TILE_B + b_off[nb]);
#pragma unroll
            for (int mf = 0; mf < 2; mf++) {
#pragma unroll
                for (int sub = 0; sub < 2; sub++) {
                    float* d = acc[mf][nb * 2 + sub];
                    mma16816(d, ah[mf], bh[sub * 2], bh[sub * 2 + 1]);
                    mma16816(d, ah[mf], bl[sub * 2], bl[sub * 2 + 1]);
                    mma16816(d, al[mf], bh[sub * 2], bh[sub * 2 + 1]);
                }
            }
        }
    }

    int g = lane >> 2, q = lane & 3;
#pragma unroll
    for (int mf = 0; mf < 2; mf++) {
#pragma unroll
        for (int n8 = 0; n8 < 8; n8++) {
            int c = wn * 64 + n8 * 8 + q * 2;
            float* d = acc[mf][n8];
            int r0 = j0 + wm * 32 + mf * 16 + g;
            float b0 = wb[c], b1 = wb[c + 1];
            uint32_t hi, lo;
            split2(d[0] + b0, d[1] + b1, hi, lo);
            *(uint32_t*)&d_Uhi[(size_t)r0 * 256 + 128 + c] = hi;
            *(uint32_t*)&d_Ulo[(size_t)r0 * 256 + 128 + c] = lo;
            split2(d[2] + b0, d[3] + b1, hi, lo);
            *(uint32_t*)&d_Uhi[(size_t)(r0 + 8) * 256 + 128 + c] = hi;
            *(uint32_t*)&d_Ulo[(size_t)(r0 + 8) * 256 + 128 + c] = lo;
        }
    }
}

// ---------------------------------------------------------------------------
// K2: g = h·A via mma.sync. Writes U cols [0,128). 3-stage single-barrier.
// ---------------------------------------------------------------------------
#define GG_ATILE_B (128 * 24 * 2)                       // 6144 B
#define GG_BTILE_B (16 * 136 * 2)                       // 4352 B
#define GG_STAGE_B (2 * GG_ATILE_B + 2 * GG_BTILE_B)    // 20992 B
#define GG_SMEM    (3 * GG_STAGE_B)                     // 62976 B

__global__ void __launch_bounds__(256) k_gemm_g_mma() {
    extern __shared__ char gg[];
    uint32_t sbase = smem_u32(gg);
    int t = threadIdx.x, lane = t & 31, wid = t >> 5;
    int wm = wid & 3, wn = wid >> 2;
    int j0 = blockIdx.x * 128;

    float acc[2][8][4];
#pragma unroll
    for (int i = 0; i < 2; i++)
#pragma unroll
        for (int j = 0; j < 8; j++)
#pragma unroll
            for (int q = 0; q < 4; q++) acc[i][j][q] = 0.f;

    int lrow = t >> 1, lhalf = t & 1;
    uint32_t sa_off = (uint32_t)(lrow * 24 + lhalf * 8) * 2;
    int frow = t >> 4, fc = (t & 15) * 8;
    uint32_t sb_off = (uint32_t)(frow * 136 + fc) * 2;

    uint32_t a_off[2];
#pragma unroll
    for (int mf = 0; mf < 2; mf++) {
        int rr = wm * 32 + mf * 16 + (lane & 15);
        a_off[mf] = (uint32_t)(rr * 24 + (lane >> 4) * 8) * 2;
    }
    int krB = (lane & 7) + (((lane >> 3) & 1) << 3);
    int ncB = wn * 64 + ((lane >> 4) << 3);

    auto load_chunk = [&](int ch, int st) {
        uint32_t base = sbase + st * GG_STAGE_B;
        const char* guh = (const char*)(d_Uhi + (size_t)(j0 + lrow) * 256 + 128 + ch * 16) + lhalf * 16;
        const char* gul = (const char*)(d_Ulo + (size_t)(j0 + lrow) * 256 + 128 + ch * 16) + lhalf * 16;
        const char* gah = (const char*)(d_Amhi + (ch * 16 + frow) * 128 + fc);
        const char* gal = (const char*)(d_Amlo + (ch * 16 + frow) * 128 + fc);
        CP_ASYNC16(base + sa_off,                 guh);
        CP_ASYNC16(base + GG_ATILE_B + sa_off,    gul);
        CP_ASYNC16(base + 2 * GG_ATILE_B + sb_off,                gah);
        CP_ASYNC16(base + 2 * GG_ATILE_B + GG_BTILE_B + sb_off,   gal);
    };

    load_chunk(0, 0); CP_COMMIT();
    load_chunk(1, 1); CP_COMMIT();

#pragma unroll 1
    for (int ch = 0; ch < 8; ch++) {
        if (ch < 7) CP_WAIT(1); else CP_WAIT(0);
        __syncthreads();
        if (ch + 2 < 8) { load_chunk(ch + 2, (ch + 2) % 3); CP_COMMIT(); }

        uint32_t base = sbase + (ch % 3) * GG_STAGE_B;
        uint32_t ah[2][4], al[2][4];
#pragma unroll
        for (int mf = 0; mf < 2; mf++) {
            ldsm_x4(ah[mf], base + a_off[mf]);
            ldsm_x4(al[mf], base + GG_ATILE_B + a_off[mf]);
        }
#pragma unroll
        for (int np = 0; np < 4; np++) {
            uint32_t boff = (uint32_t)(krB * 136 + ncB + np * 16) * 2;
            uint32_t bh[4], bl[4];
            ldsm_x4_t(bh, base + 2 * GG_ATILE_B + boff);
            ldsm_x4_t(bl, base + 2 * GG_ATILE_B + GG_BTILE_B + boff);
#pragma unroll
            for (int mf = 0; mf < 2; mf++) {
#pragma unroll
                for (int sub = 0; sub < 2; sub++) {
                    float* d = acc[mf][np * 2 + sub];
                    mma16816(d, ah[mf], bh[sub * 2], bh[sub * 2 + 1]);
                    mma16816(d, ah[mf], bl[sub * 2], bl[sub * 2 + 1]);
                    mma16816(d, al[mf], bh[sub * 2], bh[sub * 2 + 1]);
                }
            }
        }
    }

    int g = lane >> 2, q = lane & 3;
#pragma unroll
    for (int mf = 0; mf < 2; mf++) {
#pragma unroll
        for (int n8 = 0; n8 < 8; n8++) {
            int c = wn * 64 + n8 * 8 + q * 2;
            float* d = acc[mf][n8];
            int r0 = j0 + wm * 32 + mf * 16 + g;
            uint32_t hi, lo;
            split2(d[0], d[1], hi, lo);
            *(uint32_t*)&d_Uhi[(size_t)r0 * 256 + c] = hi;
            *(uint32_t*)&d_Ulo[(size_t)r0 * 256 + c] = lo;
            split2(d[2], d[3], hi, lo);
            *(uint32_t*)&d_Uhi[(size_t)(r0 + 8) * 256 + c] = hi;
            *(uint32_t*)&d_Ulo[(size_t)(r0 + 8) * 256 + c] = lo;
        }
    }
}

// ---------------------------------------------------------------------------
// K3: scores via mma.sync. e = U·V^T, K=256, V = half-swapped U.
// 3-stage single-barrier cp.async pipeline.
// ---------------------------------------------------------------------------
#define SC_TILE_B  (128 * 24 * 2)                   // 6144 B per operand tile
#define SC_STAGE_B (4 * SC_TILE_B)                  // 24576 B per stage
#define SC_SMEM    (3 * SC_STAGE_B)                 // 73728 B (stash 68096 fits)

__global__ void __launch_bounds__(256) k_scores_mma() {
    extern __shared__ char sc[];
    uint32_t sbase = smem_u32(sc);

    int t = threadIdx.x, lane = t & 31, wid = t >> 5;
    int wm = wid & 3, wn = wid >> 2;

    int b = blockIdx.y;
    int rem = blockIdx.x;
    int J = 0;
    while (rem >= 8 - J) { rem -= 8 - J; J++; }
    int K = J + rem;
    int j0 = J * 128, k0 = K * 128;

    const __nv_bfloat16* Uh = d_Uhi + (size_t)b * N_ * 256;
    const __nv_bfloat16* Ul = d_Ulo + (size_t)b * N_ * 256;

    float acc[2][8][4];
#pragma unroll
    for (int i = 0; i < 2; i++)
#pragma unroll
        for (int j = 0; j < 8; j++)
#pragma unroll
            for (int q = 0; q < 4; q++) acc[i][j][q] = 0.f;

    int lrow = t >> 1, lhalf = t & 1;
    uint32_t s_off = (uint32_t)(lrow * 24 + lhalf * 8) * 2;

    uint32_t a_off[2];
#pragma unroll
    for (int mf = 0; mf < 2; mf++) {
        int rr = wm * 32 + mf * 16 + (lane & 15);
        a_off[mf] = (uint32_t)(rr * 24 + (lane >> 4) * 8) * 2;
    }
    uint32_t b_off[4];
#pragma unroll
    for (int nb = 0; nb < 4; nb++) {
        int rr = wn * 64 + nb * 16 + ((lane >> 4) << 3) + (lane & 7);
        b_off[nb] = (uint32_t)(rr * 24 + ((lane >> 3) & 1) * 8) * 2;
    }

    auto load_chunk = [&](int ch, int st) {
        int ca = ch * 16;
        int cb = (ca + 128) & 255;
        uint32_t sb = sbase + st * SC_STAGE_B + s_off;
        const char* gAh = (const char*)(Uh + (size_t)(j0 + lrow) * 256 + ca) + lhalf * 16;
        const char* gAl = (const char*)(Ul + (size_t)(j0 + lrow) * 256 + ca) + lhalf * 16;
        const char* gBh = (const char*)(Uh + (size_t)(k0 + lrow) * 256 + cb) + lhalf * 16;
        const char* gBl = (const char*)(Ul + (size_t)(k0 + lrow) * 256 + cb) + lhalf * 16;
        CP_ASYNC16(sb,                 gAh);
        CP_ASYNC16(sb + SC_TILE_B,     gAl);
        CP_ASYNC16(sb + 2 * SC_TILE_B, gBh);
        CP_ASYNC16(sb + 3 * SC_TILE_B, gBl);
    };

    load_chunk(0, 0); CP_COMMIT();
    load_chunk(1, 1); CP_COMMIT();

#pragma unroll 1
    for (int ch = 0; ch < 16; ch++) {
        if (ch < 15) CP_WAIT(1); else CP_WAIT(0);
        __syncthreads();
        if (ch + 2 < 16) { load_chunk(ch + 2, (ch + 2) % 3); CP_COMMIT(); }

        uint32_t stb = sbase + (ch % 3) * SC_STAGE_B;
        uint32_t ah[2][4], al[2][4];
#pragma unroll
        for (int mf = 0; mf < 2; mf++) {
            ldsm_x4(ah[mf], stb + a_off[mf]);
            ldsm_x4(al[mf], stb + SC_TILE_B + a_off[mf]);
        }
#pragma unroll
        for (int nb = 0; nb < 4; nb++) {
            uint32_t bh[4], bl[4];
            ldsm_x4(bh, stb + 2 * SC_TILE_B + b_off[nb]);
            ldsm_x4(bl, stb + 3 * SC_TILE_B + b_off[nb]);
#pragma unroll
            for (int mf = 0; mf < 2; mf++) {
#pragma unroll
                for (int sub = 0; sub < 2; sub++) {
                    float* d = acc[mf][nb * 2 + sub];
                    mma16816(d, ah[mf], bh[sub * 2], bh[sub * 2 + 1]);
                    mma16816(d, ah[mf], bl[sub * 2], bl[sub * 2 + 1]);
                    mma16816(d, al[mf], bh[sub * 2], bh[sub * 2 + 1]);
                }
            }
        }
    }
    __syncthreads();   // all warps done with stage smem before stash reuse

    float* st = (float*)sc;
    int g = lane >> 2, tg = lane & 3;
#pragma unroll
    for (int mf = 0; mf < 2; mf++) {
        int rbase = wm * 32 + mf * 16;
#pragma unroll
        for (int n8 = 0; n8 < 8; n8++) {
            int cbase = wn * 64 + n8 * 8 + tg * 2;
            float* d = acc[mf][n8];
            st[(rbase + g) * 133 + cbase]         = d[0];
            st[(rbase + g) * 133 + cbase + 1]     = d[1];
            st[(rbase + g + 8) * 133 + cbase]     = d[2];
            st[(rbase + g + 8) * 133 + cbase + 1] = d[3];
        }
    }
    __syncthreads();

    float* Sb = d_S + (size_t)b * N_ * N_;
    {
        int row = t >> 1, chalf = (t & 1) * 64;
        const float* srow = st + row * 133 + chalf;
        float4* dst = (float4*)&Sb[(size_t)(j0 + row) * N_ + k0 + chalf];
#pragma unroll
        for (int q = 0; q < 16; q++) {
            float4 o;
            o.x = srow[q * 4 + 0]; o.y = srow[q * 4 + 1];
            o.z = srow[q * 4 + 2]; o.w = srow[q * 4 + 3];
            dst[q] = o;
        }
    }
    if (J != K) {
        int r = t & 127, c0 = t >> 7;
#pragma unroll 1
        for (int i = 0; i < 64; i++) {
            int c = c0 + i * 2;
            Sb[(size_t)(k0 + c) * N_ + j0 + r] = st[r * 133 + c];
        }
    }
}

// ---------------------------------------------------------------------------
// K4: transpose adj -> bitmask. adjM[b][x][w] bit k = adj[b][w*32+k][x].
// ---------------------------------------------------------------------------
__global__ void k_adjT(const float* __restrict__ adj) {
    __shared__ float tile[32][33];
    int b = blockIdx.z;
    int x0 = blockIdx.x * 32, y0 = blockIdx.y * 32;
    const float* ab = adj + (size_t)b * N_ * N_;
    int tx = threadIdx.x, ty = threadIdx.y;
#pragma unroll
    for (int i = 0; i < 32; i += 8)
        tile[ty + i][tx] = ab[(size_t)(y0 + ty + i) * N_ + x0 + tx];
    __syncthreads();
#pragma unroll
    for (int i = 0; i < 4; i++) {
        int xr = ty + i * 8;
        uint32_t m = __ballot_sync(0xffffffffu, tile[tx][xr] > 0.f);
        if (tx == 0)
            d_adjM[((size_t)b * N_ + x0 + xr) * (N_ / 32) + (y0 >> 5)] = m;
    }
}

// ---------------------------------------------------------------------------
// K5: fused masked softmax; bitmask mask; emits attn^T bf16 hi/lo.
// ---------------------------------------------------------------------------
__global__ void __launch_bounds__(256) k_sm() {
    __shared__ float red_m[8], red_s[8];
    int b = blockIdx.y, r = blockIdx.x, t = threadIdx.x;
    const float* Mrow = d_S + ((size_t)b * N_ + r) * N_;
    const uint32_t* Mask = d_adjM + ((size_t)b * N_ + r) * (N_ / 32);
    __nv_bfloat16* Oh = d_AThi + ((size_t)b * N_ + r) * N_;
    __nv_bfloat16* Ol = d_ATlo + ((size_t)b * N_ + r) * N_;

    float4 e4 = *(const float4*)&Mrow[t * 4];
    uint32_t w = Mask[t >> 3];
    int sh = (t & 7) * 4;
    bool m0 = (w >> sh) & 1, m1 = (w >> (sh + 1)) & 1;
    bool m2 = (w >> (sh + 2)) & 1, m3 = (w >> (sh + 3)) & 1;

    float v0 = m0 ? e4.x : 0.f;
    float v1 = m1 ? e4.y : 0.f;
    float v2 = m2 ? e4.z : 0.f;
    float v3 = m3 ? e4.w : 0.f;

    float lm = fmaxf(fmaxf(v0, v1), fmaxf(v2, v3));
#pragma unroll
    for (int o = 16; o > 0; o >>= 1)
        lm = fmaxf(lm, __shfl_xor_sync(0xffffffffu, lm, o));
    if ((t & 31) == 0) red_m[t >> 5] = lm;
    __syncthreads();
    float m = red_m[0];
#pragma unroll
    for (int i = 1; i < 8; i++) m = fmaxf(m, red_m[i]);

    float p0 = fexp(v0 - m), p1 = fexp(v1 - m);
    float p2 = fexp(v2 - m), p3 = fexp(v3 - m);
    float ls = (p0 + p1) + (p2 + p3);
#pragma unroll
    for (int o = 16; o > 0; o >>= 1)
        ls += __shfl_xor_sync(0xffffffffu, ls, o);
    if ((t & 31) == 0) red_s[t >> 5] = ls;
    __syncthreads();
    float Z = red_s[0];
#pragma unroll
    for (int i = 1; i < 8; i++) Z += red_s[i];
    float inv = 1.0f / Z;

    float r0 = m0 ? p0 * inv : 0.f;
    float r1 = m1 ? p1 * inv : 0.f;
    float r2 = m2 ? p2 * inv : 0.f;
    float r3 = m3 ? p3 * inv : 0.f;
    uint32_t h01, l01, h23, l23;
    split2(r0, r1, h01, l01);
    split2(r2, r3, h23, l23);
    uint2 ho; ho.x = h01; ho.y = h23;
    uint2 lo; lo.x = l01; lo.y = l23;
    *(uint2*)&Oh[t * 4] = ho;
    *(uint2*)&Ol[t * 4] = lo;
}

// ---------------------------------------------------------------------------
// K6: h' = relu(att @ h) via mma.sync, gates fused. 3-stage single-barrier.
// ---------------------------------------------------------------------------
#define KO_TILE_B  (32 * 136 * 2)                   // 8704 B
#define KO_STAGE_B (4 * KO_TILE_B)                  // 34816 B
#define KO_SMEM    (3 * KO_STAGE_B)                 // 104448 B

__global__ void __launch_bounds__(256) k_out_mma(const float* __restrict__ x,
                                                 const float* __restrict__ wiu,
                                                 const float* __restrict__ wfu,
                                                 const float* __restrict__ wou,
                                                 float* __restrict__ out) {
    extern __shared__ char ko[];
    __shared__ float red[3][128];
    __shared__ float wu[3][128];

    int b = blockIdx.y, i0 = blockIdx.x * 128;
    int t = threadIdx.x, lane = t & 31, wid = t >> 5;
    int wm = wid & 3, wn = wid >> 2;
    if (t < 128) {
        wu[0][t] = wiu[t]; wu[1][t] = wfu[t]; wu[2][t] = wou[t];
        red[0][t] = 0.f; red[1][t] = 0.f; red[2][t] = 0.f;
    }

    const __nv_bfloat16* ATh = d_AThi + (size_t)b * N_ * N_;
    const __nv_bfloat16* ATl = d_ATlo + (size_t)b * N_ * N_;
    const __nv_bfloat16* Hh  = d_Uhi + (size_t)b * N_ * 256 + 128;
    const __nv_bfloat16* Hl  = d_Ulo + (size_t)b * N_ * 256 + 128;

    uint32_t sb0 = smem_u32(ko);

    float acc[2][8][4];
#pragma unroll
    for (int i = 0; i < 2; i++)
#pragma unroll
        for (int j = 0; j < 8; j++)
#pragma unroll
            for (int q = 0; q < 4; q++) acc[i][j][q] = 0.f;

    int krA = (lane & 7) + ((lane >> 4) << 3);
    int mcA = wm * 32 + ((lane >> 3) & 1) * 8;
    int krB = (lane & 7) + (((lane >> 3) & 1) << 3);
    int ncB = wn * 64 + ((lane >> 4) << 3);

    int frow0 = t >> 4, fc0 = (t & 15) * 8;
    int frow1 = (t + 256) >> 4;

    auto load_chunk = [&](int kc, int st) {
        uint32_t base = sb0 + st * KO_STAGE_B;
        uint32_t so0 = (uint32_t)(frow0 * 136 + fc0) * 2;
        uint32_t so1 = (uint32_t)(frow1 * 136 + fc0) * 2;
        const char* ga0 = (const char*)(ATh + (size_t)(kc + frow0) * N_ + i0 + fc0);
        const char* ga1 = (const char*)(ATh + (size_t)(kc + frow1) * N_ + i0 + fc0);
        const char* gal0 = (const char*)(ATl + (size_t)(kc + frow0) * N_ + i0 + fc0);
        const char* gal1 = (const char*)(ATl + (size_t)(kc + frow1) * N_ + i0 + fc0);
        const char* gb0 = (const char*)(Hh + (size_t)(kc + frow0) * 256 + fc0);
        const char* gb1 = (const char*)(Hh + (size_t)(kc + frow1) * 256 + fc0);
        const char* gbl0 = (const char*)(Hl + (size_t)(kc + frow0) * 256 + fc0);
        const char* gbl1 = (const char*)(Hl + (size_t)(kc + frow1) * 256 + fc0);
        CP_ASYNC16(base + so0,                  ga0);
        CP_ASYNC16(base + so1,                  ga1);
        CP_ASYNC16(base + KO_TILE_B + so0,      gal0);
        CP_ASYNC16(base + KO_TILE_B + so1,      gal1);
        CP_ASYNC16(base + 2 * KO_TILE_B + so0,  gb0);
        CP_ASYNC16(base + 2 * KO_TILE_B + so1,  gb1);
        CP_ASYNC16(base + 3 * KO_TILE_B + so0,  gbl0);
        CP_ASYNC16(base + 3 * KO_TILE_B + so1,  gbl1);
    };

    load_chunk(0, 0);  CP_COMMIT();
    load_chunk(32, 1); CP_COMMIT();

#pragma unroll 1
    for (int it = 0; it < 32; it++) {
        if (it < 31) CP_WAIT(1); else CP_WAIT(0);
        __syncthreads();
        if (it + 2 < 32) { load_chunk((it + 2) * 32, (it + 2) % 3); CP_COMMIT(); }

        uint32_t base = sb0 + (it % 3) * KO_STAGE_B;
#pragma unroll
        for (int s = 0; s < 2; s++) {
            uint32_t ah[2][4], al[2][4];
#pragma unroll
            for (int mf = 0; mf < 2; mf++) {
                uint32_t off = (uint32_t)((s * 16 + krA) * 136 + mcA + mf * 16) * 2;
                ldsm_x4_t(ah[mf], base + off);
                ldsm_x4_t(al[mf], base + KO_TILE_B + off);
            }
#pragma unroll
            for (int np = 0; np < 4; np++) {
                uint32_t boff = (uint32_t)((s * 16 + krB) * 136 + ncB + np * 16) * 2;
                uint32_t bh[4], bl[4];
                ldsm_x4_t(bh, base + 2 * KO_TILE_B + boff);
                ldsm_x4_t(bl, base + 3 * KO_TILE_B + boff);
#pragma unroll
                for (int mf = 0; mf < 2; mf++) {
#pragma unroll
                    for (int sub = 0; sub < 2; sub++) {
                        float* d = acc[mf][np * 2 + sub];
                        mma16816(d, ah[mf], bh[sub * 2], bh[sub * 2 + 1]);
                        mma16816(d, ah[mf], bl[sub * 2], bl[sub * 2 + 1]);
                        mma16816(d, al[mf], bh[sub * 2], bh[sub * 2 + 1]);
                    }
                }
            }
        }
    }

    int g = lane >> 2, q = lane & 3;
    float pp[2][2][3];
#pragma unroll
    for (int mf = 0; mf < 2; mf++)
#pragma unroll
        for (int rh = 0; rh < 2; rh++)
#pragma unroll
            for (int gg = 0; gg < 3; gg++) pp[mf][rh][gg] = 0.f;

#pragma unroll
    for (int mf = 0; mf < 2; mf++) {
#pragma unroll
        for (int n8 = 0; n8 < 8; n8++) {
            int c = wn * 64 + n8 * 8 + q * 2;
            float wa0 = wu[0][c], wb0 = wu[0][c + 1];
            float wa1 = wu[1][c], wb1 = wu[1][c + 1];
            float wa2 = wu[2][c], wb2 = wu[2][c + 1];
            float* d = acc[mf][n8];
            float v0 = fmaxf(d[0], 0.f), v1 = fmaxf(d[1], 0.f);
            float v2 = fmaxf(d[2], 0.f), v3 = fmaxf(d[3], 0.f);
            d[0] = v0; d[1] = v1; d[2] = v2; d[3] = v3;
            pp[mf][0][0] += v0 * wa0 + v1 * wb0;
            pp[mf][0][1] += v0 * wa1 + v1 * wb1;
            pp[mf][0][2] += v0 * wa2 + v1 * wb2;
            pp[mf][1][0] += v2 * wa0 + v3 * wb0;
            pp[mf][1][1] += v2 * wa1 + v3 * wb1;
            pp[mf][1][2] += v2 * wa2 + v3 * wb2;
        }
    }
#pragma unroll
    for (int mf = 0; mf < 2; mf++)
#pragma unroll
        for (int rh = 0; rh < 2; rh++) {
            float s0 = pp[mf][rh][0], s1 = pp[mf][rh][1], s2 = pp[mf][rh][2];
            s0 += __shfl_xor_sync(0xffffffffu, s0, 1);
            s0 += __shfl_xor_sync(0xffffffffu, s0, 2);
            s1 += __shfl_xor_sync(0xffffffffu, s1, 1);
            s1 += __shfl_xor_sync(0xffffffffu, s1, 2);
            s2 += __shfl_xor_sync(0xffffffffu, s2, 1);
            s2 += __shfl_xor_sync(0xffffffffu, s2, 2);
            if (q == 0) {
                int r = wm * 32 + mf * 16 + rh * 8 + g;
                atomicAdd(&red[0][r], s0);
                atomicAdd(&red[1][r], s1);
                atomicAdd(&red[2][r], s2);
            }
        }
    __syncthreads();

    int nb = b * N_ + i0;
#pragma unroll
    for (int mf = 0; mf < 2; mf++) {
#pragma unroll
        for (int rh = 0; rh < 2; rh++) {
            int r = wm * 32 + mf * 16 + rh * 8 + g;
            float zi = red[0][r] + d_xd[nb + r];
            float zf = red[1][r] + d_xd[B_ * N_ + nb + r];
            float zo = red[2][r] + d_xd[2 * B_ * N_ + nb + r];
            float ic = 1.f / (1.f + fexp(-zi));
            float fc = 1.f / (1.f + fexp(-zf));
            float oc = 1.f / (1.f + fexp(-zo));
            const float* xr = x + (size_t)(nb + r) * 128;
            float* orow = out + (size_t)(nb + r) * 128;
#pragma unroll
            for (int n8 = 0; n8 < 8; n8++) {
                int c = wn * 64 + n8 * 8 + q * 2;
                float2 xv = *(const float2*)&xr[c];
                float v0 = acc[mf][n8][rh * 2 + 0];
                float v1 = acc[mf][n8][rh * 2 + 1];
                float2 o;
                o.x = oc * tanhf(ic * v0 + fc * xv.x);
                o.y = oc * tanhf(ic * v1 + fc * xv.y);
                *(float2*)&orow[c] = o;
            }
        }
    }
}

// ---------------------------------------------------------------------------
extern "C" void kernel_launch(void* const* d_in, const int* in_sizes, int n_in,
                              void* d_out, int out_size) {
    const float* x   = (const float*)d_in[0];
    const float* adj = (const float*)d_in[1];
    const float* Ww  = (const float*)d_in[2];
    const float* Wb  = (const float*)d_in[3];
    const float* A   = (const float*)d_in[4];
    const float* wiu = (const float*)d_in[5];
    const float* wix = (const float*)d_in[6];
    const float* wfu = (const float*)d_in[7];
    const float* wfx = (const float*)d_in[8];
    const float* wou = (const float*)d_in[9];
    const float* wox = (const float*)d_in[10];
    float* out = (float*)d_out;

    static int attr_set = 0;
    if (!attr_set) {
        cudaFuncSetAttribute(k_scores_mma, cudaFuncAttributeMaxDynamicSharedMemorySize, SC_SMEM);
        cudaFuncSetAttribute(k_out_mma, cudaFuncAttributeMaxDynamicSharedMemorySize, KO_SMEM);
        cudaFuncSetAttribute(k_gemm_h_mma, cudaFuncAttributeMaxDynamicSharedMemorySize, GH_SMEM);
        cudaFuncSetAttribute(k_gemm_g_mma, cudaFuncAttributeMaxDynamicSharedMemorySize, GG_SMEM);
        attr_set = 1;
    }

    k_prep<<<B_ * N_ / 8, 256>>>(x, wix, wfx, wox, Ww, A);
    k_gemm_h_mma<<<B_ * N_ / 128, 256, GH_SMEM>>>(Wb);
    k_gemm_g_mma<<<B_ * N_ / 128, 256, GG_SMEM>>>();
    {
        dim3 g(36, B_);
        k_scores_mma<<<g, 256, SC_SMEM>>>();
    }
    {
        dim3 g(N_ / 32, N_ / 32, B_);
        k_adjT<<<g, dim3(32, 8)>>>(adj);
    }
    {
        dim3 g(N_, B_);
        k_sm<<<g, 256>>>();
    }
    {
        dim3 g(N_ / 128, B_);
        k_out_mma<<<g, 256, KO_SMEM>>>(x, wiu, wfu, wou, out);
    }
}

// round 16
// speedup vs baseline: 4.5789x; 1.1564x over previous
#include <cuda_runtime.h>
#include <cuda_fp16.h>
#include <math.h>
#include <stdint.h>

#define B_ 16
#define N_ 1024
#define D_ 128

// Scratch (device globals — allocation-free per harness rules)
static __device__ float d_S[B_ * N_ * N_];              // 64 MB: e scores (fp32)
static __device__ uint32_t d_adjM[B_ * N_ * (N_ / 32)]; // 2 MB: transposed adj bitmask
static __device__ float d_xd[3 * B_ * N_];              // x·w*_x per node
static __device__ __half d_Uhi[B_ * N_ * 256];          // 8 MB: [g|h] hi part (fp16)
static __device__ __half d_Ulo[B_ * N_ * 256];          // 8 MB: [g|h] lo part
static __device__ __half d_AThi[B_ * N_ * N_];          // 32 MB: attn^T fp16 [j][i]
static __device__ __half d_Xhi[B_ * N_ * D_];           // 4 MB: x hi
static __device__ __half d_Xlo[B_ * N_ * D_];           // 4 MB: x lo
static __device__ __half d_Whi[D_ * D_];                // Ww [n][k] hi
static __device__ __half d_Wlo[D_ * D_];
static __device__ __half d_Amhi[D_ * D_];               // A [k][n] hi
static __device__ __half d_Amlo[D_ * D_];

// ---------------------------------------------------------------------------
__device__ __forceinline__ uint32_t smem_u32(const void* p) {
    uint32_t a;
    asm("{ .reg .u64 t; cvta.to.shared.u64 t, %1; cvt.u32.u64 %0, t; }" : "=r"(a) : "l"(p));
    return a;
}
__device__ __forceinline__ void ldsm_x4(uint32_t* r, uint32_t addr) {
    asm volatile("ldmatrix.sync.aligned.m8n8.x4.shared.b16 {%0,%1,%2,%3}, [%4];"
                 : "=r"(r[0]), "=r"(r[1]), "=r"(r[2]), "=r"(r[3]) : "r"(addr));
}
__device__ __forceinline__ void ldsm_x4_t(uint32_t* r, uint32_t addr) {
    asm volatile("ldmatrix.sync.aligned.m8n8.x4.trans.shared.b16 {%0,%1,%2,%3}, [%4];"
                 : "=r"(r[0]), "=r"(r[1]), "=r"(r[2]), "=r"(r[3]) : "r"(addr));
}
// fp16 MMA, fp32 accumulate
__device__ __forceinline__ void mma16816h(float* d, const uint32_t* a,
                                          uint32_t b0, uint32_t b1) {
    asm volatile(
        "mma.sync.aligned.m16n8k16.row.col.f32.f16.f16.f32 "
        "{%0,%1,%2,%3}, {%4,%5,%6,%7}, {%8,%9}, {%0,%1,%2,%3};"
        : "+f"(d[0]), "+f"(d[1]), "+f"(d[2]), "+f"(d[3])
        : "r"(a[0]), "r"(a[1]), "r"(a[2]), "r"(a[3]), "r"(b0), "r"(b1));
}
#define CP_ASYNC16(sa, gp) \
    asm volatile("cp.async.cg.shared.global [%0], [%1], 16;" :: "r"(sa), "l"(gp))
#define CP_COMMIT() asm volatile("cp.async.commit_group;" ::: "memory")
#define CP_WAIT(n)  asm volatile("cp.async.wait_group %0;" :: "n"(n) : "memory")

// fp32 -> fp16 hi/lo split (packed pairs)
__device__ __forceinline__ void split2h(float v0, float v1, uint32_t& hi, uint32_t& lo) {
    __half h0 = __float2half(v0), h1 = __float2half(v1);
    __half l0 = __float2half(v0 - __half2float(h0));
    __half l1 = __float2half(v1 - __half2float(h1));
    __half2 H = __halves2half2(h0, h1);
    __half2 L = __halves2half2(l0, l1);
    hi = *(uint32_t*)&H; lo = *(uint32_t*)&L;
}
// fp32 -> fp16 hi only (packed pair)
__device__ __forceinline__ uint32_t pack2h(float v0, float v1) {
    __half2 H = __halves2half2(__float2half(v0), __float2half(v1));
    return *(uint32_t*)&H;
}

// FMA-only exp
__device__ __forceinline__ float fexp(float x) {
    x = fmaxf(x, -87.0f);
    float y = x * 1.44269504089f;
    float n = rintf(y);
    float t = (y - n) * 0.69314718056f;
    float p = 1.38888889e-3f;
    p = fmaf(p, t, 8.33333333e-3f);
    p = fmaf(p, t, 4.16666667e-2f);
    p = fmaf(p, t, 1.66666667e-1f);
    p = fmaf(p, t, 0.5f);
    p = fmaf(p, t, 1.0f);
    p = fmaf(p, t, 1.0f);
    return p * __int_as_float(((int)n + 127) << 23);
}

// ---------------------------------------------------------------------------
// K0: fused prep — per-node gate dots + x hi/lo split; blocks 0..63 also
// split Ww and A.
// ---------------------------------------------------------------------------
__global__ void k_prep(const float* __restrict__ x,
                       const float* __restrict__ wix,
                       const float* __restrict__ wfx,
                       const float* __restrict__ wox,
                       const float* __restrict__ Ww,
                       const float* __restrict__ A) {
    int t = threadIdx.x;
    int row  = blockIdx.x * 8 + (t >> 5);
    int lane = t & 31;
    float4 xv = *(const float4*)(x + (size_t)row * D_ + lane * 4);
    float4 wi = *(const float4*)(wix + lane * 4);
    float4 wf = *(const float4*)(wfx + lane * 4);
    float4 wo = *(const float4*)(wox + lane * 4);
    float s0 = xv.x * wi.x + xv.y * wi.y + xv.z * wi.z + xv.w * wi.w;
    float s1 = xv.x * wf.x + xv.y * wf.y + xv.z * wf.z + xv.w * wf.w;
    float s2 = xv.x * wo.x + xv.y * wo.y + xv.z * wo.z + xv.w * wo.w;
#pragma unroll
    for (int o = 16; o > 0; o >>= 1) {
        s0 += __shfl_xor_sync(0xffffffffu, s0, o);
        s1 += __shfl_xor_sync(0xffffffffu, s1, o);
        s2 += __shfl_xor_sync(0xffffffffu, s2, o);
    }
    if (lane == 0) {
        d_xd[row]               = s0;
        d_xd[B_ * N_ + row]     = s1;
        d_xd[2 * B_ * N_ + row] = s2;
    }
    {
        uint32_t h01, l01, h23, l23;
        split2h(xv.x, xv.y, h01, l01);
        split2h(xv.z, xv.w, h23, l23);
        uint2 h; h.x = h01; h.y = h23;
        uint2 l; l.x = l01; l.y = l23;
        size_t off = (size_t)row * D_ + lane * 4;
        *(uint2*)&d_Xhi[off] = h;
        *(uint2*)&d_Xlo[off] = l;
    }
    if (blockIdx.x < 64) {
        int i = blockIdx.x * 256 + t;
        float wv = Ww[i];
        __half wh = __float2half(wv);
        d_Whi[i] = wh;
        d_Wlo[i] = __float2half(wv - __half2float(wh));
        float av = A[i];
        __half ah = __float2half(av);
        d_Amhi[i] = ah;
        d_Amlo[i] = __float2half(av - __half2float(ah));
    }
}

// ---------------------------------------------------------------------------
// K1: h = x·Ww^T + Wb via fp16 mma (3-term). Writes U cols [128,256) hi/lo.
// 3-stage single-barrier cp.async pipeline.
// ---------------------------------------------------------------------------
#define GH_TILE_B  (128 * 24 * 2)      // 6144 B
#define GH_STAGE_B (4 * GH_TILE_B)     // 24576 B
#define GH_SMEM    (3 * GH_STAGE_B)    // 73728 B

__global__ void __launch_bounds__(256) k_gemm_h_mma(const float* __restrict__ Wb) {
    extern __shared__ char gh[];
    __shared__ float wb[128];
    uint32_t sbase = smem_u32(gh);
    int t = threadIdx.x, lane = t & 31, wid = t >> 5;
    int wm = wid & 3, wn = wid >> 2;
    if (t < 128) wb[t] = Wb[t];
    int j0 = blockIdx.x * 128;

    float acc[2][8][4];
#pragma unroll
    for (int i = 0; i < 2; i++)
#pragma unroll
        for (int j = 0; j < 8; j++)
#pragma unroll
            for (int q = 0; q < 4; q++) acc[i][j][q] = 0.f;

    int lrow = t >> 1, lhalf = t & 1;
    uint32_t s_off = (uint32_t)(lrow * 24 + lhalf * 8) * 2;

    uint32_t a_off[2];
#pragma unroll
    for (int mf = 0; mf < 2; mf++) {
        int rr = wm * 32 + mf * 16 + (lane & 15);
        a_off[mf] = (uint32_t)(rr * 24 + (lane >> 4) * 8) * 2;
    }
    uint32_t b_off[4];
#pragma unroll
    for (int nb = 0; nb < 4; nb++) {
        int rr = wn * 64 + nb * 16 + ((lane >> 4) << 3) + (lane & 7);
        b_off[nb] = (uint32_t)(rr * 24 + ((lane >> 3) & 1) * 8) * 2;
    }

    auto load_chunk = [&](int ch, int st) {
        uint32_t sb = sbase + st * GH_STAGE_B + s_off;
        const char* gxh = (const char*)(d_Xhi + (size_t)(j0 + lrow) * 128 + ch * 16) + lhalf * 16;
        const char* gxl = (const char*)(d_Xlo + (size_t)(j0 + lrow) * 128 + ch * 16) + lhalf * 16;
        const char* gwh = (const char*)(d_Whi + lrow * 128 + ch * 16) + lhalf * 16;
        const char* gwl = (const char*)(d_Wlo + lrow * 128 + ch * 16) + lhalf * 16;
        CP_ASYNC16(sb,                 gxh);
        CP_ASYNC16(sb + GH_TILE_B,     gxl);
        CP_ASYNC16(sb + 2 * GH_TILE_B, gwh);
        CP_ASYNC16(sb + 3 * GH_TILE_B, gwl);
    };

    load_chunk(0, 0); CP_COMMIT();
    load_chunk(1, 1); CP_COMMIT();

#pragma unroll 1
    for (int ch = 0; ch < 8; ch++) {
        if (ch < 7) CP_WAIT(1); else CP_WAIT(0);
        __syncthreads();
        if (ch + 2 < 8) { load_chunk(ch + 2, (ch + 2) % 3); CP_COMMIT(); }

        uint32_t stb = sbase + (ch % 3) * GH_STAGE_B;
        uint32_t ah[2][4], al[2][4];
#pragma unroll
        for (int mf = 0; mf < 2; mf++) {
            ldsm_x4(ah[mf], stb + a_off[mf]);
            ldsm_x4(al[mf], stb + GH_TILE_B + a_off[mf]);
        }
#pragma unroll
        for (int nb = 0; nb < 4; nb++) {
            uint32_t bh[4], bl[4];
            ldsm_x4(bh, stb + 2 * GH_TILE_B + b_off[nb]);
            ldsm_x4(bl, stb + 3 * GH_TILE_B + b_off[nb]);
#pragma unroll
            for (int mf = 0; mf < 2; mf++) {
#pragma unroll
                for (int sub = 0; sub < 2; sub++) {
                    float* d = acc[mf][nb * 2 + sub];
                    mma16816h(d, ah[mf], bh[sub * 2], bh[sub * 2 + 1]);
                    mma16816h(d, ah[mf], bl[sub * 2], bl[sub * 2 + 1]);
                    mma16816h(d, al[mf], bh[sub * 2], bh[sub * 2 + 1]);
                }
            }
        }
    }

    int g = lane >> 2, q = lane & 3;
#pragma unroll
    for (int mf = 0; mf < 2; mf++) {
#pragma unroll
        for (int n8 = 0; n8 < 8; n8++) {
            int c = wn * 64 + n8 * 8 + q * 2;
            float* d = acc[mf][n8];
            int r0 = j0 + wm * 32 + mf * 16 + g;
            float b0 = wb[c], b1 = wb[c + 1];
            uint32_t hi, lo;
            split2h(d[0] + b0, d[1] + b1, hi, lo);
            *(uint32_t*)&d_Uhi[(size_t)r0 * 256 + 128 + c] = hi;
            *(uint32_t*)&d_Ulo[(size_t)r0 * 256 + 128 + c] = lo;
            split2h(d[2] + b0, d[3] + b1, hi, lo);
            *(uint32_t*)&d_Uhi[(size_t)(r0 + 8) * 256 + 128 + c] = hi;
            *(uint32_t*)&d_Ulo[(size_t)(r0 + 8) * 256 + 128 + c] = lo;
        }
    }
}

// ---------------------------------------------------------------------------
// K2: g = h·A via fp16 mma (3-term). Writes U cols [0,128).
// ---------------------------------------------------------------------------
#define GG_ATILE_B (128 * 24 * 2)                       // 6144 B
#define GG_BTILE_B (16 * 136 * 2)                       // 4352 B
#define GG_STAGE_B (2 * GG_ATILE_B + 2 * GG_BTILE_B)    // 20992 B
#define GG_SMEM    (3 * GG_STAGE_B)                     // 62976 B

__global__ void __launch_bounds__(256) k_gemm_g_mma() {
    extern __shared__ char gg[];
    uint32_t sbase = smem_u32(gg);
    int t = threadIdx.x, lane = t & 31, wid = t >> 5;
    int wm = wid & 3, wn = wid >> 2;
    int j0 = blockIdx.x * 128;

    float acc[2][8][4];
#pragma unroll
    for (int i = 0; i < 2; i++)
#pragma unroll
        for (int j = 0; j < 8; j++)
#pragma unroll
            for (int q = 0; q < 4; q++) acc[i][j][q] = 0.f;

    int lrow = t >> 1, lhalf = t & 1;
    uint32_t sa_off = (uint32_t)(lrow * 24 + lhalf * 8) * 2;
    int frow = t >> 4, fc = (t & 15) * 8;
    uint32_t sb_off = (uint32_t)(frow * 136 + fc) * 2;

    uint32_t a_off[2];
#pragma unroll
    for (int mf = 0; mf < 2; mf++) {
        int rr = wm * 32 + mf * 16 + (lane & 15);
        a_off[mf] = (uint32_t)(rr * 24 + (lane >> 4) * 8) * 2;
    }
    int krB = (lane & 7) + (((lane >> 3) & 1) << 3);
    int ncB = wn * 64 + ((lane >> 4) << 3);

    auto load_chunk = [&](int ch, int st) {
        uint32_t base = sbase + st * GG_STAGE_B;
        const char* guh = (const char*)(d_Uhi + (size_t)(j0 + lrow) * 256 + 128 + ch * 16) + lhalf * 16;
        const char* gul = (const char*)(d_Ulo + (size_t)(j0 + lrow) * 256 + 128 + ch * 16) + lhalf * 16;
        const char* gah = (const char*)(d_Amhi + (ch * 16 + frow) * 128 + fc);
        const char* gal = (const char*)(d_Amlo + (ch * 16 + frow) * 128 + fc);
        CP_ASYNC16(base + sa_off,                 guh);
        CP_ASYNC16(base + GG_ATILE_B + sa_off,    gul);
        CP_ASYNC16(base + 2 * GG_ATILE_B + sb_off,                gah);
        CP_ASYNC16(base + 2 * GG_ATILE_B + GG_BTILE_B + sb_off,   gal);
    };

    load_chunk(0, 0); CP_COMMIT();
    load_chunk(1, 1); CP_COMMIT();

#pragma unroll 1
    for (int ch = 0; ch < 8; ch++) {
        if (ch < 7) CP_WAIT(1); else CP_WAIT(0);
        __syncthreads();
        if (ch + 2 < 8) { load_chunk(ch + 2, (ch + 2) % 3); CP_COMMIT(); }

        uint32_t base = sbase + (ch % 3) * GG_STAGE_B;
        uint32_t ah[2][4], al[2][4];
#pragma unroll
        for (int mf = 0; mf < 2; mf++) {
            ldsm_x4(ah[mf], base + a_off[mf]);
            ldsm_x4(al[mf], base + GG_ATILE_B + a_off[mf]);
        }
#pragma unroll
        for (int np = 0; np < 4; np++) {
            uint32_t boff = (uint32_t)(krB * 136 + ncB + np * 16) * 2;
            uint32_t bh[4], bl[4];
            ldsm_x4_t(bh, base + 2 * GG_ATILE_B + boff);
            ldsm_x4_t(bl, base + 2 * GG_ATILE_B + GG_BTILE_B + boff);
#pragma unroll
            for (int mf = 0; mf < 2; mf++) {
#pragma unroll
                for (int sub = 0; sub < 2; sub++) {
                    float* d = acc[mf][np * 2 + sub];
                    mma16816h(d, ah[mf], bh[sub * 2], bh[sub * 2 + 1]);
                    mma16816h(d, ah[mf], bl[sub * 2], bl[sub * 2 + 1]);
                    mma16816h(d, al[mf], bh[sub * 2], bh[sub * 2 + 1]);
                }
            }
        }
    }

    int g = lane >> 2, q = lane & 3;
#pragma unroll
    for (int mf = 0; mf < 2; mf++) {
#pragma unroll
        for (int n8 = 0; n8 < 8; n8++) {
            int c = wn * 64 + n8 * 8 + q * 2;
            float* d = acc[mf][n8];
            int r0 = j0 + wm * 32 + mf * 16 + g;
            uint32_t hi, lo;
            split2h(d[0], d[1], hi, lo);
            *(uint32_t*)&d_Uhi[(size_t)r0 * 256 + c] = hi;
            *(uint32_t*)&d_Ulo[(size_t)r0 * 256 + c] = lo;
            split2h(d[2], d[3], hi, lo);
            *(uint32_t*)&d_Uhi[(size_t)(r0 + 8) * 256 + c] = hi;
            *(uint32_t*)&d_Ulo[(size_t)(r0 + 8) * 256 + c] = lo;
        }
    }
}

// ---------------------------------------------------------------------------
// K3: scores via fp16 mma, 2-term: e = hiU·hiV + hiU·loV (loU·hiV dropped,
// ~2^-11 relative). K=256, V = half-swapped U. 3 operand tiles per stage.
// ---------------------------------------------------------------------------
#define SC_TILE_B  (128 * 24 * 2)                   // 6144 B per operand tile
#define SC_STAGE_B (3 * SC_TILE_B)                  // 18432 B per stage
#define SC_SMEM    (128 * 133 * 4)                  // 68096 B (stash > 3 stages)

__global__ void __launch_bounds__(256) k_scores_mma() {
    extern __shared__ char sc[];
    uint32_t sbase = smem_u32(sc);

    int t = threadIdx.x, lane = t & 31, wid = t >> 5;
    int wm = wid & 3, wn = wid >> 2;

    int b = blockIdx.y;
    int rem = blockIdx.x;
    int J = 0;
    while (rem >= 8 - J) { rem -= 8 - J; J++; }
    int K = J + rem;
    int j0 = J * 128, k0 = K * 128;

    const __half* Uh = d_Uhi + (size_t)b * N_ * 256;
    const __half* Ul = d_Ulo + (size_t)b * N_ * 256;

    float acc[2][8][4];
#pragma unroll
    for (int i = 0; i < 2; i++)
#pragma unroll
        for (int j = 0; j < 8; j++)
#pragma unroll
            for (int q = 0; q < 4; q++) acc[i][j][q] = 0.f;

    int lrow = t >> 1, lhalf = t & 1;
    uint32_t s_off = (uint32_t)(lrow * 24 + lhalf * 8) * 2;

    uint32_t a_off[2];
#pragma unroll
    for (int mf = 0; mf < 2; mf++) {
        int rr = wm * 32 + mf * 16 + (lane & 15);
        a_off[mf] = (uint32_t)(rr * 24 + (lane >> 4) * 8) * 2;
    }
    uint32_t b_off[4];
#pragma unroll
    for (int nb = 0; nb < 4; nb++) {
        int rr = wn * 64 + nb * 16 + ((lane >> 4) << 3) + (lane & 7);
        b_off[nb] = (uint32_t)(rr * 24 + ((lane >> 3) & 1) * 8) * 2;
    }

    auto load_chunk = [&](int ch, int st) {
        int ca = ch * 16;
        int cb = (ca + 128) & 255;
        uint32_t sb = sbase + st * SC_STAGE_B + s_off;
        const char* gAh = (const char*)(Uh + (size_t)(j0 + lrow) * 256 + ca) + lhalf * 16;
        const char* gBh = (const char*)(Uh + (size_t)(k0 + lrow) * 256 + cb) + lhalf * 16;
        const char* gBl = (const char*)(Ul + (size_t)(k0 + lrow) * 256 + cb) + lhalf * 16;
        CP_ASYNC16(sb,                 gAh);
        CP_ASYNC16(sb + SC_TILE_B,     gBh);
        CP_ASYNC16(sb + 2 * SC_TILE_B, gBl);
    };

    load_chunk(0, 0); CP_COMMIT();
    load_chunk(1, 1); CP_COMMIT();

#pragma unroll 1
    for (int ch = 0; ch < 16; ch++) {
        if (ch < 15) CP_WAIT(1); else CP_WAIT(0);
        __syncthreads();
        if (ch + 2 < 16) { load_chunk(ch + 2, (ch + 2) % 3); CP_COMMIT(); }

        uint32_t stb = sbase + (ch % 3) * SC_STAGE_B;
        uint32_t ah[2][4];
#pragma unroll
        for (int mf = 0; mf < 2; mf++)
            ldsm_x4(ah[mf], stb + a_off[mf]);
#pragma unroll
        for (int nb = 0; nb < 4; nb++) {
            uint32_t bh[4], bl[4];
            ldsm_x4(bh, stb + SC_TILE_B + b_off[nb]);
            ldsm_x4(bl, stb + 2 * SC_TILE_B + b_off[nb]);
#pragma unroll
            for (int mf = 0; mf < 2; mf++) {
#pragma unroll
                for (int sub = 0; sub < 2; sub++) {
                    float* d = acc[mf][nb * 2 + sub];
                    mma16816h(d, ah[mf], bh[sub * 2], bh[sub * 2 + 1]);
                    mma16816h(d, ah[mf], bl[sub * 2], bl[sub * 2 + 1]);
                }
            }
        }
    }
    __syncthreads();   // all warps done with stage smem before stash reuse

    float* st = (float*)sc;
    int g = lane >> 2, tg = lane & 3;
#pragma unroll
    for (int mf = 0; mf < 2; mf++) {
        int rbase = wm * 32 + mf * 16;
#pragma unroll
        for (int n8 = 0; n8 < 8; n8++) {
            int cbase = wn * 64 + n8 * 8 + tg * 2;
            float* d = acc[mf][n8];
            st[(rbase + g) * 133 + cbase]         = d[0];
            st[(rbase + g) * 133 + cbase + 1]     = d[1];
            st[(rbase + g + 8) * 133 + cbase]     = d[2];
            st[(rbase + g + 8) * 133 + cbase + 1] = d[3];
        }
    }
    __syncthreads();

    float* Sb = d_S + (size_t)b * N_ * N_;
    {
        int row = t >> 1, chalf = (t & 1) * 64;
        const float* srow = st + row * 133 + chalf;
        float4* dst = (float4*)&Sb[(size_t)(j0 + row) * N_ + k0 + chalf];
#pragma unroll
        for (int q = 0; q < 16; q++) {
            float4 o;
            o.x = srow[q * 4 + 0]; o.y = srow[q * 4 + 1];
            o.z = srow[q * 4 + 2]; o.w = srow[q * 4 + 3];
            dst[q] = o;
        }
    }
    if (J != K) {
        int r = t & 127, c0 = t >> 7;
#pragma unroll 1
        for (int i = 0; i < 64; i++) {
            int c = c0 + i * 2;
            Sb[(size_t)(k0 + c) * N_ + j0 + r] = st[r * 133 + c];
        }
    }
}

// ---------------------------------------------------------------------------
// K4: transpose adj -> bitmask. adjM[b][x][w] bit k = adj[b][w*32+k][x].
// ---------------------------------------------------------------------------
__global__ void k_adjT(const float* __restrict__ adj) {
    __shared__ float tile[32][33];
    int b = blockIdx.z;
    int x0 = blockIdx.x * 32, y0 = blockIdx.y * 32;
    const float* ab = adj + (size_t)b * N_ * N_;
    int tx = threadIdx.x, ty = threadIdx.y;
#pragma unroll
    for (int i = 0; i < 32; i += 8)
        tile[ty + i][tx] = ab[(size_t)(y0 + ty + i) * N_ + x0 + tx];
    __syncthreads();
#pragma unroll
    for (int i = 0; i < 4; i++) {
        int xr = ty + i * 8;
        uint32_t m = __ballot_sync(0xffffffffu, tile[tx][xr] > 0.f);
        if (tx == 0)
            d_adjM[((size_t)b * N_ + x0 + xr) * (N_ / 32) + (y0 >> 5)] = m;
    }
}

// ---------------------------------------------------------------------------
// K5: fused masked softmax; bitmask mask; emits attn^T fp16 (hi only).
// ---------------------------------------------------------------------------
__global__ void __launch_bounds__(256) k_sm() {
    __shared__ float red_m[8], red_s[8];
    int b = blockIdx.y, r = blockIdx.x, t = threadIdx.x;
    const float* Mrow = d_S + ((size_t)b * N_ + r) * N_;
    const uint32_t* Mask = d_adjM + ((size_t)b * N_ + r) * (N_ / 32);
    __half* Oh = d_AThi + ((size_t)b * N_ + r) * N_;

    float4 e4 = *(const float4*)&Mrow[t * 4];
    uint32_t w = Mask[t >> 3];
    int sh = (t & 7) * 4;
    bool m0 = (w >> sh) & 1, m1 = (w >> (sh + 1)) & 1;
    bool m2 = (w >> (sh + 2)) & 1, m3 = (w >> (sh + 3)) & 1;

    float v0 = m0 ? e4.x : 0.f;
    float v1 = m1 ? e4.y : 0.f;
    float v2 = m2 ? e4.z : 0.f;
    float v3 = m3 ? e4.w : 0.f;

    float lm = fmaxf(fmaxf(v0, v1), fmaxf(v2, v3));
#pragma unroll
    for (int o = 16; o > 0; o >>= 1)
        lm = fmaxf(lm, __shfl_xor_sync(0xffffffffu, lm, o));
    if ((t & 31) == 0) red_m[t >> 5] = lm;
    __syncthreads();
    float m = red_m[0];
#pragma unroll
    for (int i = 1; i < 8; i++) m = fmaxf(m, red_m[i]);

    float p0 = fexp(v0 - m), p1 = fexp(v1 - m);
    float p2 = fexp(v2 - m), p3 = fexp(v3 - m);
    float ls = (p0 + p1) + (p2 + p3);
#pragma unroll
    for (int o = 16; o > 0; o >>= 1)
        ls += __shfl_xor_sync(0xffffffffu, ls, o);
    if ((t & 31) == 0) red_s[t >> 5] = ls;
    __syncthreads();
    float Z = red_s[0];
#pragma unroll
    for (int i = 1; i < 8; i++) Z += red_s[i];
    float inv = 1.0f / Z;

    float r0 = m0 ? p0 * inv : 0.f;
    float r1 = m1 ? p1 * inv : 0.f;
    float r2 = m2 ? p2 * inv : 0.f;
    float r3 = m3 ? p3 * inv : 0.f;
    uint2 ho;
    ho.x = pack2h(r0, r1);
    ho.y = pack2h(r2, r3);
    *(uint2*)&Oh[t * 4] = ho;
}

// ---------------------------------------------------------------------------
// K6: h' = relu(att @ h) via fp16 mma, 2-term: attn·hHi + attn·hLo.
// Gates fused. 3-stage single-barrier, 3 operand tiles per stage.
// ---------------------------------------------------------------------------
#define KO_TILE_B  (32 * 136 * 2)                   // 8704 B
#define KO_STAGE_B (3 * KO_TILE_B)                  // 26112 B
#define KO_SMEM    (3 * KO_STAGE_B)                 // 78336 B

__global__ void __launch_bounds__(256) k_out_mma(const float* __restrict__ x,
                                                 const float* __restrict__ wiu,
                                                 const float* __restrict__ wfu,
                                                 const float* __restrict__ wou,
                                                 float* __restrict__ out) {
    extern __shared__ char ko[];
    __shared__ float red[3][128];
    __shared__ float wu[3][128];

    int b = blockIdx.y, i0 = blockIdx.x * 128;
    int t = threadIdx.x, lane = t & 31, wid = t >> 5;
    int wm = wid & 3, wn = wid >> 2;
    if (t < 128) {
        wu[0][t] = wiu[t]; wu[1][t] = wfu[t]; wu[2][t] = wou[t];
        red[0][t] = 0.f; red[1][t] = 0.f; red[2][t] = 0.f;
    }

    const __half* ATh = d_AThi + (size_t)b * N_ * N_;
    const __half* Hh  = d_Uhi + (size_t)b * N_ * 256 + 128;
    const __half* Hl  = d_Ulo + (size_t)b * N_ * 256 + 128;

    uint32_t sb0 = smem_u32(ko);

    float acc[2][8][4];
#pragma unroll
    for (int i = 0; i < 2; i++)
#pragma unroll
        for (int j = 0; j < 8; j++)
#pragma unroll
            for (int q = 0; q < 4; q++) acc[i][j][q] = 0.f;

    int krA = (lane & 7) + ((lane >> 4) << 3);
    int mcA = wm * 32 + ((lane >> 3) & 1) * 8;
    int krB = (lane & 7) + (((lane >> 3) & 1) << 3);
    int ncB = wn * 64 + ((lane >> 4) << 3);

    int frow0 = t >> 4, fc0 = (t & 15) * 8;
    int frow1 = (t + 256) >> 4;

    auto load_chunk = [&](int kc, int st) {
        uint32_t base = sb0 + st * KO_STAGE_B;
        uint32_t so0 = (uint32_t)(frow0 * 136 + fc0) * 2;
        uint32_t so1 = (uint32_t)(frow1 * 136 + fc0) * 2;
        const char* ga0 = (const char*)(ATh + (size_t)(kc + frow0) * N_ + i0 + fc0);
        const char* ga1 = (const char*)(ATh + (size_t)(kc + frow1) * N_ + i0 + fc0);
        const char* gb0 = (const char*)(Hh + (size_t)(kc + frow0) * 256 + fc0);
        const char* gb1 = (const char*)(Hh + (size_t)(kc + frow1) * 256 + fc0);
        const char* gbl0 = (const char*)(Hl + (size_t)(kc + frow0) * 256 + fc0);
        const char* gbl1 = (const char*)(Hl + (size_t)(kc + frow1) * 256 + fc0);
        CP_ASYNC16(base + so0,                  ga0);
        CP_ASYNC16(base + so1,                  ga1);
        CP_ASYNC16(base + KO_TILE_B + so0,      gb0);
        CP_ASYNC16(base + KO_TILE_B + so1,      gb1);
        CP_ASYNC16(base + 2 * KO_TILE_B + so0,  gbl0);
        CP_ASYNC16(base + 2 * KO_TILE_B + so1,  gbl1);
    };

    load_chunk(0, 0);  CP_COMMIT();
    load_chunk(32, 1); CP_COMMIT();

#pragma unroll 1
    for (int it = 0; it < 32; it++) {
        if (it < 31) CP_WAIT(1); else CP_WAIT(0);
        __syncthreads();
        if (it + 2 < 32) { load_chunk((it + 2) * 32, (it + 2) % 3); CP_COMMIT(); }

        uint32_t base = sb0 + (it % 3) * KO_STAGE_B;
#pragma unroll
        for (int s = 0; s < 2; s++) {
            uint32_t ah[2][4];
#pragma unroll
            for (int mf = 0; mf < 2; mf++) {
                uint32_t off = (uint32_t)((s * 16 + krA) * 136 + mcA + mf * 16) * 2;
                ldsm_x4_t(ah[mf], base + off);
            }
#pragma unroll
            for (int np = 0; np < 4; np++) {
                uint32_t boff = (uint32_t)((s * 16 + krB) * 136 + ncB + np * 16) * 2;
                uint32_t bh[4], bl[4];
                ldsm_x4_t(bh, base + KO_TILE_B + boff);
                ldsm_x4_t(bl, base + 2 * KO_TILE_B + boff);
#pragma unroll
                for (int mf = 0; mf < 2; mf++) {
#pragma unroll
                    for (int sub = 0; sub < 2; sub++) {
                        float* d = acc[mf][np * 2 + sub];
                        mma16816h(d, ah[mf], bh[sub * 2], bh[sub * 2 + 1]);
                        mma16816h(d, ah[mf], bl[sub * 2], bl[sub * 2 + 1]);
                    }
                }
            }
        }
    }

    int g = lane >> 2, q = lane & 3;
    float pp[2][2][3];
#pragma unroll
    for (int mf = 0; mf < 2; mf++)
#pragma unroll
        for (int rh = 0; rh < 2; rh++)
#pragma unroll
            for (int gg = 0; gg < 3; gg++) pp[mf][rh][gg] = 0.f;

#pragma unroll
    for (int mf = 0; mf < 2; mf++) {
#pragma unroll
        for (int n8 = 0; n8 < 8; n8++) {
            int c = wn * 64 + n8 * 8 + q * 2;
            float wa0 = wu[0][c], wb0 = wu[0][c + 1];
            float wa1 = wu[1][c], wb1 = wu[1][c + 1];
            float wa2 = wu[2][c], wb2 = wu[2][c + 1];
            float* d = acc[mf][n8];
            float v0 = fmaxf(d[0], 0.f), v1 = fmaxf(d[1], 0.f);
            float v2 = fmaxf(d[2], 0.f), v3 = fmaxf(d[3], 0.f);
            d[0] = v0; d[1] = v1; d[2] = v2; d[3] = v3;
            pp[mf][0][0] += v0 * wa0 + v1 * wb0;
            pp[mf][0][1] += v0 * wa1 + v1 * wb1;
            pp[mf][0][2] += v0 * wa2 + v1 * wb2;
            pp[mf][1][0] += v2 * wa0 + v3 * wb0;
            pp[mf][1][1] += v2 * wa1 + v3 * wb1;
            pp[mf][1][2] += v2 * wa2 + v3 * wb2;
        }
    }
#pragma unroll
    for (int mf = 0; mf < 2; mf++)
#pragma unroll
        for (int rh = 0; rh < 2; rh++) {
            float s0 = pp[mf][rh][0], s1 = pp[mf][rh][1], s2 = pp[mf][rh][2];
            s0 += __shfl_xor_sync(0xffffffffu, s0, 1);
            s0 += __shfl_xor_sync(0xffffffffu, s0, 2);
            s1 += __shfl_xor_sync(0xffffffffu, s1, 1);
            s1 += __shfl_xor_sync(0xffffffffu, s1, 2);
            s2 += __shfl_xor_sync(0xffffffffu, s2, 1);
            s2 += __shfl_xor_sync(0xffffffffu, s2, 2);
            if (q == 0) {
                int r = wm * 32 + mf * 16 + rh * 8 + g;
                atomicAdd(&red[0][r], s0);
                atomicAdd(&red[1][r], s1);
                atomicAdd(&red[2][r], s2);
            }
        }
    __syncthreads();

    int nb = b * N_ + i0;
#pragma unroll
    for (int mf = 0; mf < 2; mf++) {
#pragma unroll
        for (int rh = 0; rh < 2; rh++) {
            int r = wm * 32 + mf * 16 + rh * 8 + g;
            float zi = red[0][r] + d_xd[nb + r];
            float zf = red[1][r] + d_xd[B_ * N_ + nb + r];
            float zo = red[2][r] + d_xd[2 * B_ * N_ + nb + r];
            float ic = 1.f / (1.f + fexp(-zi));
            float fc = 1.f / (1.f + fexp(-zf));
            float oc = 1.f / (1.f + fexp(-zo));
            const float* xr = x + (size_t)(nb + r) * 128;
            float* orow = out + (size_t)(nb + r) * 128;
#pragma unroll
            for (int n8 = 0; n8 < 8; n8++) {
                int c = wn * 64 + n8 * 8 + q * 2;
                float2 xv = *(const float2*)&xr[c];
                float v0 = acc[mf][n8][rh * 2 + 0];
                float v1 = acc[mf][n8][rh * 2 + 1];
                float2 o;
                o.x = oc * tanhf(ic * v0 + fc * xv.x);
                o.y = oc * tanhf(ic * v1 + fc * xv.y);
                *(float2*)&orow[c] = o;
            }
        }
    }
}

// ---------------------------------------------------------------------------
extern "C" void kernel_launch(void* const* d_in, const int* in_sizes, int n_in,
                              void* d_out, int out_size) {
    const float* x   = (const float*)d_in[0];
    const float* adj = (const float*)d_in[1];
    const float* Ww  = (const float*)d_in[2];
    const float* Wb  = (const float*)d_in[3];
    const float* A   = (const float*)d_in[4];
    const float* wiu = (const float*)d_in[5];
    const float* wix = (const float*)d_in[6];
    const float* wfu = (const float*)d_in[7];
    const float* wfx = (const float*)d_in[8];
    const float* wou = (const float*)d_in[9];
    const float* wox = (const float*)d_in[10];
    float* out = (float*)d_out;

    static int attr_set = 0;
    if (!attr_set) {
        cudaFuncSetAttribute(k_scores_mma, cudaFuncAttributeMaxDynamicSharedMemorySize, SC_SMEM);
        cudaFuncSetAttribute(k_out_mma, cudaFuncAttributeMaxDynamicSharedMemorySize, KO_SMEM);
        cudaFuncSetAttribute(k_gemm_h_mma, cudaFuncAttributeMaxDynamicSharedMemorySize, GH_SMEM);
        cudaFuncSetAttribute(k_gemm_g_mma, cudaFuncAttributeMaxDynamicSharedMemorySize, GG_SMEM);
        attr_set = 1;
    }

    k_prep<<<B_ * N_ / 8, 256>>>(x, wix, wfx, wox, Ww, A);
    k_gemm_h_mma<<<B_ * N_ / 128, 256, GH_SMEM>>>(Wb);
    k_gemm_g_mma<<<B_ * N_ / 128, 256, GG_SMEM>>>();
    {
        dim3 g(36, B_);
        k_scores_mma<<<g, 256, SC_SMEM>>>();
    }
    {
        dim3 g(N_ / 32, N_ / 32, B_);
        k_adjT<<<g, dim3(32, 8)>>>(adj);
    }
    {
        dim3 g(N_, B_);
        k_sm<<<g, 256>>>();
    }
    {
        dim3 g(N_ / 128, B_);
        k_out_mma<<<g, 256, KO_SMEM>>>(x, wiu, wfu, wou, out);
    }
}